// round 2
// baseline (speedup 1.0000x reference)
#include <cuda_runtime.h>
#include <math.h>

#define BATCH 2
#define CDIM 128
#define HDIM 128
#define WDIM 128
#define HWD (HDIM*WDIM)           // 16384
#define NPIX (BATCH*HWD)          // 32768
#define C3 (3*CDIM)               // 384
#define HIDD 340
#define NHEADS 4
#define EPSV 1e-6f

// ---------------- scratch (static device allocations) ----------------
__device__ float g_xt  [NPIX*CDIM];
__device__ float g_ln  [NPIX*CDIM];
__device__ float g_qkv1[NPIX*C3];
__device__ float g_qkv2[NPIX*C3];
__device__ float g_att [NPIX*CDIM];
__device__ float g_x1  [NPIX*CDIM];
__device__ float g_y   [NPIX*CDIM];
__device__ float g_h1  [NPIX*HIDD];
__device__ float g_h2  [NPIX*HIDD];
__device__ float g_S   [BATCH*NHEADS*32*32];
__device__ float g_nq  [BATCH*CDIM];
__device__ float g_nk  [BATCH*CDIM];

// ---------------- NCHW -> NHWC transpose ----------------
__global__ void k_nchw2nhwc(const float* __restrict__ in, float* __restrict__ out){
    __shared__ float tile[32][33];
    int b = blockIdx.z;
    int p0 = blockIdx.x*32;   // spatial
    int c0 = blockIdx.y*32;   // channel
    int tx = threadIdx.x, ty = threadIdx.y; // 32 x 8
    #pragma unroll
    for (int i=0;i<4;i++){
        int c = c0 + ty + i*8;
        tile[ty+i*8][tx] = in[((long)b*CDIM + c)*HWD + p0 + tx];
    }
    __syncthreads();
    #pragma unroll
    for (int i=0;i<4;i++){
        int p = p0 + ty + i*8;
        out[((long)b*HWD + p)*CDIM + c0 + tx] = tile[tx][ty+i*8];
    }
}

// ---------------- NHWC (a+b) -> NCHW ----------------
__global__ void k_final(const float* __restrict__ a, const float* __restrict__ b2,
                        float* __restrict__ out){
    __shared__ float tile[32][33];
    int b = blockIdx.z;
    int p0 = blockIdx.x*32;
    int c0 = blockIdx.y*32;
    int tx = threadIdx.x, ty = threadIdx.y;
    #pragma unroll
    for (int i=0;i<4;i++){
        long idx = ((long)b*HWD + p0 + ty + i*8)*CDIM + c0 + tx;
        tile[ty+i*8][tx] = a[idx] + b2[idx];
    }
    __syncthreads();
    #pragma unroll
    for (int i=0;i<4;i++){
        int c = c0 + ty + i*8;
        out[((long)b*CDIM + c)*HWD + p0 + tx] = tile[tx][ty+i*8];
    }
}

// ---------------- LayerNorm over C (warp per pixel), optional residual + roll ----
__global__ void k_ln(const float* __restrict__ in, const float* __restrict__ res,
                     const float* __restrict__ gamma, const float* __restrict__ beta,
                     float* __restrict__ out, int shift){
    int warp = threadIdx.x >> 5, lane = threadIdx.x & 31;
    int pix = blockIdx.x*8 + warp;
    if (pix >= NPIX) return;
    int b = pix / HWD, rem = pix % HWD;
    int h = rem / WDIM, w = rem % WDIM;
    int sh = (h + shift) & (HDIM-1);
    int sw = (w + shift) & (WDIM-1);
    long src = ((long)b*HWD + sh*WDIM + sw)*CDIM + lane*4;
    float4 v = *(const float4*)(in + src);
    if (res){
        float4 r = *(const float4*)(res + src);
        v.x += r.x; v.y += r.y; v.z += r.z; v.w += r.w;
    }
    float s  = v.x+v.y+v.z+v.w;
    float ss = v.x*v.x+v.y*v.y+v.z*v.z+v.w*v.w;
    #pragma unroll
    for (int o=16;o;o>>=1){
        s  += __shfl_xor_sync(0xffffffffu, s,  o);
        ss += __shfl_xor_sync(0xffffffffu, ss, o);
    }
    float mean = s * (1.f/CDIM);
    float var  = ss * (1.f/CDIM) - mean*mean;
    float rstd = rsqrtf(var + EPSV);
    float4 g  = *(const float4*)(gamma + lane*4);
    float4 be = *(const float4*)(beta  + lane*4);
    float4 o4;
    o4.x = (v.x-mean)*rstd*g.x + be.x;
    o4.y = (v.y-mean)*rstd*g.y + be.y;
    o4.z = (v.z-mean)*rstd*g.z + be.z;
    o4.w = (v.w-mean)*rstd*g.w + be.w;
    *(float4*)(out + (long)pix*CDIM + lane*4) = o4;
}

// ---------------- GEMM: C[m,n] = sum_k A[m,k]*W[n,k] -------------------
__global__ void k_gemm(const float* __restrict__ A, const float* __restrict__ Wt,
                       float* __restrict__ Cc, int M, int N, int K){
    __shared__ float As[16][64];
    __shared__ float Bs[16][64];
    int tid = threadIdx.x;            // 256
    int tx = tid & 15, ty = tid >> 4;
    int m0 = blockIdx.y*64, n0 = blockIdx.x*64;
    int lr = tid >> 2;                // 0..63
    int lk = (tid & 3) * 4;           // 0,4,8,12
    float acc[4][4] = {};
    for (int k0 = 0; k0 < K; k0 += 16){
        // A tile -> As[k][m]
        {
            int m = m0 + lr;
            int k = k0 + lk;
            if (k + 3 < K){
                float4 a4 = *(const float4*)(A + (long)m*K + k);
                As[lk+0][lr]=a4.x; As[lk+1][lr]=a4.y; As[lk+2][lr]=a4.z; As[lk+3][lr]=a4.w;
            } else {
                #pragma unroll
                for (int j=0;j<4;j++) As[lk+j][lr] = (k+j < K) ? A[(long)m*K + k + j] : 0.f;
            }
        }
        // W tile -> Bs[k][n]
        {
            int n = n0 + lr;
            int k = k0 + lk;
            if (n < N && k + 3 < K){
                float4 b4 = *(const float4*)(Wt + (long)n*K + k);
                Bs[lk+0][lr]=b4.x; Bs[lk+1][lr]=b4.y; Bs[lk+2][lr]=b4.z; Bs[lk+3][lr]=b4.w;
            } else {
                #pragma unroll
                for (int j=0;j<4;j++) Bs[lk+j][lr] = (n < N && k+j < K) ? Wt[(long)n*K + k + j] : 0.f;
            }
        }
        __syncthreads();
        #pragma unroll
        for (int k=0;k<16;k++){
            float4 a4 = *(const float4*)&As[k][ty*4];
            float4 b4 = *(const float4*)&Bs[k][tx*4];
            float a[4] = {a4.x,a4.y,a4.z,a4.w};
            float bb[4] = {b4.x,b4.y,b4.z,b4.w};
            #pragma unroll
            for (int i=0;i<4;i++)
                #pragma unroll
                for (int j=0;j<4;j++)
                    acc[i][j] += a[i]*bb[j];
        }
        __syncthreads();
    }
    #pragma unroll
    for (int i=0;i<4;i++){
        int m = m0 + ty*4 + i;
        #pragma unroll
        for (int j=0;j<4;j++){
            int n = n0 + tx*4 + j;
            if (n < N) Cc[(long)m*N + n] = acc[i][j];
        }
    }
}

// ---------------- depthwise 3x3 (SAME, zero pad), optional exact gelu ------
__global__ void k_dwconv(const float* __restrict__ in, const float* __restrict__ wdw,
                         float* __restrict__ out, int CHN, int total, int dogelu){
    int idx = blockIdx.x*256 + threadIdx.x;
    if (idx >= total) return;
    int c = idx % CHN;
    int pix = idx / CHN;
    int b = pix / HWD; int rem = pix % HWD;
    int h = rem / WDIM; int w = rem % WDIM;
    const float* wp = wdw + c*9;
    float acc = 0.f;
    #pragma unroll
    for (int dy=-1;dy<=1;dy++){
        int hh = h+dy;
        if ((unsigned)hh >= HDIM) continue;
        #pragma unroll
        for (int dx=-1;dx<=1;dx++){
            int w2 = w+dx;
            if ((unsigned)w2 >= WDIM) continue;
            acc += wp[(dy+1)*3+(dx+1)] * in[((long)b*HWD + hh*WDIM + w2)*CHN + c];
        }
    }
    if (dogelu) acc = 0.5f*acc*(1.f + erff(acc*0.70710678118654752f));
    out[idx] = acc;
}

// ---------------- RSA window attention (one CTA per 4x4 window) --------------
__global__ void k_rsa_win(const float* __restrict__ qkv, const float* __restrict__ tempp,
                          float* __restrict__ out){
    extern __shared__ float sm[];
    float* qs = sm;          // 16*128
    float* ks = sm + 2048;
    float* vs = sm + 4096;
    float* at = sm + 6144;   // 128*128
    __shared__ float rn[32];
    int tid = threadIdx.x;   // 256
    int win = blockIdx.x;
    int b = win >> 10; int wrem = win & 1023;
    int wy = wrem >> 5, wx = wrem & 31;
    // load q,k,v [16][128] each
    for (int i = tid; i < 6144; i += 256){
        int sec = i >> 11; int r = i & 2047; int p = r >> 7; int c = r & 127;
        int gh = wy*4 + (p>>2), gw = wx*4 + (p&3);
        sm[i] = qkv[((long)b*HWD + gh*WDIM + gw)*C3 + sec*128 + c];
    }
    __syncthreads();
    if (tid < 32){
        int sec = tid >> 4, p = tid & 15;
        const float* base = sm + sec*2048 + p*128;
        float s = 0.f;
        for (int c=0;c<128;c++){ float v = base[c]; s += v*v; }
        rn[tid] = 1.f / fmaxf(sqrtf(s), 1e-12f);
    }
    __syncthreads();
    for (int i = tid; i < 4096; i += 256){
        int sec = i >> 11; int p = (i & 2047) >> 7;
        sm[i] *= rn[sec*16 + p];
    }
    __syncthreads();
    float temp = tempp[0];
    for (int i = tid; i < 16384; i += 256){
        int c = i >> 7, d = i & 127;
        float s = 0.f;
        #pragma unroll
        for (int p=0;p<16;p++) s += qs[p*128+c]*ks[p*128+d];
        at[i] = fmaxf(s*temp, 0.f);
    }
    __syncthreads();
    for (int i = tid; i < 2048; i += 256){
        int p = i >> 7, d = i & 127;
        float s = 0.f;
        #pragma unroll 8
        for (int c=0;c<128;c++) s += vs[p*128+c]*at[c*128+d];
        int gh = wy*4 + (p>>2), gw = wx*4 + (p&3);
        int oh = (gh+2)&127, ow = (gw+2)&127;
        out[((long)b*HWD + oh*WDIM + ow)*CDIM + d] = s;
    }
}

// ---------------- GSA gram + per-channel sumsq reduction ---------------------
__global__ void k_gsa_gram(const float* __restrict__ qkv, float* __restrict__ S,
                           float* __restrict__ nq, float* __restrict__ nk){
    __shared__ float sq[32*32];
    __shared__ float sk[32*32];
    int tid = threadIdx.x;            // 256
    int blk = blockIdx.x;             // B*4*16
    int chunk = blk & 15;
    int head = (blk >> 4) & 3;
    int b = blk >> 6;
    int p0 = chunk*1024;
    int c0 = tid >> 3;                // 0..31
    int d0 = (tid & 7) * 4;           // 0..28
    float acc[4] = {0,0,0,0};
    float sumq = 0.f, sumk = 0.f;
    for (int t = 0; t < 32; t++){
        __syncthreads();
        for (int i = tid; i < 2048; i += 256){
            int pi = i >> 6;
            int vv = i & 63;
            long pix = (long)b*HWD + p0 + t*32 + pi;
            int chn = (vv < 32) ? (head*32 + vv) : (128 + head*32 + (vv-32));
            float val = qkv[pix*C3 + chn];
            if (vv < 32) sq[pi*32+vv] = val; else sk[pi*32+(vv-32)] = val;
        }
        __syncthreads();
        #pragma unroll 4
        for (int pi=0; pi<32; pi++){
            float qv = sq[pi*32 + c0];
            #pragma unroll
            for (int j=0;j<4;j++) acc[j] += qv * sk[pi*32 + d0 + j];
        }
        if (tid < 32){
            for (int pi=0;pi<32;pi++){ float v = sq[pi*32+tid]; sumq += v*v; }
        } else if (tid < 64){
            int c = tid-32;
            for (int pi=0;pi<32;pi++){ float v = sk[pi*32+c]; sumk += v*v; }
        }
    }
    int sbase = ((b*NHEADS + head)*32 + c0)*32 + d0;
    #pragma unroll
    for (int j=0;j<4;j++) atomicAdd(&S[sbase+j], acc[j]);
    if (tid < 32) atomicAdd(&nq[b*CDIM + head*32 + tid], sumq);
    else if (tid < 64) atomicAdd(&nk[b*CDIM + head*32 + (tid-32)], sumk);
}

// ---------------- GSA attn finalize (in-place on S) --------------------------
__global__ void k_gsa_attn(float* __restrict__ S, const float* __restrict__ nq,
                           const float* __restrict__ nk, const float* __restrict__ tempp){
    int i = blockIdx.x*256 + threadIdx.x;
    if (i >= BATCH*NHEADS*32*32) return;
    int d = i & 31; int c = (i>>5)&31; int head = (i>>10)&3; int b = i>>12;
    float qn = fmaxf(sqrtf(nq[b*CDIM+head*32+c]), 1e-12f);
    float kn = fmaxf(sqrtf(nk[b*CDIM+head*32+d]), 1e-12f);
    S[i] = fmaxf(S[i]*tempp[0]/(qn*kn), 0.f);
}

// ---------------- GSA output: out[c,n] = sum_d attn[c,d] v[d,n] --------------
__global__ void k_gsa_out(const float* __restrict__ qkv, const float* __restrict__ A,
                          float* __restrict__ out){
    __shared__ float at[NHEADS*32*33];   // padded stride 33
    __shared__ float vsm[8][128];
    int tid = threadIdx.x;               // 256
    int warp = tid >> 5, lane = tid & 31;
    int b = (blockIdx.x*8) / HWD;
    for (int i = tid; i < NHEADS*32*32; i += 256)
        at[(i>>5)*33 + (i&31)] = A[b*NHEADS*32*32 + i];
    __syncthreads();
    long pix = (long)blockIdx.x*8 + warp;
    float4 v4 = *(const float4*)(qkv + pix*C3 + 256 + lane*4);
    vsm[warp][lane*4+0]=v4.x; vsm[warp][lane*4+1]=v4.y;
    vsm[warp][lane*4+2]=v4.z; vsm[warp][lane*4+3]=v4.w;
    __syncwarp();
    #pragma unroll
    for (int hd=0; hd<4; hd++){
        const float* arow = at + (hd*32 + lane)*33;
        const float* vrow = vsm[warp] + hd*32;
        float s = 0.f;
        #pragma unroll
        for (int d=0; d<32; d++) s += arow[d]*vrow[d];
        out[pix*CDIM + hd*32 + lane] = s;
    }
}

// ---------------- elementwise add ----------------
__global__ void k_add(const float* __restrict__ a, const float* __restrict__ b,
                      float* __restrict__ o, int n4){
    int i = blockIdx.x*256 + threadIdx.x;
    if (i >= n4) return;
    float4 x = ((const float4*)a)[i];
    float4 y = ((const float4*)b)[i];
    x.x+=y.x; x.y+=y.y; x.z+=y.z; x.w+=y.w;
    ((float4*)o)[i] = x;
}

// =============================== host ===============================
static float* sym(const void* s){
    void* p = nullptr;
    cudaGetSymbolAddress(&p, s);
    return (float*)p;
}

extern "C" void kernel_launch(void* const* d_in, const int* in_sizes, int n_in,
                              void* d_out, int out_size){
    const float* x        = (const float*)d_in[0];
    const float* w_s0     = (const float*)d_in[1];
    const float* b_s0     = (const float*)d_in[2];
    const float* w_s2     = (const float*)d_in[3];
    const float* b_s2     = (const float*)d_in[4];
    const float* rsa_qkv  = (const float*)d_in[5];
    const float* rsa_dw   = (const float*)d_in[6];
    const float* rsa_proj = (const float*)d_in[7];
    const float* rsa_temp = (const float*)d_in[8];
    const float* ffs_in   = (const float*)d_in[9];
    const float* ffs_dw   = (const float*)d_in[10];
    const float* ffs_out  = (const float*)d_in[11];
    const float* w_c0     = (const float*)d_in[12];
    const float* b_c0     = (const float*)d_in[13];
    const float* w_c2     = (const float*)d_in[14];
    const float* b_c2     = (const float*)d_in[15];
    const float* gsa_qkv  = (const float*)d_in[16];
    const float* gsa_dw   = (const float*)d_in[17];
    const float* gsa_proj = (const float*)d_in[18];
    const float* gsa_temp = (const float*)d_in[19];
    const float* ffc_in   = (const float*)d_in[20];
    const float* ffc_dw   = (const float*)d_in[21];
    const float* ffc_out  = (const float*)d_in[22];
    float* out = (float*)d_out;

    float* xt  = sym(g_xt);
    float* ln  = sym(g_ln);
    float* q1  = sym(g_qkv1);
    float* q2  = sym(g_qkv2);
    float* att = sym(g_att);
    float* x1  = sym(g_x1);
    float* y   = sym(g_y);
    float* h1  = sym(g_h1);
    float* h2  = sym(g_h2);
    float* S   = sym(g_S);
    float* nq  = sym(g_nq);
    float* nk  = sym(g_nk);

    cudaFuncSetAttribute(k_rsa_win, cudaFuncAttributeMaxDynamicSharedMemorySize, 90112);

    dim3 tb(32,8);
    dim3 tg(HWD/32, CDIM/32, BATCH);
    dim3 gemmB(256);

    // ---- spatial (RSA) block ----
    k_nchw2nhwc<<<tg, tb>>>(x, xt);
    k_ln<<<NPIX/8, 256>>>(xt, nullptr, w_s0, b_s0, ln, 2);                 // LN + roll(-2,-2)
    k_gemm<<<dim3(6,512), gemmB>>>(ln, rsa_qkv, q1, NPIX, C3, CDIM);
    k_dwconv<<<(NPIX*C3+255)/256, 256>>>(q1, rsa_dw, q2, C3, NPIX*C3, 0);
    k_rsa_win<<<BATCH*1024, 256, 90112>>>(q2, rsa_temp, att);              // + roll back
    k_gemm<<<dim3(2,512), gemmB>>>(att, rsa_proj, x1, NPIX, CDIM, CDIM);   // x_ (spatial)
    k_ln<<<NPIX/8, 256>>>(x1, xt, w_s2, b_s2, ln, 0);                      // LN(x_ + x)
    k_gemm<<<dim3(6,512), gemmB>>>(ln, ffs_in, h1, NPIX, HIDD, CDIM);
    k_dwconv<<<(NPIX*HIDD+255)/256, 256>>>(h1, ffs_dw, h2, HIDD, NPIX*HIDD, 1);
    k_gemm<<<dim3(2,512), gemmB>>>(h2, ffs_out, att, NPIX, CDIM, HIDD);
    k_add<<<(NPIX*CDIM/4+255)/256, 256>>>(att, x1, y, NPIX*CDIM/4);        // x2

    // ---- channel (GSA) block ----
    k_ln<<<NPIX/8, 256>>>(y, nullptr, w_c0, b_c0, ln, 0);
    k_gemm<<<dim3(6,512), gemmB>>>(ln, gsa_qkv, q1, NPIX, C3, CDIM);
    k_dwconv<<<(NPIX*C3+255)/256, 256>>>(q1, gsa_dw, q2, C3, NPIX*C3, 0);
    cudaMemsetAsync(S,  0, BATCH*NHEADS*32*32*sizeof(float));
    cudaMemsetAsync(nq, 0, BATCH*CDIM*sizeof(float));
    cudaMemsetAsync(nk, 0, BATCH*CDIM*sizeof(float));
    k_gsa_gram<<<BATCH*NHEADS*16, 256>>>(q2, S, nq, nk);
    k_gsa_attn<<<(BATCH*NHEADS*32*32+255)/256, 256>>>(S, nq, nk, gsa_temp);
    k_gsa_out<<<NPIX/8, 256>>>(q2, S, att);
    k_gemm<<<dim3(2,512), gemmB>>>(att, gsa_proj, x1, NPIX, CDIM, CDIM);   // x_ (channel)
    k_ln<<<NPIX/8, 256>>>(x1, y, w_c2, b_c2, ln, 0);                       // LN(x_ + x2)
    k_gemm<<<dim3(6,512), gemmB>>>(ln, ffc_in, h1, NPIX, HIDD, CDIM);
    k_dwconv<<<(NPIX*HIDD+255)/256, 256>>>(h1, ffc_dw, h2, HIDD, NPIX*HIDD, 1);
    k_gemm<<<dim3(2,512), gemmB>>>(h2, ffc_out, att, NPIX, CDIM, HIDD);
    k_final<<<tg, tb>>>(att, x1, out);                                     // + x_, NHWC->NCHW
}

// round 3
// speedup vs baseline: 1.4106x; 1.4106x over previous
#include <cuda_runtime.h>
#include <math.h>

#define BATCH 2
#define CDIM 128
#define HDIM 128
#define WDIM 128
#define HWD (HDIM*WDIM)           // 16384
#define NPIX (BATCH*HWD)          // 32768
#define C3 (3*CDIM)               // 384
#define HIDD 340
#define NHEADS 4
#define EPSV 1e-6f

// ---------------- scratch (static device allocations) ----------------
__device__ float g_xt  [NPIX*CDIM];
__device__ float g_ln  [NPIX*CDIM];
__device__ float g_qkv1[NPIX*C3];
__device__ float g_qkv2[NPIX*C3];
__device__ float g_att [NPIX*CDIM];
__device__ float g_x1  [NPIX*CDIM];
__device__ float g_y   [NPIX*CDIM];
__device__ float g_h1  [NPIX*HIDD];
__device__ float g_h2  [NPIX*HIDD];
__device__ float g_S   [BATCH*NHEADS*32*32];
__device__ float g_nq  [BATCH*CDIM];
__device__ float g_nk  [BATCH*CDIM];
__device__ float g_wt  [C3*9];     // transposed dwconv weights [9][CHN]

// ---------------- NCHW -> NHWC transpose ----------------
__global__ void k_nchw2nhwc(const float* __restrict__ in, float* __restrict__ out){
    __shared__ float tile[32][33];
    int b = blockIdx.z;
    int p0 = blockIdx.x*32;
    int c0 = blockIdx.y*32;
    int tx = threadIdx.x, ty = threadIdx.y;
    #pragma unroll
    for (int i=0;i<4;i++){
        int c = c0 + ty + i*8;
        tile[ty+i*8][tx] = in[((long)b*CDIM + c)*HWD + p0 + tx];
    }
    __syncthreads();
    #pragma unroll
    for (int i=0;i<4;i++){
        int p = p0 + ty + i*8;
        out[((long)b*HWD + p)*CDIM + c0 + tx] = tile[tx][ty+i*8];
    }
}

// ---------------- NHWC (a+b) -> NCHW ----------------
__global__ void k_final(const float* __restrict__ a, const float* __restrict__ b2,
                        float* __restrict__ out){
    __shared__ float tile[32][33];
    int b = blockIdx.z;
    int p0 = blockIdx.x*32;
    int c0 = blockIdx.y*32;
    int tx = threadIdx.x, ty = threadIdx.y;
    #pragma unroll
    for (int i=0;i<4;i++){
        long idx = ((long)b*HWD + p0 + ty + i*8)*CDIM + c0 + tx;
        tile[ty+i*8][tx] = a[idx] + b2[idx];
    }
    __syncthreads();
    #pragma unroll
    for (int i=0;i<4;i++){
        int c = c0 + ty + i*8;
        out[((long)b*CDIM + c)*HWD + p0 + tx] = tile[tx][ty+i*8];
    }
}

// ---------------- LayerNorm over C (warp per pixel), optional residual + roll ----
__global__ void k_ln(const float* __restrict__ in, const float* __restrict__ res,
                     const float* __restrict__ gamma, const float* __restrict__ beta,
                     float* __restrict__ out, int shift){
    int warp = threadIdx.x >> 5, lane = threadIdx.x & 31;
    int pix = blockIdx.x*8 + warp;
    if (pix >= NPIX) return;
    int b = pix >> 14, rem = pix & (HWD-1);
    int h = rem >> 7, w = rem & 127;
    int sh = (h + shift) & (HDIM-1);
    int sw = (w + shift) & (WDIM-1);
    long src = ((long)b*HWD + sh*WDIM + sw)*CDIM + lane*4;
    float4 v = *(const float4*)(in + src);
    if (res){
        float4 r = *(const float4*)(res + src);
        v.x += r.x; v.y += r.y; v.z += r.z; v.w += r.w;
    }
    float s  = v.x+v.y+v.z+v.w;
    float ss = v.x*v.x+v.y*v.y+v.z*v.z+v.w*v.w;
    #pragma unroll
    for (int o=16;o;o>>=1){
        s  += __shfl_xor_sync(0xffffffffu, s,  o);
        ss += __shfl_xor_sync(0xffffffffu, ss, o);
    }
    float mean = s * (1.f/CDIM);
    float var  = ss * (1.f/CDIM) - mean*mean;
    float rstd = rsqrtf(var + EPSV);
    float4 g  = *(const float4*)(gamma + lane*4);
    float4 be = *(const float4*)(beta  + lane*4);
    float4 o4;
    o4.x = (v.x-mean)*rstd*g.x + be.x;
    o4.y = (v.y-mean)*rstd*g.y + be.y;
    o4.z = (v.z-mean)*rstd*g.z + be.z;
    o4.w = (v.w-mean)*rstd*g.w + be.w;
    *(float4*)(out + (long)pix*CDIM + lane*4) = o4;
}

// ---------------- GEMM: C[m,n] = sum_k A[m,k]*W[n,k] (+res), 128x64 tile ------
__global__ void __launch_bounds__(256)
k_gemm(const float* __restrict__ A, const float* __restrict__ Wt,
       float* __restrict__ Cc, const float* __restrict__ res,
       int M, int N, int K){
    __shared__ float As[2][16][132];
    __shared__ float Bs[2][16][68];
    int tid = threadIdx.x;
    int m0 = blockIdx.y*128, n0 = blockIdx.x*64;
    int lr = tid >> 2, lk = (tid & 3)*4;
    int ty = tid >> 4, tx = tid & 15;       // m: ty*8, n: tx*4
    const float* Ap0 = A + (long)(m0+lr)*K;
    const float* Ap1 = A + (long)(m0+lr+64)*K;
    const float* Bp  = Wt + (long)(n0+lr)*K;
    bool bval = (n0+lr) < N;
    int KT = (K+15) >> 4;

    float4 ra0, ra1, rb;
    // initial fetch kt=0
    {
        int k = lk;
        if (k+3 < K){ ra0 = *(const float4*)(Ap0+k); ra1 = *(const float4*)(Ap1+k); }
        else {
            float t0[4], t1[4];
            #pragma unroll
            for (int j=0;j<4;j++){ t0[j] = (k+j<K)?Ap0[k+j]:0.f; t1[j] = (k+j<K)?Ap1[k+j]:0.f; }
            ra0 = make_float4(t0[0],t0[1],t0[2],t0[3]);
            ra1 = make_float4(t1[0],t1[1],t1[2],t1[3]);
        }
        if (bval && k+3 < K) rb = *(const float4*)(Bp+k);
        else {
            float t[4];
            #pragma unroll
            for (int j=0;j<4;j++) t[j] = (bval && k+j<K)?Bp[k+j]:0.f;
            rb = make_float4(t[0],t[1],t[2],t[3]);
        }
        float a0[4]={ra0.x,ra0.y,ra0.z,ra0.w};
        float a1[4]={ra1.x,ra1.y,ra1.z,ra1.w};
        float bb[4]={rb.x,rb.y,rb.z,rb.w};
        #pragma unroll
        for (int j=0;j<4;j++){
            As[0][lk+j][lr]    = a0[j];
            As[0][lk+j][lr+64] = a1[j];
            Bs[0][lk+j][lr]    = bb[j];
        }
    }
    __syncthreads();

    float acc[8][4] = {};
    int cur = 0;
    for (int kt = 0; kt < KT; kt++){
        if (kt+1 < KT){
            int k = (kt+1)*16 + lk;
            if (k+3 < K){ ra0 = *(const float4*)(Ap0+k); ra1 = *(const float4*)(Ap1+k); }
            else {
                float t0[4], t1[4];
                #pragma unroll
                for (int j=0;j<4;j++){ t0[j] = (k+j<K)?Ap0[k+j]:0.f; t1[j] = (k+j<K)?Ap1[k+j]:0.f; }
                ra0 = make_float4(t0[0],t0[1],t0[2],t0[3]);
                ra1 = make_float4(t1[0],t1[1],t1[2],t1[3]);
            }
            if (bval && k+3 < K) rb = *(const float4*)(Bp+k);
            else {
                float t[4];
                #pragma unroll
                for (int j=0;j<4;j++) t[j] = (bval && k+j<K)?Bp[k+j]:0.f;
                rb = make_float4(t[0],t[1],t[2],t[3]);
            }
        }
        #pragma unroll
        for (int k=0;k<16;k++){
            float4 av0 = *(const float4*)&As[cur][k][ty*8];
            float4 av1 = *(const float4*)&As[cur][k][ty*8+4];
            float4 bv  = *(const float4*)&Bs[cur][k][tx*4];
            float aa[8] = {av0.x,av0.y,av0.z,av0.w,av1.x,av1.y,av1.z,av1.w};
            float bb[4] = {bv.x,bv.y,bv.z,bv.w};
            #pragma unroll
            for (int i=0;i<8;i++)
                #pragma unroll
                for (int j=0;j<4;j++)
                    acc[i][j] += aa[i]*bb[j];
        }
        if (kt+1 < KT){
            int nb = cur^1;
            float a0[4]={ra0.x,ra0.y,ra0.z,ra0.w};
            float a1[4]={ra1.x,ra1.y,ra1.z,ra1.w};
            float bb[4]={rb.x,rb.y,rb.z,rb.w};
            #pragma unroll
            for (int j=0;j<4;j++){
                As[nb][lk+j][lr]    = a0[j];
                As[nb][lk+j][lr+64] = a1[j];
                Bs[nb][lk+j][lr]    = bb[j];
            }
        }
        __syncthreads();
        cur ^= 1;
    }

    #pragma unroll
    for (int i=0;i<8;i++){
        int m = m0 + ty*8 + i;
        long base = (long)m*N + n0 + tx*4;
        #pragma unroll
        for (int j=0;j<4;j++){
            int n = n0 + tx*4 + j;
            if (n < N){
                float v = acc[i][j];
                if (res) v += res[base + j];
                Cc[base + j] = v;
            }
        }
    }
}

// ---------------- weight transpose [CHN][9] -> [9][CHN] ----------------
__global__ void k_wtrans(const float* __restrict__ w, float* __restrict__ o, int CHN){
    int i = blockIdx.x*256 + threadIdx.x;
    if (i >= CHN*9) return;
    int c = i/9, t = i - c*9;
    o[t*CHN + c] = w[i];
}

// ---------------- depthwise 3x3 vectorized: thread = 4ch x 4 pixels --------
__global__ void k_dwconv(const float* __restrict__ in, const float* __restrict__ wt,
                         float* __restrict__ out, int CHN, int dogelu){
    int cq = threadIdx.x;          // CHN/4 channel quads
    int py = threadIdx.y;          // 0..1
    int pix0 = blockIdx.x*8;       // 8 consecutive w-pixels, same row
    int b = pix0 >> 14;
    int h = (pix0 >> 7) & 127;
    int w0 = pix0 & 127;
    int c4 = cq*4;
    float4 wv[9];
    #pragma unroll
    for (int t=0;t<9;t++) wv[t] = *(const float4*)(wt + t*CHN + c4);
    const float* base = in + (long)b*HWD*CHN + c4;
    float* obase = out + (long)b*HWD*CHN + c4;
    #pragma unroll
    for (int i=0;i<4;i++){
        int w = w0 + py + i*2;
        float4 acc = make_float4(0.f,0.f,0.f,0.f);
        #pragma unroll
        for (int dy=-1;dy<=1;dy++){
            int hh = h + dy;
            if ((unsigned)hh >= HDIM) continue;
            #pragma unroll
            for (int dx=-1;dx<=1;dx++){
                int ww = w + dx;
                if ((unsigned)ww >= WDIM) continue;
                float4 v = *(const float4*)(base + ((long)hh*WDIM + ww)*CHN);
                float4 wk = wv[(dy+1)*3 + dx + 1];
                acc.x += wk.x*v.x; acc.y += wk.y*v.y;
                acc.z += wk.z*v.z; acc.w += wk.w*v.w;
            }
        }
        if (dogelu){
            acc.x = 0.5f*acc.x*(1.f + erff(acc.x*0.70710678118654752f));
            acc.y = 0.5f*acc.y*(1.f + erff(acc.y*0.70710678118654752f));
            acc.z = 0.5f*acc.z*(1.f + erff(acc.z*0.70710678118654752f));
            acc.w = 0.5f*acc.w*(1.f + erff(acc.w*0.70710678118654752f));
        }
        *(float4*)(obase + ((long)h*WDIM + w)*CHN) = acc;
    }
}

// ---------------- RSA window attention (one CTA per 4x4 window) --------------
__global__ void k_rsa_win(const float* __restrict__ qkv, const float* __restrict__ tempp,
                          float* __restrict__ out){
    extern __shared__ float sm[];
    float* qs = sm;          // 16*128
    float* ks = sm + 2048;
    float* vs = sm + 4096;
    float* at = sm + 6144;   // 128*128
    __shared__ float rn[32];
    int tid = threadIdx.x;   // 256
    int warp = tid >> 5, lane = tid & 31;
    int win = blockIdx.x;
    int b = win >> 10; int wrem = win & 1023;
    int wy = wrem >> 5, wx = wrem & 31;
    // load q,k,v [16][128] each (rolled input read)
    for (int i = tid; i < 6144; i += 256){
        int sec = i >> 11; int r = i & 2047; int p = r >> 7; int c = r & 127;
        int gh = wy*4 + (p>>2), gw = wx*4 + (p&3);
        sm[i] = qkv[((long)b*HWD + gh*WDIM + gw)*C3 + sec*128 + c];
    }
    __syncthreads();
    // l2 norms for q,k rows: 32 rows, one warp each
    #pragma unroll
    for (int r = warp; r < 32; r += 8){
        const float* basep = sm + (r>>4)*2048 + (r&15)*128;
        float4 v = *(const float4*)(basep + lane*4);
        float s = v.x*v.x + v.y*v.y + v.z*v.z + v.w*v.w;
        #pragma unroll
        for (int o=16;o;o>>=1) s += __shfl_xor_sync(0xffffffffu, s, o);
        if (lane == 0) rn[r] = 1.f / fmaxf(sqrtf(s), 1e-12f);
    }
    __syncthreads();
    for (int i = tid; i < 4096; i += 256){
        int sec = i >> 11; int p = (i & 2047) >> 7;
        sm[i] *= rn[sec*16 + p];
    }
    __syncthreads();
    float temp = tempp[0];
    // attn[c][d] = relu(temp * sum_p q[p][c]*k[p][d]); 8x8 frag per thread
    {
        int c0 = (tid >> 4)*8, d0 = (tid & 15)*8;
        float a2[8][8] = {};
        #pragma unroll
        for (int p=0;p<16;p++){
            float4 q0 = *(const float4*)&qs[p*128+c0];
            float4 q1 = *(const float4*)&qs[p*128+c0+4];
            float4 k0 = *(const float4*)&ks[p*128+d0];
            float4 k1 = *(const float4*)&ks[p*128+d0+4];
            float qa[8] = {q0.x,q0.y,q0.z,q0.w,q1.x,q1.y,q1.z,q1.w};
            float ka[8] = {k0.x,k0.y,k0.z,k0.w,k1.x,k1.y,k1.z,k1.w};
            #pragma unroll
            for (int i=0;i<8;i++)
                #pragma unroll
                for (int j=0;j<8;j++)
                    a2[i][j] += qa[i]*ka[j];
        }
        #pragma unroll
        for (int i=0;i<8;i++){
            float4 r0, r1;
            r0.x = fmaxf(a2[i][0]*temp, 0.f); r0.y = fmaxf(a2[i][1]*temp, 0.f);
            r0.z = fmaxf(a2[i][2]*temp, 0.f); r0.w = fmaxf(a2[i][3]*temp, 0.f);
            r1.x = fmaxf(a2[i][4]*temp, 0.f); r1.y = fmaxf(a2[i][5]*temp, 0.f);
            r1.z = fmaxf(a2[i][6]*temp, 0.f); r1.w = fmaxf(a2[i][7]*temp, 0.f);
            *(float4*)&at[(c0+i)*128 + d0]     = r0;
            *(float4*)&at[(c0+i)*128 + d0 + 4] = r1;
        }
    }
    __syncthreads();
    // out[p][d] = sum_c v[p][c]*attn[c][d]; thread = (p, 8 d's); write rolled back
    {
        int p = tid >> 4, d0 = (tid & 15)*8;
        float s0[4] = {}, s1[4] = {};
        #pragma unroll 4
        for (int c=0;c<128;c++){
            float v = vs[p*128+c];
            float4 t0 = *(const float4*)&at[c*128+d0];
            float4 t1 = *(const float4*)&at[c*128+d0+4];
            s0[0] += v*t0.x; s0[1] += v*t0.y; s0[2] += v*t0.z; s0[3] += v*t0.w;
            s1[0] += v*t1.x; s1[1] += v*t1.y; s1[2] += v*t1.z; s1[3] += v*t1.w;
        }
        int gh = wy*4 + (p>>2), gw = wx*4 + (p&3);
        int oh = (gh+2)&127, ow = (gw+2)&127;
        float* op = out + ((long)b*HWD + oh*WDIM + ow)*CDIM + d0;
        *(float4*)op     = make_float4(s0[0],s0[1],s0[2],s0[3]);
        *(float4*)(op+4) = make_float4(s1[0],s1[1],s1[2],s1[3]);
    }
}

// ---------------- GSA gram + per-channel sumsq reduction ---------------------
__global__ void k_gsa_gram(const float* __restrict__ qkv, float* __restrict__ S,
                           float* __restrict__ nq, float* __restrict__ nk){
    __shared__ float sq[32*32];
    __shared__ float sk[32*32];
    int tid = threadIdx.x;            // 256
    int blk = blockIdx.x;             // B*4*16
    int chunk = blk & 15;
    int head = (blk >> 4) & 3;
    int b = blk >> 6;
    int p0 = chunk*1024;
    int c0 = tid >> 3;
    int d0 = (tid & 7) * 4;
    float acc[4] = {0,0,0,0};
    float sumq = 0.f, sumk = 0.f;
    for (int t = 0; t < 32; t++){
        __syncthreads();
        for (int i = tid; i < 2048; i += 256){
            int pi = i >> 6;
            int vv = i & 63;
            long pix = (long)b*HWD + p0 + t*32 + pi;
            int chn = (vv < 32) ? (head*32 + vv) : (128 + head*32 + (vv-32));
            float val = qkv[pix*C3 + chn];
            if (vv < 32) sq[pi*32+vv] = val; else sk[pi*32+(vv-32)] = val;
        }
        __syncthreads();
        #pragma unroll 4
        for (int pi=0; pi<32; pi++){
            float qv = sq[pi*32 + c0];
            #pragma unroll
            for (int j=0;j<4;j++) acc[j] += qv * sk[pi*32 + d0 + j];
        }
        if (tid < 32){
            for (int pi=0;pi<32;pi++){ float v = sq[pi*32+tid]; sumq += v*v; }
        } else if (tid < 64){
            int c = tid-32;
            for (int pi=0;pi<32;pi++){ float v = sk[pi*32+c]; sumk += v*v; }
        }
    }
    int sbase = ((b*NHEADS + head)*32 + c0)*32 + d0;
    #pragma unroll
    for (int j=0;j<4;j++) atomicAdd(&S[sbase+j], acc[j]);
    if (tid < 32) atomicAdd(&nq[b*CDIM + head*32 + tid], sumq);
    else if (tid < 64) atomicAdd(&nk[b*CDIM + head*32 + (tid-32)], sumk);
}

// ---------------- GSA attn finalize (in-place on S) --------------------------
__global__ void k_gsa_attn(float* __restrict__ S, const float* __restrict__ nq,
                           const float* __restrict__ nk, const float* __restrict__ tempp){
    int i = blockIdx.x*256 + threadIdx.x;
    if (i >= BATCH*NHEADS*32*32) return;
    int d = i & 31; int c = (i>>5)&31; int head = (i>>10)&3; int b = i>>12;
    float qn = fmaxf(sqrtf(nq[b*CDIM+head*32+c]), 1e-12f);
    float kn = fmaxf(sqrtf(nk[b*CDIM+head*32+d]), 1e-12f);
    S[i] = fmaxf(S[i]*tempp[0]/(qn*kn), 0.f);
}

// ---------------- GSA output: out[c,n] = sum_d attn[c,d] v[d,n] --------------
__global__ void k_gsa_out(const float* __restrict__ qkv, const float* __restrict__ A,
                          float* __restrict__ out){
    __shared__ float at[NHEADS*32*33];
    __shared__ float vsm[8][128];
    int tid = threadIdx.x;               // 256
    int warp = tid >> 5, lane = tid & 31;
    int b = (blockIdx.x*8) / HWD;
    for (int i = tid; i < NHEADS*32*32; i += 256)
        at[(i>>5)*33 + (i&31)] = A[b*NHEADS*32*32 + i];
    __syncthreads();
    long pix = (long)blockIdx.x*8 + warp;
    float4 v4 = *(const float4*)(qkv + pix*C3 + 256 + lane*4);
    vsm[warp][lane*4+0]=v4.x; vsm[warp][lane*4+1]=v4.y;
    vsm[warp][lane*4+2]=v4.z; vsm[warp][lane*4+3]=v4.w;
    __syncwarp();
    #pragma unroll
    for (int hd=0; hd<4; hd++){
        const float* arow = at + (hd*32 + lane)*33;
        const float* vrow = vsm[warp] + hd*32;
        float s = 0.f;
        #pragma unroll
        for (int d=0; d<32; d++) s += arow[d]*vrow[d];
        out[pix*CDIM + hd*32 + lane] = s;
    }
}

// =============================== host ===============================
static float* sym(const void* s){
    void* p = nullptr;
    cudaGetSymbolAddress(&p, s);
    return (float*)p;
}

extern "C" void kernel_launch(void* const* d_in, const int* in_sizes, int n_in,
                              void* d_out, int out_size){
    const float* x        = (const float*)d_in[0];
    const float* w_s0     = (const float*)d_in[1];
    const float* b_s0     = (const float*)d_in[2];
    const float* w_s2     = (const float*)d_in[3];
    const float* b_s2     = (const float*)d_in[4];
    const float* rsa_qkv  = (const float*)d_in[5];
    const float* rsa_dw   = (const float*)d_in[6];
    const float* rsa_proj = (const float*)d_in[7];
    const float* rsa_temp = (const float*)d_in[8];
    const float* ffs_in   = (const float*)d_in[9];
    const float* ffs_dw   = (const float*)d_in[10];
    const float* ffs_out  = (const float*)d_in[11];
    const float* w_c0     = (const float*)d_in[12];
    const float* b_c0     = (const float*)d_in[13];
    const float* w_c2     = (const float*)d_in[14];
    const float* b_c2     = (const float*)d_in[15];
    const float* gsa_qkv  = (const float*)d_in[16];
    const float* gsa_dw   = (const float*)d_in[17];
    const float* gsa_proj = (const float*)d_in[18];
    const float* gsa_temp = (const float*)d_in[19];
    const float* ffc_in   = (const float*)d_in[20];
    const float* ffc_dw   = (const float*)d_in[21];
    const float* ffc_out  = (const float*)d_in[22];
    float* out = (float*)d_out;

    float* xt  = sym(g_xt);
    float* ln  = sym(g_ln);
    float* q1  = sym(g_qkv1);
    float* q2  = sym(g_qkv2);
    float* att = sym(g_att);
    float* x1  = sym(g_x1);
    float* y   = sym(g_y);
    float* h1  = sym(g_h1);
    float* h2  = sym(g_h2);
    float* S   = sym(g_S);
    float* nq  = sym(g_nq);
    float* nk  = sym(g_nk);
    float* wt  = sym(g_wt);

    cudaFuncSetAttribute(k_rsa_win, cudaFuncAttributeMaxDynamicSharedMemorySize, 90112);

    dim3 tb(32,8);
    dim3 tg(HWD/32, CDIM/32, BATCH);
    dim3 dwb3(C3/4, 2);      // 96x2
    dim3 dwbh(HIDD/4, 2);    // 85x2
    int dwg = NPIX/8;

    // ---- spatial (RSA) block ----
    k_nchw2nhwc<<<tg, tb>>>(x, xt);
    k_ln<<<NPIX/8, 256>>>(xt, nullptr, w_s0, b_s0, ln, 2);                   // LN + roll(-2,-2)
    k_gemm<<<dim3(6,256), 256>>>(ln, rsa_qkv, q1, nullptr, NPIX, C3, CDIM);
    k_wtrans<<<(C3*9+255)/256, 256>>>(rsa_dw, wt, C3);
    k_dwconv<<<dwg, dwb3>>>(q1, wt, q2, C3, 0);
    k_rsa_win<<<BATCH*1024, 256, 90112>>>(q2, rsa_temp, att);                // + roll back
    k_gemm<<<dim3(2,256), 256>>>(att, rsa_proj, x1, nullptr, NPIX, CDIM, CDIM);
    k_ln<<<NPIX/8, 256>>>(x1, xt, w_s2, b_s2, ln, 0);                        // LN(x_ + x)
    k_gemm<<<dim3(6,256), 256>>>(ln, ffs_in, h1, nullptr, NPIX, HIDD, CDIM);
    k_wtrans<<<(HIDD*9+255)/256, 256>>>(ffs_dw, wt, HIDD);
    k_dwconv<<<dwg, dwbh>>>(h1, wt, h2, HIDD, 1);
    k_gemm<<<dim3(2,256), 256>>>(h2, ffs_out, y, x1, NPIX, CDIM, HIDD);      // + residual

    // ---- channel (GSA) block ----
    k_ln<<<NPIX/8, 256>>>(y, nullptr, w_c0, b_c0, ln, 0);
    k_gemm<<<dim3(6,256), 256>>>(ln, gsa_qkv, q1, nullptr, NPIX, C3, CDIM);
    k_wtrans<<<(C3*9+255)/256, 256>>>(gsa_dw, wt, C3);
    k_dwconv<<<dwg, dwb3>>>(q1, wt, q2, C3, 0);
    cudaMemsetAsync(S,  0, BATCH*NHEADS*32*32*sizeof(float));
    cudaMemsetAsync(nq, 0, BATCH*CDIM*sizeof(float));
    cudaMemsetAsync(nk, 0, BATCH*CDIM*sizeof(float));
    k_gsa_gram<<<BATCH*NHEADS*16, 256>>>(q2, S, nq, nk);
    k_gsa_attn<<<(BATCH*NHEADS*32*32+255)/256, 256>>>(S, nq, nk, gsa_temp);
    k_gsa_out<<<NPIX/8, 256>>>(q2, S, att);
    k_gemm<<<dim3(2,256), 256>>>(att, gsa_proj, x1, nullptr, NPIX, CDIM, CDIM);
    k_ln<<<NPIX/8, 256>>>(x1, y, w_c2, b_c2, ln, 0);                         // LN(x_ + x2)
    k_gemm<<<dim3(6,256), 256>>>(ln, ffc_in, h1, nullptr, NPIX, HIDD, CDIM);
    k_wtrans<<<(HIDD*9+255)/256, 256>>>(ffc_dw, wt, HIDD);
    k_dwconv<<<dwg, dwbh>>>(h1, wt, h2, HIDD, 1);
    k_gemm<<<dim3(2,256), 256>>>(h2, ffc_out, att, nullptr, NPIX, CDIM, HIDD);
    k_final<<<tg, tb>>>(att, x1, out);                                       // + x_, NHWC->NCHW
}

// round 5
// speedup vs baseline: 1.7871x; 1.2669x over previous
#include <cuda_runtime.h>
#include <cuda_bf16.h>
#include <math.h>
#include <stdint.h>

#define BATCH 2
#define CDIM 128
#define HDIM 128
#define WDIM 128
#define HWD (HDIM*WDIM)           // 16384
#define NPIX (BATCH*HWD)          // 32768
#define C3 (3*CDIM)               // 384
#define HIDD 340
#define NHEADS 4
#define EPSV 1e-6f

// ---------------- scratch (static device allocations) ----------------
__device__ float g_xt  [NPIX*CDIM];
__device__ float g_ln  [NPIX*CDIM];
__device__ float g_qkv1[NPIX*C3];
__device__ float g_qkv2[NPIX*C3];
__device__ float g_att [NPIX*CDIM];
__device__ float g_x1  [NPIX*CDIM];
__device__ float g_y   [NPIX*CDIM];
__device__ float g_h1  [NPIX*HIDD];
__device__ float g_h2  [NPIX*HIDD];
__device__ float g_S   [BATCH*NHEADS*32*32];
__device__ float g_nq  [BATCH*CDIM];
__device__ float g_nk  [BATCH*CDIM];
__device__ float g_wt  [4][C3*9];     // transposed dwconv weights [9][CHN] x4

// =================== warp MMA helpers ===================
__device__ __forceinline__ uint32_t smem_u32(const void* p){
    uint32_t a;
    asm("{ .reg .u64 t; cvta.to.shared.u64 t, %1; cvt.u32.u64 %0, t; }" : "=r"(a) : "l"(p));
    return a;
}
__device__ __forceinline__ void ldsm_x4(uint32_t& r0, uint32_t& r1, uint32_t& r2, uint32_t& r3,
                                        uint32_t addr){
    asm volatile("ldmatrix.sync.aligned.m8n8.x4.shared.b16 {%0,%1,%2,%3}, [%4];"
                 : "=r"(r0), "=r"(r1), "=r"(r2), "=r"(r3) : "r"(addr));
}
__device__ __forceinline__ void mma_bf16(float* d, const uint32_t* a, const uint32_t* b){
    asm volatile("mma.sync.aligned.m16n8k16.row.col.f32.bf16.bf16.f32 "
                 "{%0,%1,%2,%3}, {%4,%5,%6,%7}, {%8,%9}, {%0,%1,%2,%3};"
                 : "+f"(d[0]), "+f"(d[1]), "+f"(d[2]), "+f"(d[3])
                 : "r"(a[0]), "r"(a[1]), "r"(a[2]), "r"(a[3]), "r"(b[0]), "r"(b[1]));
}

// ============ tensor-core GEMM: C[m,n]=sum_k A[m,k]*W[n,k] (+res) ============
// tile 128x128, K-chunks of 32 fp32 split into bf16 hi/lo, 3-pass accumulation
#define SPAD 40
__global__ void __launch_bounds__(256, 2)
k_gemm_mma(const float* __restrict__ A, const float* __restrict__ Wt,
           float* __restrict__ Cc, const float* __restrict__ res,
           int N, int K, int KC){
    __shared__ __nv_bfloat16 Ah[128][SPAD], Al[128][SPAD];
    __shared__ __nv_bfloat16 Bh[128][SPAD], Bl[128][SPAD];
    int tid = threadIdx.x, warp = tid >> 5, lane = tid & 31;
    int m0 = blockIdx.y*128, n0 = blockIdx.x*128;
    int mw = (warp & 3)*32, nw = (warp >> 2)*64;
    float acc[2][8][4];
    #pragma unroll
    for (int i=0;i<2;i++)
        #pragma unroll
        for (int j=0;j<8;j++)
            #pragma unroll
            for (int e=0;e<4;e++) acc[i][j][e] = 0.f;

    int r  = tid >> 1;            // 0..127
    int cb = (tid & 1)*16;        // 0 or 16
    const float* ap = A + (long)(m0+r)*K;
    int nrow = n0 + r;
    const float* bp = Wt + (long)nrow*K;
    bool bok = nrow < N;

    for (int kc = 0; kc < KC; kc++){
        int k0 = kc*32;
        // ---- A tile: 128 x 32 floats -> hi/lo bf16 smem ----
        #pragma unroll
        for (int j = 0; j < 16; j += 4){
            int k = k0 + cb + j;
            float4 v;
            if (k + 3 < K) v = *(const float4*)(ap + k);
            else {
                v.x = (k   < K) ? ap[k  ] : 0.f;
                v.y = (k+1 < K) ? ap[k+1] : 0.f;
                v.z = (k+2 < K) ? ap[k+2] : 0.f;
                v.w = (k+3 < K) ? ap[k+3] : 0.f;
            }
            __nv_bfloat16 hx = __float2bfloat16(v.x), hy = __float2bfloat16(v.y);
            __nv_bfloat16 hz = __float2bfloat16(v.z), hw = __float2bfloat16(v.w);
            *(__nv_bfloat162*)&Ah[r][cb+j]   = __nv_bfloat162(hx, hy);
            *(__nv_bfloat162*)&Ah[r][cb+j+2] = __nv_bfloat162(hz, hw);
            *(__nv_bfloat162*)&Al[r][cb+j]   = __nv_bfloat162(
                __float2bfloat16(v.x - __bfloat162float(hx)),
                __float2bfloat16(v.y - __bfloat162float(hy)));
            *(__nv_bfloat162*)&Al[r][cb+j+2] = __nv_bfloat162(
                __float2bfloat16(v.z - __bfloat162float(hz)),
                __float2bfloat16(v.w - __bfloat162float(hw)));
        }
        // ---- B tile: 128 x 32 floats (zero-pad beyond N/K) ----
        #pragma unroll
        for (int j = 0; j < 16; j += 4){
            int k = k0 + cb + j;
            float4 v = make_float4(0.f,0.f,0.f,0.f);
            if (bok){
                if (k + 3 < K) v = *(const float4*)(bp + k);
                else {
                    v.x = (k   < K) ? bp[k  ] : 0.f;
                    v.y = (k+1 < K) ? bp[k+1] : 0.f;
                    v.z = (k+2 < K) ? bp[k+2] : 0.f;
                    v.w = (k+3 < K) ? bp[k+3] : 0.f;
                }
            }
            __nv_bfloat16 hx = __float2bfloat16(v.x), hy = __float2bfloat16(v.y);
            __nv_bfloat16 hz = __float2bfloat16(v.z), hw = __float2bfloat16(v.w);
            *(__nv_bfloat162*)&Bh[r][cb+j]   = __nv_bfloat162(hx, hy);
            *(__nv_bfloat162*)&Bh[r][cb+j+2] = __nv_bfloat162(hz, hw);
            *(__nv_bfloat162*)&Bl[r][cb+j]   = __nv_bfloat162(
                __float2bfloat16(v.x - __bfloat162float(hx)),
                __float2bfloat16(v.y - __bfloat162float(hy)));
            *(__nv_bfloat162*)&Bl[r][cb+j+2] = __nv_bfloat162(
                __float2bfloat16(v.z - __bfloat162float(hz)),
                __float2bfloat16(v.w - __bfloat162float(hw)));
        }
        __syncthreads();

        // ldmatrix address components
        int arow = mw + ((lane >> 3) & 1)*8 + (lane & 7);
        int acolb = ((lane >> 4) & 1)*8;
        int brow = nw + ((lane >> 4) & 1)*8 + (lane & 7);
        int bcolb = ((lane >> 3) & 1)*8;

        #pragma unroll
        for (int kk = 0; kk < 32; kk += 16){
            #pragma unroll
            for (int pass = 0; pass < 3; pass++){
                const __nv_bfloat16 (*As)[SPAD] = (pass == 2) ? Al : Ah;
                const __nv_bfloat16 (*Bs)[SPAD] = (pass == 1) ? Bl : Bh;
                uint32_t a[2][4], b[8][2];
                #pragma unroll
                for (int mt = 0; mt < 2; mt++){
                    uint32_t ad = smem_u32(&As[arow + mt*16][kk + acolb]);
                    ldsm_x4(a[mt][0], a[mt][1], a[mt][2], a[mt][3], ad);
                }
                #pragma unroll
                for (int np = 0; np < 4; np++){
                    uint32_t ad = smem_u32(&Bs[brow + np*16][kk + bcolb]);
                    ldsm_x4(b[np*2][0], b[np*2][1], b[np*2+1][0], b[np*2+1][1], ad);
                }
                #pragma unroll
                for (int mt = 0; mt < 2; mt++)
                    #pragma unroll
                    for (int nt = 0; nt < 8; nt++)
                        mma_bf16(acc[mt][nt], a[mt], b[nt]);
            }
        }
        __syncthreads();
    }

    // ---- epilogue ----
    #pragma unroll
    for (int mt = 0; mt < 2; mt++){
        int mrow = m0 + mw + mt*16 + (lane >> 2);
        #pragma unroll
        for (int nt = 0; nt < 8; nt++){
            int n = n0 + nw + nt*8 + (lane & 3)*2;
            if (n < N){
                long b0 = (long)mrow*N + n;
                long b1 = (long)(mrow+8)*N + n;
                float2 v0 = make_float2(acc[mt][nt][0], acc[mt][nt][1]);
                float2 v1 = make_float2(acc[mt][nt][2], acc[mt][nt][3]);
                if (res){
                    float2 r0 = *(const float2*)(res + b0);
                    float2 r1 = *(const float2*)(res + b1);
                    v0.x += r0.x; v0.y += r0.y;
                    v1.x += r1.x; v1.y += r1.y;
                }
                *(float2*)(Cc + b0) = v0;
                *(float2*)(Cc + b1) = v1;
            }
        }
    }
}

// ---------------- NCHW -> NHWC transpose ----------------
__global__ void k_nchw2nhwc(const float* __restrict__ in, float* __restrict__ out){
    __shared__ float tile[32][33];
    int b = blockIdx.z;
    int p0 = blockIdx.x*32;
    int c0 = blockIdx.y*32;
    int tx = threadIdx.x, ty = threadIdx.y;
    #pragma unroll
    for (int i=0;i<4;i++){
        int c = c0 + ty + i*8;
        tile[ty+i*8][tx] = in[((long)b*CDIM + c)*HWD + p0 + tx];
    }
    __syncthreads();
    #pragma unroll
    for (int i=0;i<4;i++){
        int p = p0 + ty + i*8;
        out[((long)b*HWD + p)*CDIM + c0 + tx] = tile[tx][ty+i*8];
    }
}

// ---------------- NHWC (a+b) -> NCHW ----------------
__global__ void k_final(const float* __restrict__ a, const float* __restrict__ b2,
                        float* __restrict__ out){
    __shared__ float tile[32][33];
    int b = blockIdx.z;
    int p0 = blockIdx.x*32;
    int c0 = blockIdx.y*32;
    int tx = threadIdx.x, ty = threadIdx.y;
    #pragma unroll
    for (int i=0;i<4;i++){
        long idx = ((long)b*HWD + p0 + ty + i*8)*CDIM + c0 + tx;
        tile[ty+i*8][tx] = a[idx] + b2[idx];
    }
    __syncthreads();
    #pragma unroll
    for (int i=0;i<4;i++){
        int c = c0 + ty + i*8;
        out[((long)b*CDIM + c)*HWD + p0 + tx] = tile[tx][ty+i*8];
    }
}

// ---------------- LayerNorm over C (warp per pixel), optional residual + roll ----
__global__ void k_ln(const float* __restrict__ in, const float* __restrict__ res,
                     const float* __restrict__ gamma, const float* __restrict__ beta,
                     float* __restrict__ out, int shift){
    int warp = threadIdx.x >> 5, lane = threadIdx.x & 31;
    int pix = blockIdx.x*8 + warp;
    if (pix >= NPIX) return;
    int b = pix >> 14, rem = pix & (HWD-1);
    int h = rem >> 7, w = rem & 127;
    int sh = (h + shift) & (HDIM-1);
    int sw = (w + shift) & (WDIM-1);
    long src = ((long)b*HWD + sh*WDIM + sw)*CDIM + lane*4;
    float4 v = *(const float4*)(in + src);
    if (res){
        float4 r = *(const float4*)(res + src);
        v.x += r.x; v.y += r.y; v.z += r.z; v.w += r.w;
    }
    float s  = v.x+v.y+v.z+v.w;
    float ss = v.x*v.x+v.y*v.y+v.z*v.z+v.w*v.w;
    #pragma unroll
    for (int o=16;o;o>>=1){
        s  += __shfl_xor_sync(0xffffffffu, s,  o);
        ss += __shfl_xor_sync(0xffffffffu, ss, o);
    }
    float mean = s * (1.f/CDIM);
    float var  = ss * (1.f/CDIM) - mean*mean;
    float rstd = rsqrtf(var + EPSV);
    float4 g  = *(const float4*)(gamma + lane*4);
    float4 be = *(const float4*)(beta  + lane*4);
    float4 o4;
    o4.x = (v.x-mean)*rstd*g.x + be.x;
    o4.y = (v.y-mean)*rstd*g.y + be.y;
    o4.z = (v.z-mean)*rstd*g.z + be.z;
    o4.w = (v.w-mean)*rstd*g.w + be.w;
    *(float4*)(out + (long)pix*CDIM + lane*4) = o4;
}

// ---------------- weight transpose [CHN][9] -> [9][CHN] ----------------
__global__ void k_wtrans(const float* __restrict__ w, float* __restrict__ o, int CHN){
    int i = blockIdx.x*256 + threadIdx.x;
    if (i >= CHN*9) return;
    int c = i/9, t = i - c*9;
    o[t*CHN + c] = w[i];
}

// ---------------- depthwise 3x3 vectorized: thread = 4ch x 4 pixels --------
__global__ void k_dwconv(const float* __restrict__ in, const float* __restrict__ wt,
                         float* __restrict__ out, int CHN, int dogelu){
    int cq = threadIdx.x;
    int py = threadIdx.y;
    int pix0 = blockIdx.x*8;
    int b = pix0 >> 14;
    int h = (pix0 >> 7) & 127;
    int w0 = pix0 & 127;
    int c4 = cq*4;
    float4 wv[9];
    #pragma unroll
    for (int t=0;t<9;t++) wv[t] = *(const float4*)(wt + t*CHN + c4);
    const float* base = in + (long)b*HWD*CHN + c4;
    float* obase = out + (long)b*HWD*CHN + c4;
    #pragma unroll
    for (int i=0;i<4;i++){
        int w = w0 + py + i*2;
        float4 acc = make_float4(0.f,0.f,0.f,0.f);
        #pragma unroll
        for (int dy=-1;dy<=1;dy++){
            int hh = h + dy;
            if ((unsigned)hh >= HDIM) continue;
            #pragma unroll
            for (int dx=-1;dx<=1;dx++){
                int ww = w + dx;
                if ((unsigned)ww >= WDIM) continue;
                float4 v = *(const float4*)(base + ((long)hh*WDIM + ww)*CHN);
                float4 wk = wv[(dy+1)*3 + dx + 1];
                acc.x += wk.x*v.x; acc.y += wk.y*v.y;
                acc.z += wk.z*v.z; acc.w += wk.w*v.w;
            }
        }
        if (dogelu){
            acc.x = 0.5f*acc.x*(1.f + erff(acc.x*0.70710678118654752f));
            acc.y = 0.5f*acc.y*(1.f + erff(acc.y*0.70710678118654752f));
            acc.z = 0.5f*acc.z*(1.f + erff(acc.z*0.70710678118654752f));
            acc.w = 0.5f*acc.w*(1.f + erff(acc.w*0.70710678118654752f));
        }
        *(float4*)(obase + ((long)h*WDIM + w)*CHN) = acc;
    }
}

// ---------------- RSA window attention (one CTA per 4x4 window) --------------
__global__ void k_rsa_win(const float* __restrict__ qkv, const float* __restrict__ tempp,
                          float* __restrict__ out){
    extern __shared__ float sm[];
    float* qs = sm;
    float* ks = sm + 2048;
    float* vs = sm + 4096;
    float* at = sm + 6144;
    __shared__ float rn[32];
    int tid = threadIdx.x;
    int warp = tid >> 5, lane = tid & 31;
    int win = blockIdx.x;
    int b = win >> 10; int wrem = win & 1023;
    int wy = wrem >> 5, wx = wrem & 31;
    for (int i = tid; i < 6144; i += 256){
        int sec = i >> 11; int r = i & 2047; int p = r >> 7; int c = r & 127;
        int gh = wy*4 + (p>>2), gw = wx*4 + (p&3);
        sm[i] = qkv[((long)b*HWD + gh*WDIM + gw)*C3 + sec*128 + c];
    }
    __syncthreads();
    #pragma unroll
    for (int r = warp; r < 32; r += 8){
        const float* basep = sm + (r>>4)*2048 + (r&15)*128;
        float4 v = *(const float4*)(basep + lane*4);
        float s = v.x*v.x + v.y*v.y + v.z*v.z + v.w*v.w;
        #pragma unroll
        for (int o=16;o;o>>=1) s += __shfl_xor_sync(0xffffffffu, s, o);
        if (lane == 0) rn[r] = 1.f / fmaxf(sqrtf(s), 1e-12f);
    }
    __syncthreads();
    for (int i = tid; i < 4096; i += 256){
        int sec = i >> 11; int p = (i & 2047) >> 7;
        sm[i] *= rn[sec*16 + p];
    }
    __syncthreads();
    float temp = tempp[0];
    {
        int c0 = (tid >> 4)*8, d0 = (tid & 15)*8;
        float a2[8][8] = {};
        #pragma unroll
        for (int p=0;p<16;p++){
            float4 q0 = *(const float4*)&qs[p*128+c0];
            float4 q1 = *(const float4*)&qs[p*128+c0+4];
            float4 k0 = *(const float4*)&ks[p*128+d0];
            float4 k1 = *(const float4*)&ks[p*128+d0+4];
            float qa[8] = {q0.x,q0.y,q0.z,q0.w,q1.x,q1.y,q1.z,q1.w};
            float ka[8] = {k0.x,k0.y,k0.z,k0.w,k1.x,k1.y,k1.z,k1.w};
            #pragma unroll
            for (int i=0;i<8;i++)
                #pragma unroll
                for (int j=0;j<8;j++)
                    a2[i][j] += qa[i]*ka[j];
        }
        #pragma unroll
        for (int i=0;i<8;i++){
            float4 r0, r1;
            r0.x = fmaxf(a2[i][0]*temp, 0.f); r0.y = fmaxf(a2[i][1]*temp, 0.f);
            r0.z = fmaxf(a2[i][2]*temp, 0.f); r0.w = fmaxf(a2[i][3]*temp, 0.f);
            r1.x = fmaxf(a2[i][4]*temp, 0.f); r1.y = fmaxf(a2[i][5]*temp, 0.f);
            r1.z = fmaxf(a2[i][6]*temp, 0.f); r1.w = fmaxf(a2[i][7]*temp, 0.f);
            *(float4*)&at[(c0+i)*128 + d0]     = r0;
            *(float4*)&at[(c0+i)*128 + d0 + 4] = r1;
        }
    }
    __syncthreads();
    {
        int p = tid >> 4, d0 = (tid & 15)*8;
        float s0[4] = {}, s1[4] = {};
        #pragma unroll 4
        for (int c=0;c<128;c++){
            float v = vs[p*128+c];
            float4 t0 = *(const float4*)&at[c*128+d0];
            float4 t1 = *(const float4*)&at[c*128+d0+4];
            s0[0] += v*t0.x; s0[1] += v*t0.y; s0[2] += v*t0.z; s0[3] += v*t0.w;
            s1[0] += v*t1.x; s1[1] += v*t1.y; s1[2] += v*t1.z; s1[3] += v*t1.w;
        }
        int gh = wy*4 + (p>>2), gw = wx*4 + (p&3);
        int oh = (gh+2)&127, ow = (gw+2)&127;
        float* op = out + ((long)b*HWD + oh*WDIM + ow)*CDIM + d0;
        *(float4*)op     = make_float4(s0[0],s0[1],s0[2],s0[3]);
        *(float4*)(op+4) = make_float4(s1[0],s1[1],s1[2],s1[3]);
    }
}

// ---------------- GSA gram + per-channel sumsq reduction ---------------------
__global__ void k_gsa_gram(const float* __restrict__ qkv, float* __restrict__ S,
                           float* __restrict__ nq, float* __restrict__ nk){
    __shared__ float sq[32*32];
    __shared__ float sk[32*32];
    int tid = threadIdx.x;
    int blk = blockIdx.x;
    int chunk = blk & 15;
    int head = (blk >> 4) & 3;
    int b = blk >> 6;
    int p0 = chunk*1024;
    int c0 = tid >> 3;
    int d0 = (tid & 7) * 4;
    float acc[4] = {0,0,0,0};
    float sumq = 0.f, sumk = 0.f;
    for (int t = 0; t < 32; t++){
        __syncthreads();
        for (int i = tid; i < 2048; i += 256){
            int pi = i >> 6;
            int vv = i & 63;
            long pix = (long)b*HWD + p0 + t*32 + pi;
            int chn = (vv < 32) ? (head*32 + vv) : (128 + head*32 + (vv-32));
            float val = qkv[pix*C3 + chn];
            if (vv < 32) sq[pi*32+vv] = val; else sk[pi*32+(vv-32)] = val;
        }
        __syncthreads();
        #pragma unroll 4
        for (int pi=0; pi<32; pi++){
            float qv = sq[pi*32 + c0];
            #pragma unroll
            for (int j=0;j<4;j++) acc[j] += qv * sk[pi*32 + d0 + j];
        }
        if (tid < 32){
            for (int pi=0;pi<32;pi++){ float v = sq[pi*32+tid]; sumq += v*v; }
        } else if (tid < 64){
            int c = tid-32;
            for (int pi=0;pi<32;pi++){ float v = sk[pi*32+c]; sumk += v*v; }
        }
    }
    int sbase = ((b*NHEADS + head)*32 + c0)*32 + d0;
    #pragma unroll
    for (int j=0;j<4;j++) atomicAdd(&S[sbase+j], acc[j]);
    if (tid < 32) atomicAdd(&nq[b*CDIM + head*32 + tid], sumq);
    else if (tid < 64) atomicAdd(&nk[b*CDIM + head*32 + (tid-32)], sumk);
}

// ---------------- GSA attn finalize (in-place on S) --------------------------
__global__ void k_gsa_attn(float* __restrict__ S, const float* __restrict__ nq,
                           const float* __restrict__ nk, const float* __restrict__ tempp){
    int i = blockIdx.x*256 + threadIdx.x;
    if (i >= BATCH*NHEADS*32*32) return;
    int d = i & 31; int c = (i>>5)&31; int head = (i>>10)&3; int b = i>>12;
    float qn = fmaxf(sqrtf(nq[b*CDIM+head*32+c]), 1e-12f);
    float kn = fmaxf(sqrtf(nk[b*CDIM+head*32+d]), 1e-12f);
    S[i] = fmaxf(S[i]*tempp[0]/(qn*kn), 0.f);
}

// ---------------- GSA output: out[c,n] = sum_d attn[c,d] v[d,n] --------------
__global__ void k_gsa_out(const float* __restrict__ qkv, const float* __restrict__ A,
                          float* __restrict__ out){
    __shared__ float at[NHEADS*32*33];
    __shared__ float vsm[8][128];
    int tid = threadIdx.x;
    int warp = tid >> 5, lane = tid & 31;
    int b = (blockIdx.x*8) / HWD;
    for (int i = tid; i < NHEADS*32*32; i += 256)
        at[(i>>5)*33 + (i&31)] = A[b*NHEADS*32*32 + i];
    __syncthreads();
    long pix = (long)blockIdx.x*8 + warp;
    float4 v4 = *(const float4*)(qkv + pix*C3 + 256 + lane*4);
    vsm[warp][lane*4+0]=v4.x; vsm[warp][lane*4+1]=v4.y;
    vsm[warp][lane*4+2]=v4.z; vsm[warp][lane*4+3]=v4.w;
    __syncwarp();
    #pragma unroll
    for (int hd=0; hd<4; hd++){
        const float* arow = at + (hd*32 + lane)*33;
        const float* vrow = vsm[warp] + hd*32;
        float s = 0.f;
        #pragma unroll
        for (int d=0; d<32; d++) s += arow[d]*vrow[d];
        out[pix*CDIM + hd*32 + lane] = s;
    }
}

// =============================== host ===============================
static float* sym(const void* s){
    void* p = nullptr;
    cudaGetSymbolAddress(&p, s);
    return (float*)p;
}

extern "C" void kernel_launch(void* const* d_in, const int* in_sizes, int n_in,
                              void* d_out, int out_size){
    const float* x        = (const float*)d_in[0];
    const float* w_s0     = (const float*)d_in[1];
    const float* b_s0     = (const float*)d_in[2];
    const float* w_s2     = (const float*)d_in[3];
    const float* b_s2     = (const float*)d_in[4];
    const float* rsa_qkv  = (const float*)d_in[5];
    const float* rsa_dw   = (const float*)d_in[6];
    const float* rsa_proj = (const float*)d_in[7];
    const float* rsa_temp = (const float*)d_in[8];
    const float* ffs_in   = (const float*)d_in[9];
    const float* ffs_dw   = (const float*)d_in[10];
    const float* ffs_out  = (const float*)d_in[11];
    const float* w_c0     = (const float*)d_in[12];
    const float* b_c0     = (const float*)d_in[13];
    const float* w_c2     = (const float*)d_in[14];
    const float* b_c2     = (const float*)d_in[15];
    const float* gsa_qkv  = (const float*)d_in[16];
    const float* gsa_dw   = (const float*)d_in[17];
    const float* gsa_proj = (const float*)d_in[18];
    const float* gsa_temp = (const float*)d_in[19];
    const float* ffc_in   = (const float*)d_in[20];
    const float* ffc_dw   = (const float*)d_in[21];
    const float* ffc_out  = (const float*)d_in[22];
    float* out = (float*)d_out;

    float* xt  = sym(g_xt);
    float* ln  = sym(g_ln);
    float* q1  = sym(g_qkv1);
    float* q2  = sym(g_qkv2);
    float* att = sym(g_att);
    float* x1  = sym(g_x1);
    float* y   = sym(g_y);
    float* h1  = sym(g_h1);
    float* h2  = sym(g_h2);
    float* S   = sym(g_S);
    float* nq  = sym(g_nq);
    float* nk  = sym(g_nk);
    float* wt  = sym(g_wt);
    float* wt_rsa = wt;
    float* wt_ffs = wt + C3*9;
    float* wt_gsa = wt + 2*C3*9;
    float* wt_ffc = wt + 3*C3*9;

    cudaFuncSetAttribute(k_rsa_win, cudaFuncAttributeMaxDynamicSharedMemorySize, 90112);

    dim3 tb(32,8);
    dim3 tg(HWD/32, CDIM/32, BATCH);
    dim3 dwb3(C3/4, 2);
    dim3 dwbh(HIDD/4, 2);
    int dwg = NPIX/8;

    // weight transposes up front
    k_wtrans<<<(C3*9+255)/256, 256>>>(rsa_dw, wt_rsa, C3);
    k_wtrans<<<(HIDD*9+255)/256, 256>>>(ffs_dw, wt_ffs, HIDD);
    k_wtrans<<<(C3*9+255)/256, 256>>>(gsa_dw, wt_gsa, C3);
    k_wtrans<<<(HIDD*9+255)/256, 256>>>(ffc_dw, wt_ffc, HIDD);

    // ---- spatial (RSA) block ----
    k_nchw2nhwc<<<tg, tb>>>(x, xt);
    k_ln<<<NPIX/8, 256>>>(xt, nullptr, w_s0, b_s0, ln, 2);                   // LN + roll(-2,-2)
    k_gemm_mma<<<dim3(3,256), 256>>>(ln, rsa_qkv, q1, nullptr, C3, CDIM, 4);
    k_dwconv<<<dwg, dwb3>>>(q1, wt_rsa, q2, C3, 0);
    k_rsa_win<<<BATCH*1024, 256, 90112>>>(q2, rsa_temp, att);                // + roll back
    k_gemm_mma<<<dim3(1,256), 256>>>(att, rsa_proj, x1, nullptr, CDIM, CDIM, 4);
    k_ln<<<NPIX/8, 256>>>(x1, xt, w_s2, b_s2, ln, 0);                        // LN(x_ + x)
    k_gemm_mma<<<dim3(3,256), 256>>>(ln, ffs_in, h1, nullptr, HIDD, CDIM, 4);
    k_dwconv<<<dwg, dwbh>>>(h1, wt_ffs, h2, HIDD, 1);
    k_gemm_mma<<<dim3(1,256), 256>>>(h2, ffs_out, y, x1, CDIM, HIDD, 11);    // + residual

    // ---- channel (GSA) block ----
    k_ln<<<NPIX/8, 256>>>(y, nullptr, w_c0, b_c0, ln, 0);
    k_gemm_mma<<<dim3(3,256), 256>>>(ln, gsa_qkv, q1, nullptr, C3, CDIM, 4);
    k_dwconv<<<dwg, dwb3>>>(q1, wt_gsa, q2, C3, 0);
    cudaMemsetAsync(S,  0, BATCH*NHEADS*32*32*sizeof(float));
    cudaMemsetAsync(nq, 0, BATCH*CDIM*sizeof(float));
    cudaMemsetAsync(nk, 0, BATCH*CDIM*sizeof(float));
    k_gsa_gram<<<BATCH*NHEADS*16, 256>>>(q2, S, nq, nk);
    k_gsa_attn<<<(BATCH*NHEADS*32*32+255)/256, 256>>>(S, nq, nk, gsa_temp);
    k_gsa_out<<<NPIX/8, 256>>>(q2, S, att);
    k_gemm_mma<<<dim3(1,256), 256>>>(att, gsa_proj, x1, nullptr, CDIM, CDIM, 4);
    k_ln<<<NPIX/8, 256>>>(x1, y, w_c2, b_c2, ln, 0);                         // LN(x_ + x2)
    k_gemm_mma<<<dim3(3,256), 256>>>(ln, ffc_in, h1, nullptr, HIDD, CDIM, 4);
    k_dwconv<<<dwg, dwbh>>>(h1, wt_ffc, h2, HIDD, 1);
    k_gemm_mma<<<dim3(1,256), 256>>>(h2, ffc_out, att, nullptr, CDIM, HIDD, 11);
    k_final<<<tg, tb>>>(att, x1, out);                                       // + x_, NHWC->NCHW
}

// round 7
// speedup vs baseline: 1.8853x; 1.0550x over previous
#include <cuda_runtime.h>
#include <cuda_bf16.h>
#include <math.h>
#include <stdint.h>

#define BATCH 2
#define CDIM 128
#define HDIM 128
#define WDIM 128
#define HWD (HDIM*WDIM)           // 16384
#define NPIX (BATCH*HWD)          // 32768
#define C3 (3*CDIM)               // 384
#define HIDD 340
#define HIDP 352                  // padded hidden (mult of 32)
#define NHEADS 4
#define EPSV 1e-6f

typedef __nv_bfloat16 bf16;

// ---------------- scratch (static device allocations) ----------------
__device__ float g_xt  [NPIX*CDIM];
__device__ float g_qkv1[NPIX*C3];
__device__ float g_qkv2[NPIX*C3];
__device__ float g_x1  [NPIX*CDIM];
__device__ float g_y   [NPIX*CDIM];
__device__ float g_h1  [NPIX*HIDD];
__device__ float g_S   [BATCH*NHEADS*32*32];
__device__ float g_nq  [BATCH*CDIM];
__device__ float g_nk  [BATCH*CDIM];
__device__ float g_wt  [4][C3*9];       // transposed dwconv weights [9][CHN] x4
__device__ bf16  g_lnh [NPIX*CDIM];     // LN output hi/lo
__device__ bf16  g_lnl [NPIX*CDIM];
__device__ bf16  g_atth[NPIX*CDIM];     // attention output hi/lo
__device__ bf16  g_attl[NPIX*CDIM];
__device__ bf16  g_h2h [NPIX*HIDP];     // ffn hidden (post-gelu) hi/lo, K-padded
__device__ bf16  g_h2l [NPIX*HIDP];
#define WB_TOTAL 319488
__device__ bf16  g_wbh [WB_TOTAL];      // split weights hi
__device__ bf16  g_wbl [WB_TOTAL];      // split weights lo
// offsets into g_wb*
#define OFF_RQKV  0        // 384x128
#define OFF_RPROJ 49152    // 128x128
#define OFF_FSIN  65536    // 384x128 (rows padded from 340)
#define OFF_FSOUT 114688   // 128x352 (K padded from 340)
#define OFF_GQKV  159744
#define OFF_GPROJ 208896
#define OFF_FCIN  225280
#define OFF_FCOUT 274432   // 128x352

// =================== warp MMA helpers ===================
__device__ __forceinline__ uint32_t smem_u32(const void* p){
    uint32_t a;
    asm("{ .reg .u64 t; cvta.to.shared.u64 t, %1; cvt.u32.u64 %0, t; }" : "=r"(a) : "l"(p));
    return a;
}
__device__ __forceinline__ void ldsm_x4(uint32_t& r0, uint32_t& r1, uint32_t& r2, uint32_t& r3,
                                        uint32_t addr){
    asm volatile("ldmatrix.sync.aligned.m8n8.x4.shared.b16 {%0,%1,%2,%3}, [%4];"
                 : "=r"(r0), "=r"(r1), "=r"(r2), "=r"(r3) : "r"(addr));
}
__device__ __forceinline__ void mma_bf16(float* d, const uint32_t* a, const uint32_t* b){
    asm volatile("mma.sync.aligned.m16n8k16.row.col.f32.bf16.bf16.f32 "
                 "{%0,%1,%2,%3}, {%4,%5,%6,%7}, {%8,%9}, {%0,%1,%2,%3};"
                 : "+f"(d[0]), "+f"(d[1]), "+f"(d[2]), "+f"(d[3])
                 : "r"(a[0]), "r"(a[1]), "r"(a[2]), "r"(a[3]), "r"(b[0]), "r"(b[1]));
}
__device__ __forceinline__ void split2(float v, bf16& h, bf16& l){
    h = __float2bfloat16(v);
    l = __float2bfloat16(v - __bfloat162float(h));
}

// ============ bf16-split GEMM: C[m,n]=sum_k A[m,k]*W[n,k] (+res) ============
// A, B pre-split into hi/lo bf16; K padded to mult of 32; B rows padded
#define SPAD 40
__global__ void __launch_bounds__(256, 2)
k_gemm_bf(const bf16* __restrict__ Ah, const bf16* __restrict__ Al,
          const bf16* __restrict__ Bh, const bf16* __restrict__ Bl,
          float* __restrict__ Cc, const float* __restrict__ res,
          int N, int sA, int sB, int KC){
    __shared__ bf16 Ahs[128][SPAD], Als[128][SPAD];
    __shared__ bf16 Bhs[128][SPAD], Bls[128][SPAD];
    int tid = threadIdx.x, warp = tid >> 5, lane = tid & 31;
    int m0 = blockIdx.y*128, n0 = blockIdx.x*128;
    int mw = (warp & 3)*32, nw = (warp >> 2)*64;
    float acc[2][8][4];
    #pragma unroll
    for (int i=0;i<2;i++)
        #pragma unroll
        for (int j=0;j<8;j++)
            #pragma unroll
            for (int e=0;e<4;e++) acc[i][j][e] = 0.f;

    int r  = tid >> 1;            // 0..127
    int cb = (tid & 1)*16;        // 0 or 16
    const bf16* pAh = Ah + (long)(m0+r)*sA + cb;
    const bf16* pAl = Al + (long)(m0+r)*sA + cb;
    const bf16* pBh = Bh + (long)(n0+r)*sB + cb;
    const bf16* pBl = Bl + (long)(n0+r)*sB + cb;

    int arow = mw + ((lane >> 3) & 1)*8 + (lane & 7);
    int acolb = ((lane >> 4) & 1)*8;
    int brow = nw + ((lane >> 4) & 1)*8 + (lane & 7);
    int bcolb = ((lane >> 3) & 1)*8;

    for (int kc = 0; kc < KC; kc++){
        int k0 = kc*32;
        *(uint4*)&Ahs[r][cb]   = *(const uint4*)(pAh + k0);
        *(uint4*)&Ahs[r][cb+8] = *(const uint4*)(pAh + k0 + 8);
        *(uint4*)&Als[r][cb]   = *(const uint4*)(pAl + k0);
        *(uint4*)&Als[r][cb+8] = *(const uint4*)(pAl + k0 + 8);
        *(uint4*)&Bhs[r][cb]   = *(const uint4*)(pBh + k0);
        *(uint4*)&Bhs[r][cb+8] = *(const uint4*)(pBh + k0 + 8);
        *(uint4*)&Bls[r][cb]   = *(const uint4*)(pBl + k0);
        *(uint4*)&Bls[r][cb+8] = *(const uint4*)(pBl + k0 + 8);
        __syncthreads();

        #pragma unroll
        for (int kk = 0; kk < 32; kk += 16){
            #pragma unroll
            for (int pass = 0; pass < 3; pass++){
                const bf16 (*As)[SPAD] = (pass == 2) ? Als : Ahs;
                const bf16 (*Bs)[SPAD] = (pass == 1) ? Bls : Bhs;
                uint32_t a[2][4], b[8][2];
                #pragma unroll
                for (int mt = 0; mt < 2; mt++){
                    uint32_t ad = smem_u32(&As[arow + mt*16][kk + acolb]);
                    ldsm_x4(a[mt][0], a[mt][1], a[mt][2], a[mt][3], ad);
                }
                #pragma unroll
                for (int np = 0; np < 4; np++){
                    uint32_t ad = smem_u32(&Bs[brow + np*16][kk + bcolb]);
                    ldsm_x4(b[np*2][0], b[np*2][1], b[np*2+1][0], b[np*2+1][1], ad);
                }
                #pragma unroll
                for (int mt = 0; mt < 2; mt++)
                    #pragma unroll
                    for (int nt = 0; nt < 8; nt++)
                        mma_bf16(acc[mt][nt], a[mt], b[nt]);
            }
        }
        __syncthreads();
    }

    // ---- epilogue ----
    #pragma unroll
    for (int mt = 0; mt < 2; mt++){
        int mrow = m0 + mw + mt*16 + (lane >> 2);
        #pragma unroll
        for (int nt = 0; nt < 8; nt++){
            int n = n0 + nw + nt*8 + (lane & 3)*2;
            if (n < N){
                long b0 = (long)mrow*N + n;
                long b1 = (long)(mrow+8)*N + n;
                float2 v0 = make_float2(acc[mt][nt][0], acc[mt][nt][1]);
                float2 v1 = make_float2(acc[mt][nt][2], acc[mt][nt][3]);
                if (res){
                    float2 r0 = *(const float2*)(res + b0);
                    float2 r1 = *(const float2*)(res + b1);
                    v0.x += r0.x; v0.y += r0.y;
                    v1.x += r1.x; v1.y += r1.y;
                }
                *(float2*)(Cc + b0) = v0;
                *(float2*)(Cc + b1) = v1;
            }
        }
    }
}

// ---------------- weight split: fp32 [Nr][Kr] -> padded bf16 hi/lo [Npad][Kpad]
__global__ void k_wsplit(const float* __restrict__ w, bf16* __restrict__ oh,
                         bf16* __restrict__ ol, int Nr, int Kr, int Npad, int Kpad){
    int i = blockIdx.x*256 + threadIdx.x;
    if (i >= Npad*Kpad) return;
    int rr = i / Kpad, c = i - rr*Kpad;
    float v = (rr < Nr && c < Kr) ? w[(long)rr*Kr + c] : 0.f;
    bf16 h, l; split2(v, h, l);
    oh[i] = h; ol[i] = l;
}

// ---------------- NCHW -> NHWC transpose ----------------
__global__ void k_nchw2nhwc(const float* __restrict__ in, float* __restrict__ out){
    __shared__ float tile[32][33];
    int b = blockIdx.z;
    int p0 = blockIdx.x*32;
    int c0 = blockIdx.y*32;
    int tx = threadIdx.x, ty = threadIdx.y;
    #pragma unroll
    for (int i=0;i<4;i++){
        int c = c0 + ty + i*8;
        tile[ty+i*8][tx] = in[((long)b*CDIM + c)*HWD + p0 + tx];
    }
    __syncthreads();
    #pragma unroll
    for (int i=0;i<4;i++){
        int p = p0 + ty + i*8;
        out[((long)b*HWD + p)*CDIM + c0 + tx] = tile[tx][ty+i*8];
    }
}

// ---------------- NHWC (a+b) -> NCHW ----------------
__global__ void k_final(const float* __restrict__ a, const float* __restrict__ b2,
                        float* __restrict__ out){
    __shared__ float tile[32][33];
    int b = blockIdx.z;
    int p0 = blockIdx.x*32;
    int c0 = blockIdx.y*32;
    int tx = threadIdx.x, ty = threadIdx.y;
    #pragma unroll
    for (int i=0;i<4;i++){
        long idx = ((long)b*HWD + p0 + ty + i*8)*CDIM + c0 + tx;
        tile[ty+i*8][tx] = a[idx] + b2[idx];
    }
    __syncthreads();
    #pragma unroll
    for (int i=0;i<4;i++){
        int c = c0 + ty + i*8;
        out[((long)b*CDIM + c)*HWD + p0 + tx] = tile[tx][ty+i*8];
    }
}

// ------ LayerNorm over C (warp per pixel), optional residual+roll, bf16 hi/lo out
__global__ void k_ln(const float* __restrict__ in, const float* __restrict__ res,
                     const float* __restrict__ gamma, const float* __restrict__ beta,
                     bf16* __restrict__ oh, bf16* __restrict__ ol, int shift){
    int warp = threadIdx.x >> 5, lane = threadIdx.x & 31;
    int pix = blockIdx.x*8 + warp;
    if (pix >= NPIX) return;
    int b = pix >> 14, rem = pix & (HWD-1);
    int h = rem >> 7, w = rem & 127;
    int sh = (h + shift) & (HDIM-1);
    int sw = (w + shift) & (WDIM-1);
    long src = ((long)b*HWD + sh*WDIM + sw)*CDIM + lane*4;
    float4 v = *(const float4*)(in + src);
    if (res){
        float4 r = *(const float4*)(res + src);
        v.x += r.x; v.y += r.y; v.z += r.z; v.w += r.w;
    }
    float s  = v.x+v.y+v.z+v.w;
    float ss = v.x*v.x+v.y*v.y+v.z*v.z+v.w*v.w;
    #pragma unroll
    for (int o=16;o;o>>=1){
        s  += __shfl_xor_sync(0xffffffffu, s,  o);
        ss += __shfl_xor_sync(0xffffffffu, ss, o);
    }
    float mean = s * (1.f/CDIM);
    float var  = ss * (1.f/CDIM) - mean*mean;
    float rstd = rsqrtf(var + EPSV);
    float4 g  = *(const float4*)(gamma + lane*4);
    float4 be = *(const float4*)(beta  + lane*4);
    float o0 = (v.x-mean)*rstd*g.x + be.x;
    float o1 = (v.y-mean)*rstd*g.y + be.y;
    float o2 = (v.z-mean)*rstd*g.z + be.z;
    float o3 = (v.w-mean)*rstd*g.w + be.w;
    bf16 hh[4], ll[4];
    split2(o0, hh[0], ll[0]); split2(o1, hh[1], ll[1]);
    split2(o2, hh[2], ll[2]); split2(o3, hh[3], ll[3]);
    long dst = (long)pix*CDIM + lane*4;
    *(uint2*)(oh + dst) = *(uint2*)hh;
    *(uint2*)(ol + dst) = *(uint2*)ll;
}

// ---------------- weight transpose [CHN][9] -> [9][CHN] ----------------
__global__ void k_wtrans(const float* __restrict__ w, float* __restrict__ o, int CHN){
    int i = blockIdx.x*256 + threadIdx.x;
    if (i >= CHN*9) return;
    int c = i/9, t = i - c*9;
    o[t*CHN + c] = w[i];
}

// ---------------- depthwise 3x3, fp32 out (qkv path) --------
__global__ void k_dwconv(const float* __restrict__ in, const float* __restrict__ wt,
                         float* __restrict__ out, int CHN){
    int cq = threadIdx.x;
    int py = threadIdx.y;
    int pix0 = blockIdx.x*8;
    int b = pix0 >> 14;
    int h = (pix0 >> 7) & 127;
    int w0 = pix0 & 127;
    int c4 = cq*4;
    float4 wv[9];
    #pragma unroll
    for (int t=0;t<9;t++) wv[t] = *(const float4*)(wt + t*CHN + c4);
    const float* base = in + (long)b*HWD*CHN + c4;
    float* obase = out + (long)b*HWD*CHN + c4;
    #pragma unroll
    for (int i=0;i<4;i++){
        int w = w0 + py + i*2;
        float4 acc = make_float4(0.f,0.f,0.f,0.f);
        #pragma unroll
        for (int dy=-1;dy<=1;dy++){
            int hh = h + dy;
            if ((unsigned)hh >= HDIM) continue;
            #pragma unroll
            for (int dx=-1;dx<=1;dx++){
                int ww = w + dx;
                if ((unsigned)ww >= WDIM) continue;
                float4 v = *(const float4*)(base + ((long)hh*WDIM + ww)*CHN);
                float4 wk = wv[(dy+1)*3 + dx + 1];
                acc.x += wk.x*v.x; acc.y += wk.y*v.y;
                acc.z += wk.z*v.z; acc.w += wk.w*v.w;
            }
        }
        *(float4*)(obase + ((long)h*WDIM + w)*CHN) = acc;
    }
}

// -------- depthwise 3x3 + gelu -> bf16 hi/lo out, K-padded to HIDP --------
__global__ void k_dwconv_gelu(const float* __restrict__ in, const float* __restrict__ wt,
                              bf16* __restrict__ oh, bf16* __restrict__ ol){
    int cq = threadIdx.x;          // 0..87 (HIDP/4)
    int py = threadIdx.y;          // 0..1
    int pix0 = blockIdx.x*8;
    int b = pix0 >> 14;
    int h = (pix0 >> 7) & 127;
    int w0 = pix0 & 127;
    int c4 = cq*4;
    bool pad = (c4 >= HIDD);
    float4 wv[9];
    if (!pad){
        #pragma unroll
        for (int t=0;t<9;t++) wv[t] = *(const float4*)(wt + t*HIDD + c4);
    }
    const float* base = in + (long)b*HWD*HIDD + c4;
    long obase = (long)b*HWD*HIDP + c4;
    #pragma unroll
    for (int i=0;i<4;i++){
        int w = w0 + py + i*2;
        bf16 hh[4] = {}, ll[4] = {};
        if (!pad){
            float4 acc = make_float4(0.f,0.f,0.f,0.f);
            #pragma unroll
            for (int dy=-1;dy<=1;dy++){
                int hy = h + dy;
                if ((unsigned)hy >= HDIM) continue;
                #pragma unroll
                for (int dx=-1;dx<=1;dx++){
                    int ww = w + dx;
                    if ((unsigned)ww >= WDIM) continue;
                    float4 v = *(const float4*)(base + ((long)hy*WDIM + ww)*HIDD);
                    float4 wk = wv[(dy+1)*3 + dx + 1];
                    acc.x += wk.x*v.x; acc.y += wk.y*v.y;
                    acc.z += wk.z*v.z; acc.w += wk.w*v.w;
                }
            }
            acc.x = 0.5f*acc.x*(1.f + erff(acc.x*0.70710678118654752f));
            acc.y = 0.5f*acc.y*(1.f + erff(acc.y*0.70710678118654752f));
            acc.z = 0.5f*acc.z*(1.f + erff(acc.z*0.70710678118654752f));
            acc.w = 0.5f*acc.w*(1.f + erff(acc.w*0.70710678118654752f));
            split2(acc.x, hh[0], ll[0]); split2(acc.y, hh[1], ll[1]);
            split2(acc.z, hh[2], ll[2]); split2(acc.w, hh[3], ll[3]);
        }
        long o = obase + ((long)h*WDIM + w)*HIDP;
        *(uint2*)(oh + o) = *(uint2*)hh;
        *(uint2*)(ol + o) = *(uint2*)ll;
    }
}

// ---------------- RSA window attention (one CTA per 4x4 window) --------------
__global__ void k_rsa_win(const float* __restrict__ qkv, const float* __restrict__ tempp,
                          bf16* __restrict__ oh, bf16* __restrict__ ol){
    extern __shared__ float sm[];
    float* qs = sm;
    float* ks = sm + 2048;
    float* vs = sm + 4096;
    float* at = sm + 6144;
    __shared__ float rn[32];
    int tid = threadIdx.x;
    int warp = tid >> 5, lane = tid & 31;
    int win = blockIdx.x;
    int b = win >> 10; int wrem = win & 1023;
    int wy = wrem >> 5, wx = wrem & 31;
    for (int i = tid; i < 6144; i += 256){
        int sec = i >> 11; int r = i & 2047; int p = r >> 7; int c = r & 127;
        int gh = wy*4 + (p>>2), gw = wx*4 + (p&3);
        sm[i] = qkv[((long)b*HWD + gh*WDIM + gw)*C3 + sec*128 + c];
    }
    __syncthreads();
    #pragma unroll
    for (int r = warp; r < 32; r += 8){
        const float* basep = sm + (r>>4)*2048 + (r&15)*128;
        float4 v = *(const float4*)(basep + lane*4);
        float s = v.x*v.x + v.y*v.y + v.z*v.z + v.w*v.w;
        #pragma unroll
        for (int o=16;o;o>>=1) s += __shfl_xor_sync(0xffffffffu, s, o);
        if (lane == 0) rn[r] = 1.f / fmaxf(sqrtf(s), 1e-12f);
    }
    __syncthreads();
    for (int i = tid; i < 4096; i += 256){
        int sec = i >> 11; int p = (i & 2047) >> 7;
        sm[i] *= rn[sec*16 + p];
    }
    __syncthreads();
    float temp = tempp[0];
    {
        int c0 = (tid >> 4)*8, d0 = (tid & 15)*8;
        float a2[8][8] = {};
        #pragma unroll
        for (int p=0;p<16;p++){
            float4 q0 = *(const float4*)&qs[p*128+c0];
            float4 q1 = *(const float4*)&qs[p*128+c0+4];
            float4 k0 = *(const float4*)&ks[p*128+d0];
            float4 k1 = *(const float4*)&ks[p*128+d0+4];
            float qa[8] = {q0.x,q0.y,q0.z,q0.w,q1.x,q1.y,q1.z,q1.w};
            float ka[8] = {k0.x,k0.y,k0.z,k0.w,k1.x,k1.y,k1.z,k1.w};
            #pragma unroll
            for (int i=0;i<8;i++)
                #pragma unroll
                for (int j=0;j<8;j++)
                    a2[i][j] += qa[i]*ka[j];
        }
        #pragma unroll
        for (int i=0;i<8;i++){
            float4 r0, r1;
            r0.x = fmaxf(a2[i][0]*temp, 0.f); r0.y = fmaxf(a2[i][1]*temp, 0.f);
            r0.z = fmaxf(a2[i][2]*temp, 0.f); r0.w = fmaxf(a2[i][3]*temp, 0.f);
            r1.x = fmaxf(a2[i][4]*temp, 0.f); r1.y = fmaxf(a2[i][5]*temp, 0.f);
            r1.z = fmaxf(a2[i][6]*temp, 0.f); r1.w = fmaxf(a2[i][7]*temp, 0.f);
            *(float4*)&at[(c0+i)*128 + d0]     = r0;
            *(float4*)&at[(c0+i)*128 + d0 + 4] = r1;
        }
    }
    __syncthreads();
    {
        int p = tid >> 4, d0 = (tid & 15)*8;
        float s0[4] = {}, s1[4] = {};
        #pragma unroll 4
        for (int c=0;c<128;c++){
            float v = vs[p*128+c];
            float4 t0 = *(const float4*)&at[c*128+d0];
            float4 t1 = *(const float4*)&at[c*128+d0+4];
            s0[0] += v*t0.x; s0[1] += v*t0.y; s0[2] += v*t0.z; s0[3] += v*t0.w;
            s1[0] += v*t1.x; s1[1] += v*t1.y; s1[2] += v*t1.z; s1[3] += v*t1.w;
        }
        int gh = wy*4 + (p>>2), gw = wx*4 + (p&3);
        int oh2 = (gh+2)&127, ow = (gw+2)&127;
        long off = ((long)b*HWD + oh2*WDIM + ow)*CDIM + d0;
        bf16 hh[8], ll[8];
        split2(s0[0], hh[0], ll[0]); split2(s0[1], hh[1], ll[1]);
        split2(s0[2], hh[2], ll[2]); split2(s0[3], hh[3], ll[3]);
        split2(s1[0], hh[4], ll[4]); split2(s1[1], hh[5], ll[5]);
        split2(s1[2], hh[6], ll[6]); split2(s1[3], hh[7], ll[7]);
        *(uint4*)(oh + off) = *(uint4*)hh;
        *(uint4*)(ol + off) = *(uint4*)ll;
    }
}

// ---------------- GSA gram + per-channel sumsq reduction ---------------------
__global__ void k_gsa_gram(const float* __restrict__ qkv, float* __restrict__ S,
                           float* __restrict__ nq, float* __restrict__ nk){
    __shared__ float sq[32*32];
    __shared__ float sk[32*32];
    int tid = threadIdx.x;
    int blk = blockIdx.x;
    int chunk = blk & 15;
    int head = (blk >> 4) & 3;
    int b = blk >> 6;
    int p0 = chunk*1024;
    int c0 = tid >> 3;
    int d0 = (tid & 7) * 4;
    float acc[4] = {0,0,0,0};
    float sumq = 0.f, sumk = 0.f;
    for (int t = 0; t < 32; t++){
        __syncthreads();
        for (int i = tid; i < 2048; i += 256){
            int pi = i >> 6;
            int vv = i & 63;
            long pix = (long)b*HWD + p0 + t*32 + pi;
            int chn = (vv < 32) ? (head*32 + vv) : (128 + head*32 + (vv-32));
            float val = qkv[pix*C3 + chn];
            if (vv < 32) sq[pi*32+vv] = val; else sk[pi*32+(vv-32)] = val;
        }
        __syncthreads();
        #pragma unroll 4
        for (int pi=0; pi<32; pi++){
            float qv = sq[pi*32 + c0];
            #pragma unroll
            for (int j=0;j<4;j++) acc[j] += qv * sk[pi*32 + d0 + j];
        }
        if (tid < 32){
            for (int pi=0;pi<32;pi++){ float v = sq[pi*32+tid]; sumq += v*v; }
        } else if (tid < 64){
            int c = tid-32;
            for (int pi=0;pi<32;pi++){ float v = sk[pi*32+c]; sumk += v*v; }
        }
    }
    int sbase = ((b*NHEADS + head)*32 + c0)*32 + d0;
    #pragma unroll
    for (int j=0;j<4;j++) atomicAdd(&S[sbase+j], acc[j]);
    if (tid < 32) atomicAdd(&nq[b*CDIM + head*32 + tid], sumq);
    else if (tid < 64) atomicAdd(&nk[b*CDIM + head*32 + (tid-32)], sumk);
}

// ---------------- GSA attn finalize (in-place on S) --------------------------
__global__ void k_gsa_attn(float* __restrict__ S, const float* __restrict__ nq,
                           const float* __restrict__ nk, const float* __restrict__ tempp){
    int i = blockIdx.x*256 + threadIdx.x;
    if (i >= BATCH*NHEADS*32*32) return;
    int d = i & 31; int c = (i>>5)&31; int head = (i>>10)&3; int b = i>>12;
    float qn = fmaxf(sqrtf(nq[b*CDIM+head*32+c]), 1e-12f);
    float kn = fmaxf(sqrtf(nk[b*CDIM+head*32+d]), 1e-12f);
    S[i] = fmaxf(S[i]*tempp[0]/(qn*kn), 0.f);
}

// ---------------- GSA output: out[c,n] = sum_d attn[c,d] v[d,n] --------------
__global__ void k_gsa_out(const float* __restrict__ qkv, const float* __restrict__ A,
                          bf16* __restrict__ oh, bf16* __restrict__ ol){
    __shared__ float at[NHEADS*32*33];
    __shared__ float vsm[8][128];
    int tid = threadIdx.x;
    int warp = tid >> 5, lane = tid & 31;
    int b = (blockIdx.x*8) / HWD;
    for (int i = tid; i < NHEADS*32*32; i += 256)
        at[(i>>5)*33 + (i&31)] = A[b*NHEADS*32*32 + i];
    __syncthreads();
    long pix = (long)blockIdx.x*8 + warp;
    float4 v4 = *(const float4*)(qkv + pix*C3 + 256 + lane*4);
    vsm[warp][lane*4+0]=v4.x; vsm[warp][lane*4+1]=v4.y;
    vsm[warp][lane*4+2]=v4.z; vsm[warp][lane*4+3]=v4.w;
    __syncwarp();
    #pragma unroll
    for (int hd=0; hd<4; hd++){
        const float* arow = at + (hd*32 + lane)*33;
        const float* vrow = vsm[warp] + hd*32;
        float s = 0.f;
        #pragma unroll
        for (int d=0; d<32; d++) s += arow[d]*vrow[d];
        bf16 h, l; split2(s, h, l);
        long off = pix*CDIM + hd*32 + lane;
        oh[off] = h; ol[off] = l;
    }
}

// =============================== host ===============================
static float* sym(const void* s){
    void* p = nullptr;
    cudaGetSymbolAddress(&p, s);
    return (float*)p;
}
static bf16* symb(const void* s){
    void* p = nullptr;
    cudaGetSymbolAddress(&p, s);
    return (bf16*)p;
}

extern "C" void kernel_launch(void* const* d_in, const int* in_sizes, int n_in,
                              void* d_out, int out_size){
    const float* x        = (const float*)d_in[0];
    const float* w_s0     = (const float*)d_in[1];
    const float* b_s0     = (const float*)d_in[2];
    const float* w_s2     = (const float*)d_in[3];
    const float* b_s2     = (const float*)d_in[4];
    const float* rsa_qkv  = (const float*)d_in[5];
    const float* rsa_dw   = (const float*)d_in[6];
    const float* rsa_proj = (const float*)d_in[7];
    const float* rsa_temp = (const float*)d_in[8];
    const float* ffs_in   = (const float*)d_in[9];
    const float* ffs_dw   = (const float*)d_in[10];
    const float* ffs_out  = (const float*)d_in[11];
    const float* w_c0     = (const float*)d_in[12];
    const float* b_c0     = (const float*)d_in[13];
    const float* w_c2     = (const float*)d_in[14];
    const float* b_c2     = (const float*)d_in[15];
    const float* gsa_qkv  = (const float*)d_in[16];
    const float* gsa_dw   = (const float*)d_in[17];
    const float* gsa_proj = (const float*)d_in[18];
    const float* gsa_temp = (const float*)d_in[19];
    const float* ffc_in   = (const float*)d_in[20];
    const float* ffc_dw   = (const float*)d_in[21];
    const float* ffc_out  = (const float*)d_in[22];
    float* out = (float*)d_out;

    float* xt  = sym(g_xt);
    float* q1  = sym(g_qkv1);
    float* q2  = sym(g_qkv2);
    float* x1  = sym(g_x1);
    float* y   = sym(g_y);
    float* h1  = sym(g_h1);
    float* S   = sym(g_S);
    float* nq  = sym(g_nq);
    float* nk  = sym(g_nk);
    float* wt  = sym(g_wt);
    bf16* lnh  = symb(g_lnh);
    bf16* lnl  = symb(g_lnl);
    bf16* atth = symb(g_atth);
    bf16* attl = symb(g_attl);
    bf16* h2h  = symb(g_h2h);
    bf16* h2l  = symb(g_h2l);
    bf16* wbh  = symb(g_wbh);
    bf16* wbl  = symb(g_wbl);
    float* wt_rsa = wt;
    float* wt_ffs = wt + C3*9;
    float* wt_gsa = wt + 2*C3*9;
    float* wt_ffc = wt + 3*C3*9;

    cudaFuncSetAttribute(k_rsa_win, cudaFuncAttributeMaxDynamicSharedMemorySize, 90112);

    dim3 tb(32,8);
    dim3 tg(HWD/32, CDIM/32, BATCH);
    dim3 dwb3(C3/4, 2);
    dim3 dwbh2(HIDP/4, 2);
    int dwg = NPIX/8;

    // weight prep
    k_wtrans<<<(C3*9+255)/256, 256>>>(rsa_dw, wt_rsa, C3);
    k_wtrans<<<(HIDD*9+255)/256, 256>>>(ffs_dw, wt_ffs, HIDD);
    k_wtrans<<<(C3*9+255)/256, 256>>>(gsa_dw, wt_gsa, C3);
    k_wtrans<<<(HIDD*9+255)/256, 256>>>(ffc_dw, wt_ffc, HIDD);
    k_wsplit<<<(384*128+255)/256, 256>>>(rsa_qkv,  wbh+OFF_RQKV,  wbl+OFF_RQKV,  C3,   CDIM, 384, 128);
    k_wsplit<<<(128*128+255)/256, 256>>>(rsa_proj, wbh+OFF_RPROJ, wbl+OFF_RPROJ, CDIM, CDIM, 128, 128);
    k_wsplit<<<(384*128+255)/256, 256>>>(ffs_in,   wbh+OFF_FSIN,  wbl+OFF_FSIN,  HIDD, CDIM, 384, 128);
    k_wsplit<<<(128*352+255)/256, 256>>>(ffs_out,  wbh+OFF_FSOUT, wbl+OFF_FSOUT, CDIM, HIDD, 128, 352);
    k_wsplit<<<(384*128+255)/256, 256>>>(gsa_qkv,  wbh+OFF_GQKV,  wbl+OFF_GQKV,  C3,   CDIM, 384, 128);
    k_wsplit<<<(128*128+255)/256, 256>>>(gsa_proj, wbh+OFF_GPROJ, wbl+OFF_GPROJ, CDIM, CDIM, 128, 128);
    k_wsplit<<<(384*128+255)/256, 256>>>(ffc_in,   wbh+OFF_FCIN,  wbl+OFF_FCIN,  HIDD, CDIM, 384, 128);
    k_wsplit<<<(128*352+255)/256, 256>>>(ffc_out,  wbh+OFF_FCOUT, wbl+OFF_FCOUT, CDIM, HIDD, 128, 352);

    // ---- spatial (RSA) block ----
    k_nchw2nhwc<<<tg, tb>>>(x, xt);
    k_ln<<<NPIX/8, 256>>>(xt, nullptr, w_s0, b_s0, lnh, lnl, 2);             // LN + roll(-2,-2)
    k_gemm_bf<<<dim3(3,256), 256>>>(lnh, lnl, wbh+OFF_RQKV, wbl+OFF_RQKV, q1, nullptr, C3, 128, 128, 4);
    k_dwconv<<<dwg, dwb3>>>(q1, wt_rsa, q2, C3);
    k_rsa_win<<<BATCH*1024, 256, 90112>>>(q2, rsa_temp, atth, attl);         // + roll back
    k_gemm_bf<<<dim3(1,256), 256>>>(atth, attl, wbh+OFF_RPROJ, wbl+OFF_RPROJ, x1, nullptr, CDIM, 128, 128, 4);
    k_ln<<<NPIX/8, 256>>>(x1, xt, w_s2, b_s2, lnh, lnl, 0);                  // LN(x_ + x)
    k_gemm_bf<<<dim3(3,256), 256>>>(lnh, lnl, wbh+OFF_FSIN, wbl+OFF_FSIN, h1, nullptr, HIDD, 128, 128, 4);
    k_dwconv_gelu<<<dwg, dwbh2>>>(h1, wt_ffs, h2h, h2l);
    k_gemm_bf<<<dim3(1,256), 256>>>(h2h, h2l, wbh+OFF_FSOUT, wbl+OFF_FSOUT, y, x1, CDIM, 352, 352, 11);

    // ---- channel (GSA) block ----
    k_ln<<<NPIX/8, 256>>>(y, nullptr, w_c0, b_c0, lnh, lnl, 0);
    k_gemm_bf<<<dim3(3,256), 256>>>(lnh, lnl, wbh+OFF_GQKV, wbl+OFF_GQKV, q1, nullptr, C3, 128, 128, 4);
    k_dwconv<<<dwg, dwb3>>>(q1, wt_gsa, q2, C3);
    cudaMemsetAsync(S,  0, BATCH*NHEADS*32*32*sizeof(float));
    cudaMemsetAsync(nq, 0, BATCH*CDIM*sizeof(float));
    cudaMemsetAsync(nk, 0, BATCH*CDIM*sizeof(float));
    k_gsa_gram<<<BATCH*NHEADS*16, 256>>>(q2, S, nq, nk);
    k_gsa_attn<<<(BATCH*NHEADS*32*32+255)/256, 256>>>(S, nq, nk, gsa_temp);
    k_gsa_out<<<NPIX/8, 256>>>(q2, S, atth, attl);
    k_gemm_bf<<<dim3(1,256), 256>>>(atth, attl, wbh+OFF_GPROJ, wbl+OFF_GPROJ, x1, nullptr, CDIM, 128, 128, 4);
    k_ln<<<NPIX/8, 256>>>(x1, y, w_c2, b_c2, lnh, lnl, 0);                   // LN(x_ + x2)
    k_gemm_bf<<<dim3(3,256), 256>>>(lnh, lnl, wbh+OFF_FCIN, wbl+OFF_FCIN, h1, nullptr, HIDD, 128, 128, 4);
    k_dwconv_gelu<<<dwg, dwbh2>>>(h1, wt_ffc, h2h, h2l);
    k_gemm_bf<<<dim3(1,256), 256>>>(h2h, h2l, wbh+OFF_FCOUT, wbl+OFF_FCOUT, q1, nullptr, CDIM, 352, 352, 11);
    k_final<<<tg, tb>>>(q1, x1, out);                                        // + x_, NHWC->NCHW
}

// round 8
// speedup vs baseline: 1.8959x; 1.0056x over previous
#include <cuda_runtime.h>
#include <cuda_bf16.h>
#include <math.h>
#include <stdint.h>

#define BATCH 2
#define CDIM 128
#define HDIM 128
#define WDIM 128
#define HWD (HDIM*WDIM)           // 16384
#define NPIX (BATCH*HWD)          // 32768
#define C3 (3*CDIM)               // 384
#define HIDD 340
#define HIDP 352                  // padded hidden (mult of 32)
#define NHEADS 4
#define EPSV 1e-6f

typedef __nv_bfloat16 bf16;

// ---------------- scratch (static device allocations) ----------------
__device__ float g_xt  [NPIX*CDIM];
__device__ float g_qkv1[NPIX*C3];
__device__ float g_qkv2[NPIX*C3];
__device__ float g_x1  [NPIX*CDIM];
__device__ float g_y   [NPIX*CDIM];
__device__ float g_h1  [NPIX*HIDD];
__device__ float g_S   [BATCH*NHEADS*32*32];
__device__ float g_nq  [BATCH*CDIM];
__device__ float g_nk  [BATCH*CDIM];
__device__ float g_wt  [4][C3*9];       // transposed dwconv weights [9][CHN] x4
__device__ bf16  g_lnh [NPIX*CDIM];
__device__ bf16  g_lnl [NPIX*CDIM];
__device__ bf16  g_atth[NPIX*CDIM];
__device__ bf16  g_attl[NPIX*CDIM];
__device__ bf16  g_h2h [NPIX*HIDP];
__device__ bf16  g_h2l [NPIX*HIDP];
#define WB_TOTAL 319488
__device__ bf16  g_wbh [WB_TOTAL];
__device__ bf16  g_wbl [WB_TOTAL];
// offsets into g_wb*
#define OFF_RQKV  0        // 384x128
#define OFF_RPROJ 49152    // 128x128
#define OFF_FSIN  65536    // 384x128 (rows padded from 340)
#define OFF_FSOUT 114688   // 128x352 (K padded from 340)
#define OFF_GQKV  159744
#define OFF_GPROJ 208896
#define OFF_FCIN  225280
#define OFF_FCOUT 274432   // 128x352
#define WT_ELEMS 13032     // 3456+3060+3456+3060

// =================== helpers ===================
__device__ __forceinline__ uint32_t smem_u32(const void* p){
    uint32_t a;
    asm("{ .reg .u64 t; cvta.to.shared.u64 t, %1; cvt.u32.u64 %0, t; }" : "=r"(a) : "l"(p));
    return a;
}
__device__ __forceinline__ void ldsm_x4(uint32_t& r0, uint32_t& r1, uint32_t& r2, uint32_t& r3,
                                        uint32_t addr){
    asm volatile("ldmatrix.sync.aligned.m8n8.x4.shared.b16 {%0,%1,%2,%3}, [%4];"
                 : "=r"(r0), "=r"(r1), "=r"(r2), "=r"(r3) : "r"(addr));
}
__device__ __forceinline__ void mma_bf16(float* d, const uint32_t* a, const uint32_t* b){
    asm volatile("mma.sync.aligned.m16n8k16.row.col.f32.bf16.bf16.f32 "
                 "{%0,%1,%2,%3}, {%4,%5,%6,%7}, {%8,%9}, {%0,%1,%2,%3};"
                 : "+f"(d[0]), "+f"(d[1]), "+f"(d[2]), "+f"(d[3])
                 : "r"(a[0]), "r"(a[1]), "r"(a[2]), "r"(a[3]), "r"(b[0]), "r"(b[1]));
}
__device__ __forceinline__ void split2(float v, bf16& h, bf16& l){
    h = __float2bfloat16(v);
    l = __float2bfloat16(v - __bfloat162float(h));
}
__device__ __forceinline__ void cpa16(uint32_t dst, const void* src){
    asm volatile("cp.async.ca.shared.global [%0], [%1], 16;" :: "r"(dst), "l"(src) : "memory");
}

// ============ bf16-split GEMM, cp.async double-buffered ============
#define SPAD 40
#define STG_E (128*SPAD)          // elements per array per stage
#define GT_SMEM (2*4*STG_E*2)     // 81920 bytes
__global__ void __launch_bounds__(256, 2)
k_gemm_bf(const bf16* __restrict__ Ah, const bf16* __restrict__ Al,
          const bf16* __restrict__ Bh, const bf16* __restrict__ Bl,
          float* __restrict__ Cc, const float* __restrict__ res,
          int N, int sA, int sB, int KC){
    extern __shared__ __align__(16) char smem[];
    int tid = threadIdx.x, warp = tid >> 5, lane = tid & 31;
    int m0 = blockIdx.y*128, n0 = blockIdx.x*128;
    int mw = (warp & 3)*32, nw = (warp >> 2)*64;
    float acc[2][8][4];
    #pragma unroll
    for (int i=0;i<2;i++)
        #pragma unroll
        for (int j=0;j<8;j++)
            #pragma unroll
            for (int e=0;e<4;e++) acc[i][j][e] = 0.f;

    int r  = tid >> 1;            // 0..127
    int cb = (tid & 1)*16;        // 0 or 16
    const bf16* gp0 = Ah + (long)(m0+r)*sA + cb;
    const bf16* gp1 = Al + (long)(m0+r)*sA + cb;
    const bf16* gp2 = Bh + (long)(n0+r)*sB + cb;
    const bf16* gp3 = Bl + (long)(n0+r)*sB + cb;

    // per-thread smem store addresses (byte) for stage 0
    uint32_t stb = smem_u32(smem);
    uint32_t doff = (uint32_t)(r*SPAD + cb)*2;
    const uint32_t STG_B = STG_E*2;           // 10240 bytes per array

    int arow = mw + ((lane >> 3) & 1)*8 + (lane & 7);
    int acolb = ((lane >> 4) & 1)*8;
    int brow = nw + ((lane >> 4) & 1)*8 + (lane & 7);
    int bcolb = ((lane >> 3) & 1)*8;

    // prefetch chunk 0 into stage 0
    {
        uint32_t base = stb + doff;
        cpa16(base + 0*STG_B,      gp0);
        cpa16(base + 0*STG_B + 16, gp0 + 8);
        cpa16(base + 1*STG_B,      gp1);
        cpa16(base + 1*STG_B + 16, gp1 + 8);
        cpa16(base + 2*STG_B,      gp2);
        cpa16(base + 2*STG_B + 16, gp2 + 8);
        cpa16(base + 3*STG_B,      gp3);
        cpa16(base + 3*STG_B + 16, gp3 + 8);
        asm volatile("cp.async.commit_group;" ::: "memory");
    }

    for (int kc = 0; kc < KC; kc++){
        if (kc+1 < KC){
            int k0 = (kc+1)*32;
            uint32_t base = stb + ((kc+1)&1)*4*STG_B + doff;
            cpa16(base + 0*STG_B,      gp0 + k0);
            cpa16(base + 0*STG_B + 16, gp0 + k0 + 8);
            cpa16(base + 1*STG_B,      gp1 + k0);
            cpa16(base + 1*STG_B + 16, gp1 + k0 + 8);
            cpa16(base + 2*STG_B,      gp2 + k0);
            cpa16(base + 2*STG_B + 16, gp2 + k0 + 8);
            cpa16(base + 3*STG_B,      gp3 + k0);
            cpa16(base + 3*STG_B + 16, gp3 + k0 + 8);
            asm volatile("cp.async.commit_group;" ::: "memory");
            asm volatile("cp.async.wait_group 1;" ::: "memory");
        } else {
            asm volatile("cp.async.wait_group 0;" ::: "memory");
        }
        __syncthreads();

        const bf16* Ahs = (const bf16*)(smem + ((kc&1)*4 + 0)*STG_B);
        const bf16* Als = (const bf16*)(smem + ((kc&1)*4 + 1)*STG_B);
        const bf16* Bhs = (const bf16*)(smem + ((kc&1)*4 + 2)*STG_B);
        const bf16* Bls = (const bf16*)(smem + ((kc&1)*4 + 3)*STG_B);

        #pragma unroll
        for (int kk = 0; kk < 32; kk += 16){
            #pragma unroll
            for (int pass = 0; pass < 3; pass++){
                const bf16* As = (pass == 2) ? Als : Ahs;
                const bf16* Bs = (pass == 1) ? Bls : Bhs;
                uint32_t a[2][4], b[8][2];
                #pragma unroll
                for (int mt = 0; mt < 2; mt++){
                    uint32_t ad = smem_u32(As + (arow + mt*16)*SPAD + kk + acolb);
                    ldsm_x4(a[mt][0], a[mt][1], a[mt][2], a[mt][3], ad);
                }
                #pragma unroll
                for (int np = 0; np < 4; np++){
                    uint32_t ad = smem_u32(Bs + (brow + np*16)*SPAD + kk + bcolb);
                    ldsm_x4(b[np*2][0], b[np*2][1], b[np*2+1][0], b[np*2+1][1], ad);
                }
                #pragma unroll
                for (int mt = 0; mt < 2; mt++)
                    #pragma unroll
                    for (int nt = 0; nt < 8; nt++)
                        mma_bf16(acc[mt][nt], a[mt], b[nt]);
            }
        }
        __syncthreads();
    }

    // ---- epilogue ----
    #pragma unroll
    for (int mt = 0; mt < 2; mt++){
        int mrow = m0 + mw + mt*16 + (lane >> 2);
        #pragma unroll
        for (int nt = 0; nt < 8; nt++){
            int n = n0 + nw + nt*8 + (lane & 3)*2;
            if (n < N){
                long b0 = (long)mrow*N + n;
                long b1 = (long)(mrow+8)*N + n;
                float2 v0 = make_float2(acc[mt][nt][0], acc[mt][nt][1]);
                float2 v1 = make_float2(acc[mt][nt][2], acc[mt][nt][3]);
                if (res){
                    float2 r0 = *(const float2*)(res + b0);
                    float2 r1 = *(const float2*)(res + b1);
                    v0.x += r0.x; v0.y += r0.y;
                    v1.x += r1.x; v1.y += r1.y;
                }
                *(float2*)(Cc + b0) = v0;
                *(float2*)(Cc + b1) = v1;
            }
        }
    }
}

// ---------------- unified prep: all weight transposes + splits ----------------
__global__ void k_prep(const float* __restrict__ rsa_dw, const float* __restrict__ ffs_dw,
                       const float* __restrict__ gsa_dw, const float* __restrict__ ffc_dw,
                       const float* __restrict__ rqkv, const float* __restrict__ rproj,
                       const float* __restrict__ fsin, const float* __restrict__ fsout,
                       const float* __restrict__ gqkv, const float* __restrict__ gproj,
                       const float* __restrict__ fcin, const float* __restrict__ fcout){
    int i = blockIdx.x*256 + threadIdx.x;
    if (i < WB_TOTAL){
        const float* srcs[8] = {rqkv, rproj, fsin, fsout, gqkv, gproj, fcin, fcout};
        const int offs[9] = {OFF_RQKV, OFF_RPROJ, OFF_FSIN, OFF_FSOUT,
                             OFF_GQKV, OFF_GPROJ, OFF_FCIN, OFF_FCOUT, WB_TOTAL};
        const int Nr[8]   = {C3, CDIM, HIDD, CDIM, C3, CDIM, HIDD, CDIM};
        const int Kr[8]   = {CDIM, CDIM, CDIM, HIDD, CDIM, CDIM, CDIM, HIDD};
        const int Kpad[8] = {128, 128, 128, 352, 128, 128, 128, 352};
        int s = 0;
        while (i >= offs[s+1]) s++;
        int j = i - offs[s];
        int rr = j / Kpad[s], c = j - rr*Kpad[s];
        float v = (rr < Nr[s] && c < Kr[s]) ? srcs[s][(long)rr*Kr[s] + c] : 0.f;
        bf16 h, l; split2(v, h, l);
        g_wbh[i] = h; g_wbl[i] = l;
    } else {
        int j = i - WB_TOTAL;
        const float* s4[4] = {rsa_dw, ffs_dw, gsa_dw, ffc_dw};
        const int chn[4] = {C3, HIDD, C3, HIDD};
        int seg = 0;
        while (seg < 4 && j >= chn[seg]*9){ j -= chn[seg]*9; seg++; }
        if (seg >= 4) return;
        int c = j/9, t = j - c*9;
        g_wt[seg][t*chn[seg] + c] = s4[seg][j];
    }
}

// ---------------- NCHW -> NHWC transpose ----------------
__global__ void k_nchw2nhwc(const float* __restrict__ in, float* __restrict__ out){
    __shared__ float tile[32][33];
    int b = blockIdx.z;
    int p0 = blockIdx.x*32;
    int c0 = blockIdx.y*32;
    int tx = threadIdx.x, ty = threadIdx.y;
    #pragma unroll
    for (int i=0;i<4;i++){
        int c = c0 + ty + i*8;
        tile[ty+i*8][tx] = in[((long)b*CDIM + c)*HWD + p0 + tx];
    }
    __syncthreads();
    #pragma unroll
    for (int i=0;i<4;i++){
        int p = p0 + ty + i*8;
        out[((long)b*HWD + p)*CDIM + c0 + tx] = tile[tx][ty+i*8];
    }
}

// ---------------- NHWC (a+b) -> NCHW ----------------
__global__ void k_final(const float* __restrict__ a, const float* __restrict__ b2,
                        float* __restrict__ out){
    __shared__ float tile[32][33];
    int b = blockIdx.z;
    int p0 = blockIdx.x*32;
    int c0 = blockIdx.y*32;
    int tx = threadIdx.x, ty = threadIdx.y;
    #pragma unroll
    for (int i=0;i<4;i++){
        long idx = ((long)b*HWD + p0 + ty + i*8)*CDIM + c0 + tx;
        tile[ty+i*8][tx] = a[idx] + b2[idx];
    }
    __syncthreads();
    #pragma unroll
    for (int i=0;i<4;i++){
        int c = c0 + ty + i*8;
        out[((long)b*CDIM + c)*HWD + p0 + tx] = tile[tx][ty+i*8];
    }
}

// ------ LayerNorm over C (warp per pixel), optional residual+roll, bf16 hi/lo out
__global__ void k_ln(const float* __restrict__ in, const float* __restrict__ res,
                     const float* __restrict__ gamma, const float* __restrict__ beta,
                     bf16* __restrict__ oh, bf16* __restrict__ ol, int shift){
    int warp = threadIdx.x >> 5, lane = threadIdx.x & 31;
    int pix = blockIdx.x*8 + warp;
    if (pix >= NPIX) return;
    int b = pix >> 14, rem = pix & (HWD-1);
    int h = rem >> 7, w = rem & 127;
    int sh = (h + shift) & (HDIM-1);
    int sw = (w + shift) & (WDIM-1);
    long src = ((long)b*HWD + sh*WDIM + sw)*CDIM + lane*4;
    float4 v = *(const float4*)(in + src);
    if (res){
        float4 r = *(const float4*)(res + src);
        v.x += r.x; v.y += r.y; v.z += r.z; v.w += r.w;
    }
    float s  = v.x+v.y+v.z+v.w;
    float ss = v.x*v.x+v.y*v.y+v.z*v.z+v.w*v.w;
    #pragma unroll
    for (int o=16;o;o>>=1){
        s  += __shfl_xor_sync(0xffffffffu, s,  o);
        ss += __shfl_xor_sync(0xffffffffu, ss, o);
    }
    float mean = s * (1.f/CDIM);
    float var  = ss * (1.f/CDIM) - mean*mean;
    float rstd = rsqrtf(var + EPSV);
    float4 g  = *(const float4*)(gamma + lane*4);
    float4 be = *(const float4*)(beta  + lane*4);
    float o0 = (v.x-mean)*rstd*g.x + be.x;
    float o1 = (v.y-mean)*rstd*g.y + be.y;
    float o2 = (v.z-mean)*rstd*g.z + be.z;
    float o3 = (v.w-mean)*rstd*g.w + be.w;
    bf16 hh[4], ll[4];
    split2(o0, hh[0], ll[0]); split2(o1, hh[1], ll[1]);
    split2(o2, hh[2], ll[2]); split2(o3, hh[3], ll[3]);
    long dst = (long)pix*CDIM + lane*4;
    *(uint2*)(oh + dst) = *(uint2*)hh;
    *(uint2*)(ol + dst) = *(uint2*)ll;
}

// ---------------- depthwise 3x3, fp32 out (qkv path) --------
__global__ void k_dwconv(const float* __restrict__ in, const float* __restrict__ wt,
                         float* __restrict__ out, int CHN){
    int cq = threadIdx.x;
    int py = threadIdx.y;
    int pix0 = blockIdx.x*8;
    int b = pix0 >> 14;
    int h = (pix0 >> 7) & 127;
    int w0 = pix0 & 127;
    int c4 = cq*4;
    float4 wv[9];
    #pragma unroll
    for (int t=0;t<9;t++) wv[t] = *(const float4*)(wt + t*CHN + c4);
    const float* base = in + (long)b*HWD*CHN + c4;
    float* obase = out + (long)b*HWD*CHN + c4;
    #pragma unroll
    for (int i=0;i<4;i++){
        int w = w0 + py + i*2;
        float4 acc = make_float4(0.f,0.f,0.f,0.f);
        #pragma unroll
        for (int dy=-1;dy<=1;dy++){
            int hh = h + dy;
            if ((unsigned)hh >= HDIM) continue;
            #pragma unroll
            for (int dx=-1;dx<=1;dx++){
                int ww = w + dx;
                if ((unsigned)ww >= WDIM) continue;
                float4 v = *(const float4*)(base + ((long)hh*WDIM + ww)*CHN);
                float4 wk = wv[(dy+1)*3 + dx + 1];
                acc.x += wk.x*v.x; acc.y += wk.y*v.y;
                acc.z += wk.z*v.z; acc.w += wk.w*v.w;
            }
        }
        *(float4*)(obase + ((long)h*WDIM + w)*CHN) = acc;
    }
}

// -------- depthwise 3x3 + gelu -> bf16 hi/lo out, K-padded to HIDP --------
__global__ void k_dwconv_gelu(const float* __restrict__ in, const float* __restrict__ wt,
                              bf16* __restrict__ oh, bf16* __restrict__ ol){
    int cq = threadIdx.x;          // 0..87 (HIDP/4)
    int py = threadIdx.y;          // 0..1
    int pix0 = blockIdx.x*8;
    int b = pix0 >> 14;
    int h = (pix0 >> 7) & 127;
    int w0 = pix0 & 127;
    int c4 = cq*4;
    bool pad = (c4 >= HIDD);
    float4 wv[9];
    if (!pad){
        #pragma unroll
        for (int t=0;t<9;t++) wv[t] = *(const float4*)(wt + t*HIDD + c4);
    }
    const float* base = in + (long)b*HWD*HIDD + c4;
    long obase = (long)b*HWD*HIDP + c4;
    #pragma unroll
    for (int i=0;i<4;i++){
        int w = w0 + py + i*2;
        bf16 hh[4] = {}, ll[4] = {};
        if (!pad){
            float4 acc = make_float4(0.f,0.f,0.f,0.f);
            #pragma unroll
            for (int dy=-1;dy<=1;dy++){
                int hy = h + dy;
                if ((unsigned)hy >= HDIM) continue;
                #pragma unroll
                for (int dx=-1;dx<=1;dx++){
                    int ww = w + dx;
                    if ((unsigned)ww >= WDIM) continue;
                    float4 v = *(const float4*)(base + ((long)hy*WDIM + ww)*HIDD);
                    float4 wk = wv[(dy+1)*3 + dx + 1];
                    acc.x += wk.x*v.x; acc.y += wk.y*v.y;
                    acc.z += wk.z*v.z; acc.w += wk.w*v.w;
                }
            }
            acc.x = 0.5f*acc.x*(1.f + erff(acc.x*0.70710678118654752f));
            acc.y = 0.5f*acc.y*(1.f + erff(acc.y*0.70710678118654752f));
            acc.z = 0.5f*acc.z*(1.f + erff(acc.z*0.70710678118654752f));
            acc.w = 0.5f*acc.w*(1.f + erff(acc.w*0.70710678118654752f));
            split2(acc.x, hh[0], ll[0]); split2(acc.y, hh[1], ll[1]);
            split2(acc.z, hh[2], ll[2]); split2(acc.w, hh[3], ll[3]);
        }
        long o = obase + ((long)h*WDIM + w)*HIDP;
        *(uint2*)(oh + o) = *(uint2*)hh;
        *(uint2*)(ol + o) = *(uint2*)ll;
    }
}

// ---------------- RSA window attention (one CTA per 4x4 window) --------------
__global__ void k_rsa_win(const float* __restrict__ qkv, const float* __restrict__ tempp,
                          bf16* __restrict__ oh, bf16* __restrict__ ol){
    extern __shared__ float sm[];
    float* qs = sm;
    float* ks = sm + 2048;
    float* vs = sm + 4096;
    float* at = sm + 6144;
    __shared__ float rn[32];
    int tid = threadIdx.x;
    int warp = tid >> 5, lane = tid & 31;
    int win = blockIdx.x;
    int b = win >> 10; int wrem = win & 1023;
    int wy = wrem >> 5, wx = wrem & 31;
    for (int i = tid; i < 6144; i += 256){
        int sec = i >> 11; int r = i & 2047; int p = r >> 7; int c = r & 127;
        int gh = wy*4 + (p>>2), gw = wx*4 + (p&3);
        sm[i] = qkv[((long)b*HWD + gh*WDIM + gw)*C3 + sec*128 + c];
    }
    __syncthreads();
    #pragma unroll
    for (int r = warp; r < 32; r += 8){
        const float* basep = sm + (r>>4)*2048 + (r&15)*128;
        float4 v = *(const float4*)(basep + lane*4);
        float s = v.x*v.x + v.y*v.y + v.z*v.z + v.w*v.w;
        #pragma unroll
        for (int o=16;o;o>>=1) s += __shfl_xor_sync(0xffffffffu, s, o);
        if (lane == 0) rn[r] = 1.f / fmaxf(sqrtf(s), 1e-12f);
    }
    __syncthreads();
    for (int i = tid; i < 4096; i += 256){
        int sec = i >> 11; int p = (i & 2047) >> 7;
        sm[i] *= rn[sec*16 + p];
    }
    __syncthreads();
    float temp = tempp[0];
    {
        int c0 = (tid >> 4)*8, d0 = (tid & 15)*8;
        float a2[8][8] = {};
        #pragma unroll
        for (int p=0;p<16;p++){
            float4 q0 = *(const float4*)&qs[p*128+c0];
            float4 q1 = *(const float4*)&qs[p*128+c0+4];
            float4 k0 = *(const float4*)&ks[p*128+d0];
            float4 k1 = *(const float4*)&ks[p*128+d0+4];
            float qa[8] = {q0.x,q0.y,q0.z,q0.w,q1.x,q1.y,q1.z,q1.w};
            float ka[8] = {k0.x,k0.y,k0.z,k0.w,k1.x,k1.y,k1.z,k1.w};
            #pragma unroll
            for (int i=0;i<8;i++)
                #pragma unroll
                for (int j=0;j<8;j++)
                    a2[i][j] += qa[i]*ka[j];
        }
        #pragma unroll
        for (int i=0;i<8;i++){
            float4 r0, r1;
            r0.x = fmaxf(a2[i][0]*temp, 0.f); r0.y = fmaxf(a2[i][1]*temp, 0.f);
            r0.z = fmaxf(a2[i][2]*temp, 0.f); r0.w = fmaxf(a2[i][3]*temp, 0.f);
            r1.x = fmaxf(a2[i][4]*temp, 0.f); r1.y = fmaxf(a2[i][5]*temp, 0.f);
            r1.z = fmaxf(a2[i][6]*temp, 0.f); r1.w = fmaxf(a2[i][7]*temp, 0.f);
            *(float4*)&at[(c0+i)*128 + d0]     = r0;
            *(float4*)&at[(c0+i)*128 + d0 + 4] = r1;
        }
    }
    __syncthreads();
    {
        int p = tid >> 4, d0 = (tid & 15)*8;
        float s0[4] = {}, s1[4] = {};
        #pragma unroll 4
        for (int c=0;c<128;c++){
            float v = vs[p*128+c];
            float4 t0 = *(const float4*)&at[c*128+d0];
            float4 t1 = *(const float4*)&at[c*128+d0+4];
            s0[0] += v*t0.x; s0[1] += v*t0.y; s0[2] += v*t0.z; s0[3] += v*t0.w;
            s1[0] += v*t1.x; s1[1] += v*t1.y; s1[2] += v*t1.z; s1[3] += v*t1.w;
        }
        int gh = wy*4 + (p>>2), gw = wx*4 + (p&3);
        int oh2 = (gh+2)&127, ow = (gw+2)&127;
        long off = ((long)b*HWD + oh2*WDIM + ow)*CDIM + d0;
        bf16 hh[8], ll[8];
        split2(s0[0], hh[0], ll[0]); split2(s0[1], hh[1], ll[1]);
        split2(s0[2], hh[2], ll[2]); split2(s0[3], hh[3], ll[3]);
        split2(s1[0], hh[4], ll[4]); split2(s1[1], hh[5], ll[5]);
        split2(s1[2], hh[6], ll[6]); split2(s1[3], hh[7], ll[7]);
        *(uint4*)(oh + off) = *(uint4*)hh;
        *(uint4*)(ol + off) = *(uint4*)ll;
    }
}

// ---------------- GSA gram + per-channel sumsq reduction ---------------------
__global__ void k_gsa_gram(const float* __restrict__ qkv, float* __restrict__ S,
                           float* __restrict__ nq, float* __restrict__ nk){
    __shared__ float sq[32*32];
    __shared__ float sk[32*32];
    int tid = threadIdx.x;
    int blk = blockIdx.x;
    int chunk = blk & 15;
    int head = (blk >> 4) & 3;
    int b = blk >> 6;
    int p0 = chunk*1024;
    int c0 = tid >> 3;
    int d0 = (tid & 7) * 4;
    float acc[4] = {0,0,0,0};
    float sumq = 0.f, sumk = 0.f;
    for (int t = 0; t < 32; t++){
        __syncthreads();
        for (int i = tid; i < 2048; i += 256){
            int pi = i >> 6;
            int vv = i & 63;
            long pix = (long)b*HWD + p0 + t*32 + pi;
            int chn = (vv < 32) ? (head*32 + vv) : (128 + head*32 + (vv-32));
            float val = qkv[pix*C3 + chn];
            if (vv < 32) sq[pi*32+vv] = val; else sk[pi*32+(vv-32)] = val;
        }
        __syncthreads();
        #pragma unroll 4
        for (int pi=0; pi<32; pi++){
            float qv = sq[pi*32 + c0];
            #pragma unroll
            for (int j=0;j<4;j++) acc[j] += qv * sk[pi*32 + d0 + j];
        }
        if (tid < 32){
            for (int pi=0;pi<32;pi++){ float v = sq[pi*32+tid]; sumq += v*v; }
        } else if (tid < 64){
            int c = tid-32;
            for (int pi=0;pi<32;pi++){ float v = sk[pi*32+c]; sumk += v*v; }
        }
    }
    int sbase = ((b*NHEADS + head)*32 + c0)*32 + d0;
    #pragma unroll
    for (int j=0;j<4;j++) atomicAdd(&S[sbase+j], acc[j]);
    if (tid < 32) atomicAdd(&nq[b*CDIM + head*32 + tid], sumq);
    else if (tid < 64) atomicAdd(&nk[b*CDIM + head*32 + (tid-32)], sumk);
}

// ---- GSA output: normalize S in-flight, out[c,n] = sum_d attn[c,d] v[d,n] ----
__global__ void k_gsa_out(const float* __restrict__ qkv, const float* __restrict__ A,
                          const float* __restrict__ nq, const float* __restrict__ nk,
                          const float* __restrict__ tempp,
                          bf16* __restrict__ oh, bf16* __restrict__ ol){
    __shared__ float at[NHEADS*32*33];
    __shared__ float vsm[8][128];
    int tid = threadIdx.x;
    int warp = tid >> 5, lane = tid & 31;
    int b = (blockIdx.x*8) / HWD;
    float temp = tempp[0];
    for (int i = tid; i < NHEADS*32*32; i += 256){
        int head = i >> 10; int c = (i >> 5) & 31; int d = i & 31;
        float qn = fmaxf(sqrtf(nq[b*CDIM + head*32 + c]), 1e-12f);
        float kn = fmaxf(sqrtf(nk[b*CDIM + head*32 + d]), 1e-12f);
        float val = fmaxf(A[b*NHEADS*32*32 + i]*temp/(qn*kn), 0.f);
        at[(i>>5)*33 + d] = val;
    }
    __syncthreads();
    long pix = (long)blockIdx.x*8 + warp;
    float4 v4 = *(const float4*)(qkv + pix*C3 + 256 + lane*4);
    vsm[warp][lane*4+0]=v4.x; vsm[warp][lane*4+1]=v4.y;
    vsm[warp][lane*4+2]=v4.z; vsm[warp][lane*4+3]=v4.w;
    __syncwarp();
    #pragma unroll
    for (int hd=0; hd<4; hd++){
        const float* arow = at + (hd*32 + lane)*33;
        const float* vrow = vsm[warp] + hd*32;
        float s = 0.f;
        #pragma unroll
        for (int d=0; d<32; d++) s += arow[d]*vrow[d];
        bf16 h, l; split2(s, h, l);
        long off = pix*CDIM + hd*32 + lane;
        oh[off] = h; ol[off] = l;
    }
}

// =============================== host ===============================
static float* sym(const void* s){
    void* p = nullptr;
    cudaGetSymbolAddress(&p, s);
    return (float*)p;
}
static bf16* symb(const void* s){
    void* p = nullptr;
    cudaGetSymbolAddress(&p, s);
    return (bf16*)p;
}

extern "C" void kernel_launch(void* const* d_in, const int* in_sizes, int n_in,
                              void* d_out, int out_size){
    const float* x        = (const float*)d_in[0];
    const float* w_s0     = (const float*)d_in[1];
    const float* b_s0     = (const float*)d_in[2];
    const float* w_s2     = (const float*)d_in[3];
    const float* b_s2     = (const float*)d_in[4];
    const float* rsa_qkv  = (const float*)d_in[5];
    const float* rsa_dw   = (const float*)d_in[6];
    const float* rsa_proj = (const float*)d_in[7];
    const float* rsa_temp = (const float*)d_in[8];
    const float* ffs_in   = (const float*)d_in[9];
    const float* ffs_dw   = (const float*)d_in[10];
    const float* ffs_out  = (const float*)d_in[11];
    const float* w_c0     = (const float*)d_in[12];
    const float* b_c0     = (const float*)d_in[13];
    const float* w_c2     = (const float*)d_in[14];
    const float* b_c2     = (const float*)d_in[15];
    const float* gsa_qkv  = (const float*)d_in[16];
    const float* gsa_dw   = (const float*)d_in[17];
    const float* gsa_proj = (const float*)d_in[18];
    const float* gsa_temp = (const float*)d_in[19];
    const float* ffc_in   = (const float*)d_in[20];
    const float* ffc_dw   = (const float*)d_in[21];
    const float* ffc_out  = (const float*)d_in[22];
    float* out = (float*)d_out;

    float* xt  = sym(g_xt);
    float* q1  = sym(g_qkv1);
    float* q2  = sym(g_qkv2);
    float* x1  = sym(g_x1);
    float* y   = sym(g_y);
    float* h1  = sym(g_h1);
    float* S   = sym(g_S);
    float* nq  = sym(g_nq);
    float* nk  = sym(g_nk);
    float* wt  = sym(g_wt);
    bf16* lnh  = symb(g_lnh);
    bf16* lnl  = symb(g_lnl);
    bf16* atth = symb(g_atth);
    bf16* attl = symb(g_attl);
    bf16* h2h  = symb(g_h2h);
    bf16* h2l  = symb(g_h2l);
    bf16* wbh  = symb(g_wbh);
    bf16* wbl  = symb(g_wbl);
    float* wt_rsa = wt;
    float* wt_ffs = wt + C3*9;
    float* wt_gsa = wt + 2*C3*9;
    float* wt_ffc = wt + 3*C3*9;

    cudaFuncSetAttribute(k_rsa_win, cudaFuncAttributeMaxDynamicSharedMemorySize, 90112);
    cudaFuncSetAttribute(k_gemm_bf, cudaFuncAttributeMaxDynamicSharedMemorySize, GT_SMEM);

    dim3 tb(32,8);
    dim3 tg(HWD/32, CDIM/32, BATCH);
    dim3 dwb3(C3/4, 2);
    dim3 dwbh2(HIDP/4, 2);
    int dwg = NPIX/8;

    // one-shot prep: all weight transposes + bf16 splits
    k_prep<<<(WB_TOTAL + WT_ELEMS + 255)/256, 256>>>(
        rsa_dw, ffs_dw, gsa_dw, ffc_dw,
        rsa_qkv, rsa_proj, ffs_in, ffs_out, gsa_qkv, gsa_proj, ffc_in, ffc_out);

    // ---- spatial (RSA) block ----
    k_nchw2nhwc<<<tg, tb>>>(x, xt);
    k_ln<<<NPIX/8, 256>>>(xt, nullptr, w_s0, b_s0, lnh, lnl, 2);             // LN + roll(-2,-2)
    k_gemm_bf<<<dim3(3,256), 256, GT_SMEM>>>(lnh, lnl, wbh+OFF_RQKV, wbl+OFF_RQKV, q1, nullptr, C3, 128, 128, 4);
    k_dwconv<<<dwg, dwb3>>>(q1, wt_rsa, q2, C3);
    k_rsa_win<<<BATCH*1024, 256, 90112>>>(q2, rsa_temp, atth, attl);         // + roll back
    k_gemm_bf<<<dim3(1,256), 256, GT_SMEM>>>(atth, attl, wbh+OFF_RPROJ, wbl+OFF_RPROJ, x1, nullptr, CDIM, 128, 128, 4);
    k_ln<<<NPIX/8, 256>>>(x1, xt, w_s2, b_s2, lnh, lnl, 0);                  // LN(x_ + x)
    k_gemm_bf<<<dim3(3,256), 256, GT_SMEM>>>(lnh, lnl, wbh+OFF_FSIN, wbl+OFF_FSIN, h1, nullptr, HIDD, 128, 128, 4);
    k_dwconv_gelu<<<dwg, dwbh2>>>(h1, wt_ffs, h2h, h2l);
    k_gemm_bf<<<dim3(1,256), 256, GT_SMEM>>>(h2h, h2l, wbh+OFF_FSOUT, wbl+OFF_FSOUT, y, x1, CDIM, 352, 352, 11);

    // ---- channel (GSA) block ----
    k_ln<<<NPIX/8, 256>>>(y, nullptr, w_c0, b_c0, lnh, lnl, 0);
    k_gemm_bf<<<dim3(3,256), 256, GT_SMEM>>>(lnh, lnl, wbh+OFF_GQKV, wbl+OFF_GQKV, q1, nullptr, C3, 128, 128, 4);
    k_dwconv<<<dwg, dwb3>>>(q1, wt_gsa, q2, C3);
    cudaMemsetAsync(S,  0, BATCH*NHEADS*32*32*sizeof(float));
    cudaMemsetAsync(nq, 0, BATCH*CDIM*sizeof(float));
    cudaMemsetAsync(nk, 0, BATCH*CDIM*sizeof(float));
    k_gsa_gram<<<BATCH*NHEADS*16, 256>>>(q2, S, nq, nk);
    k_gsa_out<<<NPIX/8, 256>>>(q2, S, nq, nk, gsa_temp, atth, attl);
    k_gemm_bf<<<dim3(1,256), 256, GT_SMEM>>>(atth, attl, wbh+OFF_GPROJ, wbl+OFF_GPROJ, x1, nullptr, CDIM, 128, 128, 4);
    k_ln<<<NPIX/8, 256>>>(x1, y, w_c2, b_c2, lnh, lnl, 0);                   // LN(x_ + x2)
    k_gemm_bf<<<dim3(3,256), 256, GT_SMEM>>>(lnh, lnl, wbh+OFF_FCIN, wbl+OFF_FCIN, h1, nullptr, HIDD, 128, 128, 4);
    k_dwconv_gelu<<<dwg, dwbh2>>>(h1, wt_ffc, h2h, h2l);
    k_gemm_bf<<<dim3(1,256), 256, GT_SMEM>>>(h2h, h2l, wbh+OFF_FCOUT, wbl+OFF_FCOUT, q1, nullptr, CDIM, 352, 352, 11);
    k_final<<<tg, tb>>>(q1, x1, out);                                        // + x_, NHWC->NCHW
}

// round 9
// speedup vs baseline: 2.2438x; 1.1835x over previous
#include <cuda_runtime.h>
#include <cuda_bf16.h>
#include <math.h>
#include <stdint.h>

#define BATCH 2
#define CDIM 128
#define HDIM 128
#define WDIM 128
#define HWD (HDIM*WDIM)           // 16384
#define NPIX (BATCH*HWD)          // 32768
#define C3 (3*CDIM)               // 384
#define HIDD 340
#define HIDP 352                  // padded hidden (mult of 32)
#define NHEADS 4
#define EPSV 1e-6f

typedef __nv_bfloat16 bf16;

// ---------------- scratch (static device allocations) ----------------
__device__ float g_xt  [NPIX*CDIM];
__device__ float g_qkv1[NPIX*C3];
__device__ float g_qkv2[NPIX*C3];
__device__ float g_x1  [NPIX*CDIM];
__device__ float g_y   [NPIX*CDIM];
__device__ float g_h1  [NPIX*HIDD];
__device__ float g_S   [BATCH*NHEADS*32*32 + 2*BATCH*CDIM];  // S | nq | nk contiguous
#define SOFF_NQ (BATCH*NHEADS*32*32)
#define SOFF_NK (BATCH*NHEADS*32*32 + BATCH*CDIM)
__device__ float g_wt  [4][C3*9];       // transposed dwconv weights [9][CHN] x4
__device__ bf16  g_lnh [NPIX*CDIM];
__device__ bf16  g_lnl [NPIX*CDIM];
__device__ bf16  g_atth[NPIX*CDIM];
__device__ bf16  g_attl[NPIX*CDIM];
__device__ bf16  g_h2h [NPIX*HIDP];
__device__ bf16  g_h2l [NPIX*HIDP];
#define WB_TOTAL 319488
__device__ bf16  g_wbh [WB_TOTAL];
__device__ bf16  g_wbl [WB_TOTAL];
// offsets into g_wb*
#define OFF_RQKV  0        // 384x128
#define OFF_RPROJ 49152    // 128x128
#define OFF_FSIN  65536    // 384x128 (rows padded from 340)
#define OFF_FSOUT 114688   // 128x352 (K padded from 340)
#define OFF_GQKV  159744
#define OFF_GPROJ 208896
#define OFF_FCIN  225280
#define OFF_FCOUT 274432   // 128x352
#define WT_ELEMS 13032     // 3456+3060+3456+3060

// =================== helpers ===================
__device__ __forceinline__ uint32_t smem_u32(const void* p){
    uint32_t a;
    asm("{ .reg .u64 t; cvta.to.shared.u64 t, %1; cvt.u32.u64 %0, t; }" : "=r"(a) : "l"(p));
    return a;
}
__device__ __forceinline__ void ldsm_x4(uint32_t& r0, uint32_t& r1, uint32_t& r2, uint32_t& r3,
                                        uint32_t addr){
    asm volatile("ldmatrix.sync.aligned.m8n8.x4.shared.b16 {%0,%1,%2,%3}, [%4];"
                 : "=r"(r0), "=r"(r1), "=r"(r2), "=r"(r3) : "r"(addr));
}
__device__ __forceinline__ void mma_bf16(float* d, const uint32_t* a, const uint32_t* b){
    asm volatile("mma.sync.aligned.m16n8k16.row.col.f32.bf16.bf16.f32 "
                 "{%0,%1,%2,%3}, {%4,%5,%6,%7}, {%8,%9}, {%0,%1,%2,%3};"
                 : "+f"(d[0]), "+f"(d[1]), "+f"(d[2]), "+f"(d[3])
                 : "r"(a[0]), "r"(a[1]), "r"(a[2]), "r"(a[3]), "r"(b[0]), "r"(b[1]));
}
__device__ __forceinline__ void split2(float v, bf16& h, bf16& l){
    h = __float2bfloat16(v);
    l = __float2bfloat16(v - __bfloat162float(h));
}
__device__ __forceinline__ void cpa16(uint32_t dst, const void* src){
    asm volatile("cp.async.ca.shared.global [%0], [%1], 16;" :: "r"(dst), "l"(src) : "memory");
}

// ============ bf16-split GEMM, cp.async double-buffered, frag reuse ============
#define SPAD 40
#define STG_E (128*SPAD)          // elements per array per stage
#define GT_SMEM (2*4*STG_E*2)     // 81920 bytes
__global__ void __launch_bounds__(256, 2)
k_gemm_bf(const bf16* __restrict__ Ah, const bf16* __restrict__ Al,
          const bf16* __restrict__ Bh, const bf16* __restrict__ Bl,
          float* __restrict__ Cc, const float* __restrict__ res,
          int N, int sA, int sB, int KC){
    extern __shared__ __align__(16) char smem[];
    int tid = threadIdx.x, warp = tid >> 5, lane = tid & 31;
    int m0 = blockIdx.y*128, n0 = blockIdx.x*128;
    int mw = (warp & 3)*32, nw = (warp >> 2)*64;
    float acc[2][8][4];
    #pragma unroll
    for (int i=0;i<2;i++)
        #pragma unroll
        for (int j=0;j<8;j++)
            #pragma unroll
            for (int e=0;e<4;e++) acc[i][j][e] = 0.f;

    int r  = tid >> 1;            // 0..127
    int cb = (tid & 1)*16;        // 0 or 16
    const bf16* gp0 = Ah + (long)(m0+r)*sA + cb;
    const bf16* gp1 = Al + (long)(m0+r)*sA + cb;
    const bf16* gp2 = Bh + (long)(n0+r)*sB + cb;
    const bf16* gp3 = Bl + (long)(n0+r)*sB + cb;

    uint32_t stb = smem_u32(smem);
    uint32_t doff = (uint32_t)(r*SPAD + cb)*2;
    const uint32_t STG_B = STG_E*2;           // 10240 bytes per array

    int arow = mw + ((lane >> 3) & 1)*8 + (lane & 7);
    int acolb = ((lane >> 4) & 1)*8;
    int brow = nw + ((lane >> 4) & 1)*8 + (lane & 7);
    int bcolb = ((lane >> 3) & 1)*8;

    // prefetch chunk 0 into stage 0
    {
        uint32_t base = stb + doff;
        cpa16(base + 0*STG_B,      gp0);
        cpa16(base + 0*STG_B + 16, gp0 + 8);
        cpa16(base + 1*STG_B,      gp1);
        cpa16(base + 1*STG_B + 16, gp1 + 8);
        cpa16(base + 2*STG_B,      gp2);
        cpa16(base + 2*STG_B + 16, gp2 + 8);
        cpa16(base + 3*STG_B,      gp3);
        cpa16(base + 3*STG_B + 16, gp3 + 8);
        asm volatile("cp.async.commit_group;" ::: "memory");
    }

    for (int kc = 0; kc < KC; kc++){
        if (kc+1 < KC){
            int k0 = (kc+1)*32;
            uint32_t base = stb + ((kc+1)&1)*4*STG_B + doff;
            cpa16(base + 0*STG_B,      gp0 + k0);
            cpa16(base + 0*STG_B + 16, gp0 + k0 + 8);
            cpa16(base + 1*STG_B,      gp1 + k0);
            cpa16(base + 1*STG_B + 16, gp1 + k0 + 8);
            cpa16(base + 2*STG_B,      gp2 + k0);
            cpa16(base + 2*STG_B + 16, gp2 + k0 + 8);
            cpa16(base + 3*STG_B,      gp3 + k0);
            cpa16(base + 3*STG_B + 16, gp3 + k0 + 8);
            asm volatile("cp.async.commit_group;" ::: "memory");
            asm volatile("cp.async.wait_group 1;" ::: "memory");
        } else {
            asm volatile("cp.async.wait_group 0;" ::: "memory");
        }
        __syncthreads();

        const bf16* Ahs = (const bf16*)(smem + ((kc&1)*4 + 0)*STG_B);
        const bf16* Als = (const bf16*)(smem + ((kc&1)*4 + 1)*STG_B);
        const bf16* Bhs = (const bf16*)(smem + ((kc&1)*4 + 2)*STG_B);
        const bf16* Bls = (const bf16*)(smem + ((kc&1)*4 + 3)*STG_B);

        #pragma unroll
        for (int kk = 0; kk < 32; kk += 16){
            uint32_t ah[2][4], tfr[2][4], bh[8][2], bl[8][2];
            // load Ah, Bh
            #pragma unroll
            for (int mt = 0; mt < 2; mt++){
                uint32_t ad = smem_u32(Ahs + (arow + mt*16)*SPAD + kk + acolb);
                ldsm_x4(ah[mt][0], ah[mt][1], ah[mt][2], ah[mt][3], ad);
            }
            #pragma unroll
            for (int np = 0; np < 4; np++){
                uint32_t ad = smem_u32(Bhs + (brow + np*16)*SPAD + kk + bcolb);
                ldsm_x4(bh[np*2][0], bh[np*2][1], bh[np*2+1][0], bh[np*2+1][1], ad);
            }
            // pass 1: Ah*Bh
            #pragma unroll
            for (int mt = 0; mt < 2; mt++)
                #pragma unroll
                for (int nt = 0; nt < 8; nt++)
                    mma_bf16(acc[mt][nt], ah[mt], bh[nt]);
            // load Al, pass 2: Al*Bh (reuse bh)
            #pragma unroll
            for (int mt = 0; mt < 2; mt++){
                uint32_t ad = smem_u32(Als + (arow + mt*16)*SPAD + kk + acolb);
                ldsm_x4(tfr[mt][0], tfr[mt][1], tfr[mt][2], tfr[mt][3], ad);
            }
            #pragma unroll
            for (int mt = 0; mt < 2; mt++)
                #pragma unroll
                for (int nt = 0; nt < 8; nt++)
                    mma_bf16(acc[mt][nt], tfr[mt], bh[nt]);
            // load Bl, pass 3: Ah*Bl (reuse ah)
            #pragma unroll
            for (int np = 0; np < 4; np++){
                uint32_t ad = smem_u32(Bls + (brow + np*16)*SPAD + kk + bcolb);
                ldsm_x4(bl[np*2][0], bl[np*2][1], bl[np*2+1][0], bl[np*2+1][1], ad);
            }
            #pragma unroll
            for (int mt = 0; mt < 2; mt++)
                #pragma unroll
                for (int nt = 0; nt < 8; nt++)
                    mma_bf16(acc[mt][nt], ah[mt], bl[nt]);
        }
        __syncthreads();
    }

    // ---- epilogue ----
    #pragma unroll
    for (int mt = 0; mt < 2; mt++){
        int mrow = m0 + mw + mt*16 + (lane >> 2);
        #pragma unroll
        for (int nt = 0; nt < 8; nt++){
            int n = n0 + nw + nt*8 + (lane & 3)*2;
            if (n < N){
                long b0 = (long)mrow*N + n;
                long b1 = (long)(mrow+8)*N + n;
                float2 v0 = make_float2(acc[mt][nt][0], acc[mt][nt][1]);
                float2 v1 = make_float2(acc[mt][nt][2], acc[mt][nt][3]);
                if (res){
                    float2 r0 = *(const float2*)(res + b0);
                    float2 r1 = *(const float2*)(res + b1);
                    v0.x += r0.x; v0.y += r0.y;
                    v1.x += r1.x; v1.y += r1.y;
                }
                *(float2*)(Cc + b0) = v0;
                *(float2*)(Cc + b1) = v1;
            }
        }
    }
}

// ---------------- unified prep: all weight transposes + splits ----------------
__global__ void k_prep(const float* __restrict__ rsa_dw, const float* __restrict__ ffs_dw,
                       const float* __restrict__ gsa_dw, const float* __restrict__ ffc_dw,
                       const float* __restrict__ rqkv, const float* __restrict__ rproj,
                       const float* __restrict__ fsin, const float* __restrict__ fsout,
                       const float* __restrict__ gqkv, const float* __restrict__ gproj,
                       const float* __restrict__ fcin, const float* __restrict__ fcout){
    int i = blockIdx.x*256 + threadIdx.x;
    if (i < WB_TOTAL){
        const float* srcs[8] = {rqkv, rproj, fsin, fsout, gqkv, gproj, fcin, fcout};
        const int offs[9] = {OFF_RQKV, OFF_RPROJ, OFF_FSIN, OFF_FSOUT,
                             OFF_GQKV, OFF_GPROJ, OFF_FCIN, OFF_FCOUT, WB_TOTAL};
        const int Nr[8]   = {C3, CDIM, HIDD, CDIM, C3, CDIM, HIDD, CDIM};
        const int Kr[8]   = {CDIM, CDIM, CDIM, HIDD, CDIM, CDIM, CDIM, HIDD};
        const int Kpad[8] = {128, 128, 128, 352, 128, 128, 128, 352};
        int s = 0;
        while (i >= offs[s+1]) s++;
        int j = i - offs[s];
        int rr = j / Kpad[s], c = j - rr*Kpad[s];
        float v = (rr < Nr[s] && c < Kr[s]) ? srcs[s][(long)rr*Kr[s] + c] : 0.f;
        bf16 h, l; split2(v, h, l);
        g_wbh[i] = h; g_wbl[i] = l;
    } else {
        int j = i - WB_TOTAL;
        const float* s4[4] = {rsa_dw, ffs_dw, gsa_dw, ffc_dw};
        const int chn[4] = {C3, HIDD, C3, HIDD};
        int seg = 0;
        while (seg < 4 && j >= chn[seg]*9){ j -= chn[seg]*9; seg++; }
        if (seg >= 4) return;
        int c = j/9, t = j - c*9;
        g_wt[seg][t*chn[seg] + c] = s4[seg][j];
    }
}

// ---------------- NCHW -> NHWC transpose ----------------
__global__ void k_nchw2nhwc(const float* __restrict__ in, float* __restrict__ out){
    __shared__ float tile[32][33];
    int b = blockIdx.z;
    int p0 = blockIdx.x*32;
    int c0 = blockIdx.y*32;
    int tx = threadIdx.x, ty = threadIdx.y;
    #pragma unroll
    for (int i=0;i<4;i++){
        int c = c0 + ty + i*8;
        tile[ty+i*8][tx] = in[((long)b*CDIM + c)*HWD + p0 + tx];
    }
    __syncthreads();
    #pragma unroll
    for (int i=0;i<4;i++){
        int p = p0 + ty + i*8;
        out[((long)b*HWD + p)*CDIM + c0 + tx] = tile[tx][ty+i*8];
    }
}

// ---------------- NHWC (a+b) -> NCHW ----------------
__global__ void k_final(const float* __restrict__ a, const float* __restrict__ b2,
                        float* __restrict__ out){
    __shared__ float tile[32][33];
    int b = blockIdx.z;
    int p0 = blockIdx.x*32;
    int c0 = blockIdx.y*32;
    int tx = threadIdx.x, ty = threadIdx.y;
    #pragma unroll
    for (int i=0;i<4;i++){
        long idx = ((long)b*HWD + p0 + ty + i*8)*CDIM + c0 + tx;
        tile[ty+i*8][tx] = a[idx] + b2[idx];
    }
    __syncthreads();
    #pragma unroll
    for (int i=0;i<4;i++){
        int c = c0 + ty + i*8;
        out[((long)b*CDIM + c)*HWD + p0 + tx] = tile[tx][ty+i*8];
    }
}

// ------ LayerNorm over C (warp per pixel), optional residual+roll, bf16 hi/lo out
__global__ void k_ln(const float* __restrict__ in, const float* __restrict__ res,
                     const float* __restrict__ gamma, const float* __restrict__ beta,
                     bf16* __restrict__ oh, bf16* __restrict__ ol, int shift){
    int warp = threadIdx.x >> 5, lane = threadIdx.x & 31;
    int pix = blockIdx.x*8 + warp;
    if (pix >= NPIX) return;
    int b = pix >> 14, rem = pix & (HWD-1);
    int h = rem >> 7, w = rem & 127;
    int sh = (h + shift) & (HDIM-1);
    int sw = (w + shift) & (WDIM-1);
    long src = ((long)b*HWD + sh*WDIM + sw)*CDIM + lane*4;
    float4 v = *(const float4*)(in + src);
    if (res){
        float4 r = *(const float4*)(res + src);
        v.x += r.x; v.y += r.y; v.z += r.z; v.w += r.w;
    }
    float s  = v.x+v.y+v.z+v.w;
    float ss = v.x*v.x+v.y*v.y+v.z*v.z+v.w*v.w;
    #pragma unroll
    for (int o=16;o;o>>=1){
        s  += __shfl_xor_sync(0xffffffffu, s,  o);
        ss += __shfl_xor_sync(0xffffffffu, ss, o);
    }
    float mean = s * (1.f/CDIM);
    float var  = ss * (1.f/CDIM) - mean*mean;
    float rstd = rsqrtf(var + EPSV);
    float4 g  = *(const float4*)(gamma + lane*4);
    float4 be = *(const float4*)(beta  + lane*4);
    float o0 = (v.x-mean)*rstd*g.x + be.x;
    float o1 = (v.y-mean)*rstd*g.y + be.y;
    float o2 = (v.z-mean)*rstd*g.z + be.z;
    float o3 = (v.w-mean)*rstd*g.w + be.w;
    bf16 hh[4], ll[4];
    split2(o0, hh[0], ll[0]); split2(o1, hh[1], ll[1]);
    split2(o2, hh[2], ll[2]); split2(o3, hh[3], ll[3]);
    long dst = (long)pix*CDIM + lane*4;
    *(uint2*)(oh + dst) = *(uint2*)hh;
    *(uint2*)(ol + dst) = *(uint2*)ll;
}

// ---------------- depthwise 3x3, fp32 out (qkv path) --------
__global__ void k_dwconv(const float* __restrict__ in, const float* __restrict__ wt,
                         float* __restrict__ out, int CHN){
    int cq = threadIdx.x;
    int py = threadIdx.y;
    int pix0 = blockIdx.x*8;
    int b = pix0 >> 14;
    int h = (pix0 >> 7) & 127;
    int w0 = pix0 & 127;
    int c4 = cq*4;
    float4 wv[9];
    #pragma unroll
    for (int t=0;t<9;t++) wv[t] = *(const float4*)(wt + t*CHN + c4);
    const float* base = in + (long)b*HWD*CHN + c4;
    float* obase = out + (long)b*HWD*CHN + c4;
    #pragma unroll
    for (int i=0;i<4;i++){
        int w = w0 + py + i*2;
        float4 acc = make_float4(0.f,0.f,0.f,0.f);
        #pragma unroll
        for (int dy=-1;dy<=1;dy++){
            int hh = h + dy;
            if ((unsigned)hh >= HDIM) continue;
            #pragma unroll
            for (int dx=-1;dx<=1;dx++){
                int ww = w + dx;
                if ((unsigned)ww >= WDIM) continue;
                float4 v = *(const float4*)(base + ((long)hh*WDIM + ww)*CHN);
                float4 wk = wv[(dy+1)*3 + dx + 1];
                acc.x += wk.x*v.x; acc.y += wk.y*v.y;
                acc.z += wk.z*v.z; acc.w += wk.w*v.w;
            }
        }
        *(float4*)(obase + ((long)h*WDIM + w)*CHN) = acc;
    }
}

// -------- depthwise 3x3 + gelu -> bf16 hi/lo out, K-padded to HIDP --------
__global__ void k_dwconv_gelu(const float* __restrict__ in, const float* __restrict__ wt,
                              bf16* __restrict__ oh, bf16* __restrict__ ol){
    int cq = threadIdx.x;          // 0..87 (HIDP/4)
    int py = threadIdx.y;          // 0..1
    int pix0 = blockIdx.x*8;
    int b = pix0 >> 14;
    int h = (pix0 >> 7) & 127;
    int w0 = pix0 & 127;
    int c4 = cq*4;
    bool pad = (c4 >= HIDD);
    float4 wv[9];
    if (!pad){
        #pragma unroll
        for (int t=0;t<9;t++) wv[t] = *(const float4*)(wt + t*HIDD + c4);
    }
    const float* base = in + (long)b*HWD*HIDD + c4;
    long obase = (long)b*HWD*HIDP + c4;
    #pragma unroll
    for (int i=0;i<4;i++){
        int w = w0 + py + i*2;
        bf16 hh[4] = {}, ll[4] = {};
        if (!pad){
            float4 acc = make_float4(0.f,0.f,0.f,0.f);
            #pragma unroll
            for (int dy=-1;dy<=1;dy++){
                int hy = h + dy;
                if ((unsigned)hy >= HDIM) continue;
                #pragma unroll
                for (int dx=-1;dx<=1;dx++){
                    int ww = w + dx;
                    if ((unsigned)ww >= WDIM) continue;
                    float4 v = *(const float4*)(base + ((long)hy*WDIM + ww)*HIDD);
                    float4 wk = wv[(dy+1)*3 + dx + 1];
                    acc.x += wk.x*v.x; acc.y += wk.y*v.y;
                    acc.z += wk.z*v.z; acc.w += wk.w*v.w;
                }
            }
            acc.x = 0.5f*acc.x*(1.f + erff(acc.x*0.70710678118654752f));
            acc.y = 0.5f*acc.y*(1.f + erff(acc.y*0.70710678118654752f));
            acc.z = 0.5f*acc.z*(1.f + erff(acc.z*0.70710678118654752f));
            acc.w = 0.5f*acc.w*(1.f + erff(acc.w*0.70710678118654752f));
            split2(acc.x, hh[0], ll[0]); split2(acc.y, hh[1], ll[1]);
            split2(acc.z, hh[2], ll[2]); split2(acc.w, hh[3], ll[3]);
        }
        long o = obase + ((long)h*WDIM + w)*HIDP;
        *(uint2*)(oh + o) = *(uint2*)hh;
        *(uint2*)(ol + o) = *(uint2*)ll;
    }
}

// ---------------- RSA window attention (one CTA per 4x4 window) --------------
__global__ void k_rsa_win(const float* __restrict__ qkv, const float* __restrict__ tempp,
                          bf16* __restrict__ oh, bf16* __restrict__ ol){
    extern __shared__ float sm[];
    float* qs = sm;
    float* ks = sm + 2048;
    float* vs = sm + 4096;
    float* at = sm + 6144;
    __shared__ float rn[32];
    int tid = threadIdx.x;
    int warp = tid >> 5, lane = tid & 31;
    int win = blockIdx.x;
    int b = win >> 10; int wrem = win & 1023;
    int wy = wrem >> 5, wx = wrem & 31;
    for (int i = tid; i < 6144; i += 256){
        int sec = i >> 11; int r = i & 2047; int p = r >> 7; int c = r & 127;
        int gh = wy*4 + (p>>2), gw = wx*4 + (p&3);
        sm[i] = qkv[((long)b*HWD + gh*WDIM + gw)*C3 + sec*128 + c];
    }
    __syncthreads();
    #pragma unroll
    for (int r = warp; r < 32; r += 8){
        const float* basep = sm + (r>>4)*2048 + (r&15)*128;
        float4 v = *(const float4*)(basep + lane*4);
        float s = v.x*v.x + v.y*v.y + v.z*v.z + v.w*v.w;
        #pragma unroll
        for (int o=16;o;o>>=1) s += __shfl_xor_sync(0xffffffffu, s, o);
        if (lane == 0) rn[r] = 1.f / fmaxf(sqrtf(s), 1e-12f);
    }
    __syncthreads();
    for (int i = tid; i < 4096; i += 256){
        int sec = i >> 11; int p = (i & 2047) >> 7;
        sm[i] *= rn[sec*16 + p];
    }
    __syncthreads();
    float temp = tempp[0];
    {
        int c0 = (tid >> 4)*8, d0 = (tid & 15)*8;
        float a2[8][8] = {};
        #pragma unroll
        for (int p=0;p<16;p++){
            float4 q0 = *(const float4*)&qs[p*128+c0];
            float4 q1 = *(const float4*)&qs[p*128+c0+4];
            float4 k0 = *(const float4*)&ks[p*128+d0];
            float4 k1 = *(const float4*)&ks[p*128+d0+4];
            float qa[8] = {q0.x,q0.y,q0.z,q0.w,q1.x,q1.y,q1.z,q1.w};
            float ka[8] = {k0.x,k0.y,k0.z,k0.w,k1.x,k1.y,k1.z,k1.w};
            #pragma unroll
            for (int i=0;i<8;i++)
                #pragma unroll
                for (int j=0;j<8;j++)
                    a2[i][j] += qa[i]*ka[j];
        }
        #pragma unroll
        for (int i=0;i<8;i++){
            float4 r0, r1;
            r0.x = fmaxf(a2[i][0]*temp, 0.f); r0.y = fmaxf(a2[i][1]*temp, 0.f);
            r0.z = fmaxf(a2[i][2]*temp, 0.f); r0.w = fmaxf(a2[i][3]*temp, 0.f);
            r1.x = fmaxf(a2[i][4]*temp, 0.f); r1.y = fmaxf(a2[i][5]*temp, 0.f);
            r1.z = fmaxf(a2[i][6]*temp, 0.f); r1.w = fmaxf(a2[i][7]*temp, 0.f);
            *(float4*)&at[(c0+i)*128 + d0]     = r0;
            *(float4*)&at[(c0+i)*128 + d0 + 4] = r1;
        }
    }
    __syncthreads();
    {
        int p = tid >> 4, d0 = (tid & 15)*8;
        float s0[4] = {}, s1[4] = {};
        #pragma unroll 4
        for (int c=0;c<128;c++){
            float v = vs[p*128+c];
            float4 t0 = *(const float4*)&at[c*128+d0];
            float4 t1 = *(const float4*)&at[c*128+d0+4];
            s0[0] += v*t0.x; s0[1] += v*t0.y; s0[2] += v*t0.z; s0[3] += v*t0.w;
            s1[0] += v*t1.x; s1[1] += v*t1.y; s1[2] += v*t1.z; s1[3] += v*t1.w;
        }
        int gh = wy*4 + (p>>2), gw = wx*4 + (p&3);
        int oh2 = (gh+2)&127, ow = (gw+2)&127;
        long off = ((long)b*HWD + oh2*WDIM + ow)*CDIM + d0;
        bf16 hh[8], ll[8];
        split2(s0[0], hh[0], ll[0]); split2(s0[1], hh[1], ll[1]);
        split2(s0[2], hh[2], ll[2]); split2(s0[3], hh[3], ll[3]);
        split2(s1[0], hh[4], ll[4]); split2(s1[1], hh[5], ll[5]);
        split2(s1[2], hh[6], ll[6]); split2(s1[3], hh[7], ll[7]);
        *(uint4*)(oh + off) = *(uint4*)hh;
        *(uint4*)(ol + off) = *(uint4*)ll;
    }
}

// ---------------- GSA gram + per-channel sumsq reduction (64 chunks) ---------
__global__ void k_gsa_gram(const float* __restrict__ qkv, float* __restrict__ S,
                           float* __restrict__ nq, float* __restrict__ nk){
    __shared__ float sq[32*32];
    __shared__ float sk[32*32];
    int tid = threadIdx.x;
    int blk = blockIdx.x;
    int chunk = blk & 63;
    int head = (blk >> 6) & 3;
    int b = blk >> 8;
    int p0 = chunk*256;
    int c0 = tid >> 3;
    int d0 = (tid & 7) * 4;
    float acc[4] = {0,0,0,0};
    float sumq = 0.f, sumk = 0.f;
    for (int t = 0; t < 8; t++){
        __syncthreads();
        for (int i = tid; i < 2048; i += 256){
            int pi = i >> 6;
            int vv = i & 63;
            long pix = (long)b*HWD + p0 + t*32 + pi;
            int chn = (vv < 32) ? (head*32 + vv) : (128 + head*32 + (vv-32));
            float val = qkv[pix*C3 + chn];
            if (vv < 32) sq[pi*32+vv] = val; else sk[pi*32+(vv-32)] = val;
        }
        __syncthreads();
        #pragma unroll 4
        for (int pi=0; pi<32; pi++){
            float qv = sq[pi*32 + c0];
            #pragma unroll
            for (int j=0;j<4;j++) acc[j] += qv * sk[pi*32 + d0 + j];
        }
        if (tid < 32){
            for (int pi=0;pi<32;pi++){ float v = sq[pi*32+tid]; sumq += v*v; }
        } else if (tid < 64){
            int c = tid-32;
            for (int pi=0;pi<32;pi++){ float v = sk[pi*32+c]; sumk += v*v; }
        }
    }
    int sbase = ((b*NHEADS + head)*32 + c0)*32 + d0;
    #pragma unroll
    for (int j=0;j<4;j++) atomicAdd(&S[sbase+j], acc[j]);
    if (tid < 32) atomicAdd(&nq[b*CDIM + head*32 + tid], sumq);
    else if (tid < 64) atomicAdd(&nk[b*CDIM + head*32 + (tid-32)], sumk);
}

// ---- GSA output: normalize S in-flight, out[c,n] = sum_d attn[c,d] v[d,n] ----
__global__ void k_gsa_out(const float* __restrict__ qkv, const float* __restrict__ A,
                          const float* __restrict__ nq, const float* __restrict__ nk,
                          const float* __restrict__ tempp,
                          bf16* __restrict__ oh, bf16* __restrict__ ol){
    __shared__ float at[NHEADS*32*33];
    __shared__ float vsm[8][128];
    int tid = threadIdx.x;
    int warp = tid >> 5, lane = tid & 31;
    int b = (blockIdx.x*8) / HWD;
    float temp = tempp[0];
    for (int i = tid; i < NHEADS*32*32; i += 256){
        int head = i >> 10; int c = (i >> 5) & 31; int d = i & 31;
        float qn = fmaxf(sqrtf(nq[b*CDIM + head*32 + c]), 1e-12f);
        float kn = fmaxf(sqrtf(nk[b*CDIM + head*32 + d]), 1e-12f);
        float val = fmaxf(A[b*NHEADS*32*32 + i]*temp/(qn*kn), 0.f);
        at[(i>>5)*33 + d] = val;
    }
    __syncthreads();
    long pix = (long)blockIdx.x*8 + warp;
    float4 v4 = *(const float4*)(qkv + pix*C3 + 256 + lane*4);
    vsm[warp][lane*4+0]=v4.x; vsm[warp][lane*4+1]=v4.y;
    vsm[warp][lane*4+2]=v4.z; vsm[warp][lane*4+3]=v4.w;
    __syncwarp();
    #pragma unroll
    for (int hd=0; hd<4; hd++){
        const float* arow = at + (hd*32 + lane)*33;
        const float* vrow = vsm[warp] + hd*32;
        float s = 0.f;
        #pragma unroll
        for (int d=0; d<32; d++) s += arow[d]*vrow[d];
        bf16 h, l; split2(s, h, l);
        long off = pix*CDIM + hd*32 + lane;
        oh[off] = h; ol[off] = l;
    }
}

// =============================== host ===============================
static float* sym(const void* s){
    void* p = nullptr;
    cudaGetSymbolAddress(&p, s);
    return (float*)p;
}
static bf16* symb(const void* s){
    void* p = nullptr;
    cudaGetSymbolAddress(&p, s);
    return (bf16*)p;
}

extern "C" void kernel_launch(void* const* d_in, const int* in_sizes, int n_in,
                              void* d_out, int out_size){
    const float* x        = (const float*)d_in[0];
    const float* w_s0     = (const float*)d_in[1];
    const float* b_s0     = (const float*)d_in[2];
    const float* w_s2     = (const float*)d_in[3];
    const float* b_s2     = (const float*)d_in[4];
    const float* rsa_qkv  = (const float*)d_in[5];
    const float* rsa_dw   = (const float*)d_in[6];
    const float* rsa_proj = (const float*)d_in[7];
    const float* rsa_temp = (const float*)d_in[8];
    const float* ffs_in   = (const float*)d_in[9];
    const float* ffs_dw   = (const float*)d_in[10];
    const float* ffs_out  = (const float*)d_in[11];
    const float* w_c0     = (const float*)d_in[12];
    const float* b_c0     = (const float*)d_in[13];
    const float* w_c2     = (const float*)d_in[14];
    const float* b_c2     = (const float*)d_in[15];
    const float* gsa_qkv  = (const float*)d_in[16];
    const float* gsa_dw   = (const float*)d_in[17];
    const float* gsa_proj = (const float*)d_in[18];
    const float* gsa_temp = (const float*)d_in[19];
    const float* ffc_in   = (const float*)d_in[20];
    const float* ffc_dw   = (const float*)d_in[21];
    const float* ffc_out  = (const float*)d_in[22];
    float* out = (float*)d_out;

    float* xt  = sym(g_xt);
    float* q1  = sym(g_qkv1);
    float* q2  = sym(g_qkv2);
    float* x1  = sym(g_x1);
    float* y   = sym(g_y);
    float* h1  = sym(g_h1);
    float* S   = sym(g_S);
    float* nq  = S + SOFF_NQ;
    float* nk  = S + SOFF_NK;
    float* wt  = sym(g_wt);
    bf16* lnh  = symb(g_lnh);
    bf16* lnl  = symb(g_lnl);
    bf16* atth = symb(g_atth);
    bf16* attl = symb(g_attl);
    bf16* h2h  = symb(g_h2h);
    bf16* h2l  = symb(g_h2l);
    bf16* wbh  = symb(g_wbh);
    bf16* wbl  = symb(g_wbl);
    float* wt_rsa = wt;
    float* wt_ffs = wt + C3*9;
    float* wt_gsa = wt + 2*C3*9;
    float* wt_ffc = wt + 3*C3*9;

    cudaFuncSetAttribute(k_rsa_win, cudaFuncAttributeMaxDynamicSharedMemorySize, 90112);
    cudaFuncSetAttribute(k_gemm_bf, cudaFuncAttributeMaxDynamicSharedMemorySize, GT_SMEM);

    dim3 tb(32,8);
    dim3 tg(HWD/32, CDIM/32, BATCH);
    dim3 dwb3(C3/4, 2);
    dim3 dwbh2(HIDP/4, 2);
    int dwg = NPIX/8;

    // one-shot prep: all weight transposes + bf16 splits
    k_prep<<<(WB_TOTAL + WT_ELEMS + 255)/256, 256>>>(
        rsa_dw, ffs_dw, gsa_dw, ffc_dw,
        rsa_qkv, rsa_proj, ffs_in, ffs_out, gsa_qkv, gsa_proj, ffc_in, ffc_out);

    // ---- spatial (RSA) block ----
    k_nchw2nhwc<<<tg, tb>>>(x, xt);
    k_ln<<<NPIX/8, 256>>>(xt, nullptr, w_s0, b_s0, lnh, lnl, 2);             // LN + roll(-2,-2)
    k_gemm_bf<<<dim3(3,256), 256, GT_SMEM>>>(lnh, lnl, wbh+OFF_RQKV, wbl+OFF_RQKV, q1, nullptr, C3, 128, 128, 4);
    k_dwconv<<<dwg, dwb3>>>(q1, wt_rsa, q2, C3);
    k_rsa_win<<<BATCH*1024, 256, 90112>>>(q2, rsa_temp, atth, attl);         // + roll back
    k_gemm_bf<<<dim3(1,256), 256, GT_SMEM>>>(atth, attl, wbh+OFF_RPROJ, wbl+OFF_RPROJ, x1, nullptr, CDIM, 128, 128, 4);
    k_ln<<<NPIX/8, 256>>>(x1, xt, w_s2, b_s2, lnh, lnl, 0);                  // LN(x_ + x)
    k_gemm_bf<<<dim3(3,256), 256, GT_SMEM>>>(lnh, lnl, wbh+OFF_FSIN, wbl+OFF_FSIN, h1, nullptr, HIDD, 128, 128, 4);
    k_dwconv_gelu<<<dwg, dwbh2>>>(h1, wt_ffs, h2h, h2l);
    k_gemm_bf<<<dim3(1,256), 256, GT_SMEM>>>(h2h, h2l, wbh+OFF_FSOUT, wbl+OFF_FSOUT, y, x1, CDIM, 352, 352, 11);

    // ---- channel (GSA) block ----
    k_ln<<<NPIX/8, 256>>>(y, nullptr, w_c0, b_c0, lnh, lnl, 0);
    k_gemm_bf<<<dim3(3,256), 256, GT_SMEM>>>(lnh, lnl, wbh+OFF_GQKV, wbl+OFF_GQKV, q1, nullptr, C3, 128, 128, 4);
    k_dwconv<<<dwg, dwb3>>>(q1, wt_gsa, q2, C3);
    cudaMemsetAsync(S, 0, (BATCH*NHEADS*32*32 + 2*BATCH*CDIM)*sizeof(float));
    k_gsa_gram<<<BATCH*NHEADS*64, 256>>>(q2, S, nq, nk);
    k_gsa_out<<<NPIX/8, 256>>>(q2, S, nq, nk, gsa_temp, atth, attl);
    k_gemm_bf<<<dim3(1,256), 256, GT_SMEM>>>(atth, attl, wbh+OFF_GPROJ, wbl+OFF_GPROJ, x1, nullptr, CDIM, 128, 128, 4);
    k_ln<<<NPIX/8, 256>>>(x1, y, w_c2, b_c2, lnh, lnl, 0);                   // LN(x_ + x2)
    k_gemm_bf<<<dim3(3,256), 256, GT_SMEM>>>(lnh, lnl, wbh+OFF_FCIN, wbl+OFF_FCIN, h1, nullptr, HIDD, 128, 128, 4);
    k_dwconv_gelu<<<dwg, dwbh2>>>(h1, wt_ffc, h2h, h2l);
    k_gemm_bf<<<dim3(1,256), 256, GT_SMEM>>>(h2h, h2l, wbh+OFF_FCOUT, wbl+OFF_FCOUT, q1, nullptr, CDIM, 352, 352, 11);
    k_final<<<tg, tb>>>(q1, x1, out);                                        // + x_, NHWC->NCHW
}

// round 10
// speedup vs baseline: 2.3687x; 1.0557x over previous
#include <cuda_runtime.h>
#include <cuda_bf16.h>
#include <math.h>
#include <stdint.h>

#define BATCH 2
#define CDIM 128
#define HDIM 128
#define WDIM 128
#define HWD (HDIM*WDIM)           // 16384
#define NPIX (BATCH*HWD)          // 32768
#define C3 (3*CDIM)               // 384
#define HIDD 340
#define HIDP 352                  // padded hidden (mult of 32)
#define NHEADS 4
#define EPSV 1e-6f

typedef __nv_bfloat16 bf16;

// ---------------- scratch (static device allocations) ----------------
__device__ float g_xt  [NPIX*CDIM];
__device__ float g_qkv1[NPIX*C3];
__device__ float g_qkv2[NPIX*C3];
__device__ float g_x1  [NPIX*CDIM];
__device__ float g_y   [NPIX*CDIM];
__device__ float g_h1  [NPIX*HIDD];
__device__ float g_S   [BATCH*NHEADS*32*32 + 2*BATCH*CDIM];  // S | nq | nk contiguous
#define SOFF_NQ (BATCH*NHEADS*32*32)
#define SOFF_NK (BATCH*NHEADS*32*32 + BATCH*CDIM)
__device__ float g_wt  [4][C3*9];       // transposed dwconv weights [9][CHN] x4
__device__ bf16  g_lnh [NPIX*CDIM];
__device__ bf16  g_lnl [NPIX*CDIM];
__device__ bf16  g_atth[NPIX*CDIM];
__device__ bf16  g_attl[NPIX*CDIM];
__device__ bf16  g_h2h [NPIX*HIDP];
__device__ bf16  g_h2l [NPIX*HIDP];
#define WB_TOTAL 319488
__device__ bf16  g_wbh [WB_TOTAL];
__device__ bf16  g_wbl [WB_TOTAL];
// offsets into g_wb*
#define OFF_RQKV  0        // 384x128
#define OFF_RPROJ 49152    // 128x128
#define OFF_FSIN  65536    // 384x128 (rows padded from 340)
#define OFF_FSOUT 114688   // 128x352 (K padded from 340)
#define OFF_GQKV  159744
#define OFF_GPROJ 208896
#define OFF_FCIN  225280
#define OFF_FCOUT 274432   // 128x352
#define WT_ELEMS 13032     // 3456+3060+3456+3060

// =================== helpers ===================
__device__ __forceinline__ uint32_t smem_u32(const void* p){
    uint32_t a;
    asm("{ .reg .u64 t; cvta.to.shared.u64 t, %1; cvt.u32.u64 %0, t; }" : "=r"(a) : "l"(p));
    return a;
}
__device__ __forceinline__ void ldsm_x4(uint32_t& r0, uint32_t& r1, uint32_t& r2, uint32_t& r3,
                                        uint32_t addr){
    asm volatile("ldmatrix.sync.aligned.m8n8.x4.shared.b16 {%0,%1,%2,%3}, [%4];"
                 : "=r"(r0), "=r"(r1), "=r"(r2), "=r"(r3) : "r"(addr));
}
__device__ __forceinline__ void mma_bf16(float* d, const uint32_t* a, const uint32_t* b){
    asm volatile("mma.sync.aligned.m16n8k16.row.col.f32.bf16.bf16.f32 "
                 "{%0,%1,%2,%3}, {%4,%5,%6,%7}, {%8,%9}, {%0,%1,%2,%3};"
                 : "+f"(d[0]), "+f"(d[1]), "+f"(d[2]), "+f"(d[3])
                 : "r"(a[0]), "r"(a[1]), "r"(a[2]), "r"(a[3]), "r"(b[0]), "r"(b[1]));
}
__device__ __forceinline__ void split2(float v, bf16& h, bf16& l){
    h = __float2bfloat16(v);
    l = __float2bfloat16(v - __bfloat162float(h));
}
__device__ __forceinline__ void cpa16(uint32_t dst, const void* src){
    asm volatile("cp.async.cg.shared.global [%0], [%1], 16;" :: "r"(dst), "l"(src) : "memory");
}

// ============ bf16-split GEMM, cp.async double-buffered, frag reuse ============
#define SPAD 40
#define STG_E (128*SPAD)          // elements per array per stage
#define GT_SMEM (2*4*STG_E*2)     // 81920 bytes
__global__ void __launch_bounds__(256, 2)
k_gemm_bf(const bf16* __restrict__ Ah, const bf16* __restrict__ Al,
          const bf16* __restrict__ Bh, const bf16* __restrict__ Bl,
          float* __restrict__ Cc, const float* __restrict__ res,
          int N, int sA, int sB, int KC){
    extern __shared__ __align__(16) char smem[];
    int tid = threadIdx.x, warp = tid >> 5, lane = tid & 31;
    int m0 = blockIdx.y*128, n0 = blockIdx.x*128;
    int mw = (warp & 3)*32, nw = (warp >> 2)*64;
    float acc[2][8][4];
    #pragma unroll
    for (int i=0;i<2;i++)
        #pragma unroll
        for (int j=0;j<8;j++)
            #pragma unroll
            for (int e=0;e<4;e++) acc[i][j][e] = 0.f;

    int r  = tid >> 1;            // 0..127
    int cb = (tid & 1)*16;        // 0 or 16
    const bf16* gp0 = Ah + (long)(m0+r)*sA + cb;
    const bf16* gp1 = Al + (long)(m0+r)*sA + cb;
    const bf16* gp2 = Bh + (long)(n0+r)*sB + cb;
    const bf16* gp3 = Bl + (long)(n0+r)*sB + cb;

    uint32_t stb = smem_u32(smem);
    uint32_t doff = (uint32_t)(r*SPAD + cb)*2;
    const uint32_t STG_B = STG_E*2;           // 10240 bytes per array

    int arow = mw + ((lane >> 3) & 1)*8 + (lane & 7);
    int acolb = ((lane >> 4) & 1)*8;
    int brow = nw + ((lane >> 4) & 1)*8 + (lane & 7);
    int bcolb = ((lane >> 3) & 1)*8;

    // prefetch chunk 0 into stage 0
    {
        uint32_t base = stb + doff;
        cpa16(base + 0*STG_B,      gp0);
        cpa16(base + 0*STG_B + 16, gp0 + 8);
        cpa16(base + 1*STG_B,      gp1);
        cpa16(base + 1*STG_B + 16, gp1 + 8);
        cpa16(base + 2*STG_B,      gp2);
        cpa16(base + 2*STG_B + 16, gp2 + 8);
        cpa16(base + 3*STG_B,      gp3);
        cpa16(base + 3*STG_B + 16, gp3 + 8);
        asm volatile("cp.async.commit_group;" ::: "memory");
    }

    for (int kc = 0; kc < KC; kc++){
        if (kc+1 < KC){
            int k0 = (kc+1)*32;
            uint32_t base = stb + ((kc+1)&1)*4*STG_B + doff;
            cpa16(base + 0*STG_B,      gp0 + k0);
            cpa16(base + 0*STG_B + 16, gp0 + k0 + 8);
            cpa16(base + 1*STG_B,      gp1 + k0);
            cpa16(base + 1*STG_B + 16, gp1 + k0 + 8);
            cpa16(base + 2*STG_B,      gp2 + k0);
            cpa16(base + 2*STG_B + 16, gp2 + k0 + 8);
            cpa16(base + 3*STG_B,      gp3 + k0);
            cpa16(base + 3*STG_B + 16, gp3 + k0 + 8);
            asm volatile("cp.async.commit_group;" ::: "memory");
            asm volatile("cp.async.wait_group 1;" ::: "memory");
        } else {
            asm volatile("cp.async.wait_group 0;" ::: "memory");
        }
        __syncthreads();

        const bf16* Ahs = (const bf16*)(smem + ((kc&1)*4 + 0)*STG_B);
        const bf16* Als = (const bf16*)(smem + ((kc&1)*4 + 1)*STG_B);
        const bf16* Bhs = (const bf16*)(smem + ((kc&1)*4 + 2)*STG_B);
        const bf16* Bls = (const bf16*)(smem + ((kc&1)*4 + 3)*STG_B);

        #pragma unroll
        for (int kk = 0; kk < 32; kk += 16){
            uint32_t ah[2][4], tfr[2][4], bh[8][2], bl[8][2];
            // load Ah, Bh
            #pragma unroll
            for (int mt = 0; mt < 2; mt++){
                uint32_t ad = smem_u32(Ahs + (arow + mt*16)*SPAD + kk + acolb);
                ldsm_x4(ah[mt][0], ah[mt][1], ah[mt][2], ah[mt][3], ad);
            }
            #pragma unroll
            for (int np = 0; np < 4; np++){
                uint32_t ad = smem_u32(Bhs + (brow + np*16)*SPAD + kk + bcolb);
                ldsm_x4(bh[np*2][0], bh[np*2][1], bh[np*2+1][0], bh[np*2+1][1], ad);
            }
            // pass 1: Ah*Bh
            #pragma unroll
            for (int mt = 0; mt < 2; mt++)
                #pragma unroll
                for (int nt = 0; nt < 8; nt++)
                    mma_bf16(acc[mt][nt], ah[mt], bh[nt]);
            // load Al, pass 2: Al*Bh (reuse bh)
            #pragma unroll
            for (int mt = 0; mt < 2; mt++){
                uint32_t ad = smem_u32(Als + (arow + mt*16)*SPAD + kk + acolb);
                ldsm_x4(tfr[mt][0], tfr[mt][1], tfr[mt][2], tfr[mt][3], ad);
            }
            #pragma unroll
            for (int mt = 0; mt < 2; mt++)
                #pragma unroll
                for (int nt = 0; nt < 8; nt++)
                    mma_bf16(acc[mt][nt], tfr[mt], bh[nt]);
            // load Bl, pass 3: Ah*Bl (reuse ah)
            #pragma unroll
            for (int np = 0; np < 4; np++){
                uint32_t ad = smem_u32(Bls + (brow + np*16)*SPAD + kk + bcolb);
                ldsm_x4(bl[np*2][0], bl[np*2][1], bl[np*2+1][0], bl[np*2+1][1], ad);
            }
            #pragma unroll
            for (int mt = 0; mt < 2; mt++)
                #pragma unroll
                for (int nt = 0; nt < 8; nt++)
                    mma_bf16(acc[mt][nt], ah[mt], bl[nt]);
        }
        __syncthreads();
    }

    // ---- epilogue ----
    #pragma unroll
    for (int mt = 0; mt < 2; mt++){
        int mrow = m0 + mw + mt*16 + (lane >> 2);
        #pragma unroll
        for (int nt = 0; nt < 8; nt++){
            int n = n0 + nw + nt*8 + (lane & 3)*2;
            if (n < N){
                long b0 = (long)mrow*N + n;
                long b1 = (long)(mrow+8)*N + n;
                float2 v0 = make_float2(acc[mt][nt][0], acc[mt][nt][1]);
                float2 v1 = make_float2(acc[mt][nt][2], acc[mt][nt][3]);
                if (res){
                    float2 r0 = *(const float2*)(res + b0);
                    float2 r1 = *(const float2*)(res + b1);
                    v0.x += r0.x; v0.y += r0.y;
                    v1.x += r1.x; v1.y += r1.y;
                }
                *(float2*)(Cc + b0) = v0;
                *(float2*)(Cc + b1) = v1;
            }
        }
    }
}

// ---------------- unified prep: all weight transposes + splits ----------------
__global__ void k_prep(const float* __restrict__ rsa_dw, const float* __restrict__ ffs_dw,
                       const float* __restrict__ gsa_dw, const float* __restrict__ ffc_dw,
                       const float* __restrict__ rqkv, const float* __restrict__ rproj,
                       const float* __restrict__ fsin, const float* __restrict__ fsout,
                       const float* __restrict__ gqkv, const float* __restrict__ gproj,
                       const float* __restrict__ fcin, const float* __restrict__ fcout){
    int i = blockIdx.x*256 + threadIdx.x;
    if (i < WB_TOTAL){
        const float* srcs[8] = {rqkv, rproj, fsin, fsout, gqkv, gproj, fcin, fcout};
        const int offs[9] = {OFF_RQKV, OFF_RPROJ, OFF_FSIN, OFF_FSOUT,
                             OFF_GQKV, OFF_GPROJ, OFF_FCIN, OFF_FCOUT, WB_TOTAL};
        const int Nr[8]   = {C3, CDIM, HIDD, CDIM, C3, CDIM, HIDD, CDIM};
        const int Kr[8]   = {CDIM, CDIM, CDIM, HIDD, CDIM, CDIM, CDIM, HIDD};
        const int Kpad[8] = {128, 128, 128, 352, 128, 128, 128, 352};
        int s = 0;
        while (i >= offs[s+1]) s++;
        int j = i - offs[s];
        int rr = j / Kpad[s], c = j - rr*Kpad[s];
        float v = (rr < Nr[s] && c < Kr[s]) ? srcs[s][(long)rr*Kr[s] + c] : 0.f;
        bf16 h, l; split2(v, h, l);
        g_wbh[i] = h; g_wbl[i] = l;
    } else {
        int j = i - WB_TOTAL;
        const float* s4[4] = {rsa_dw, ffs_dw, gsa_dw, ffc_dw};
        const int chn[4] = {C3, HIDD, C3, HIDD};
        int seg = 0;
        while (seg < 4 && j >= chn[seg]*9){ j -= chn[seg]*9; seg++; }
        if (seg >= 4) return;
        int c = j/9, t = j - c*9;
        g_wt[seg][t*chn[seg] + c] = s4[seg][j];
    }
}

// ---------------- NCHW -> NHWC transpose ----------------
__global__ void k_nchw2nhwc(const float* __restrict__ in, float* __restrict__ out){
    __shared__ float tile[32][33];
    int b = blockIdx.z;
    int p0 = blockIdx.x*32;
    int c0 = blockIdx.y*32;
    int tx = threadIdx.x, ty = threadIdx.y;
    #pragma unroll
    for (int i=0;i<4;i++){
        int c = c0 + ty + i*8;
        tile[ty+i*8][tx] = in[((long)b*CDIM + c)*HWD + p0 + tx];
    }
    __syncthreads();
    #pragma unroll
    for (int i=0;i<4;i++){
        int p = p0 + ty + i*8;
        out[((long)b*HWD + p)*CDIM + c0 + tx] = tile[tx][ty+i*8];
    }
}

// ---------------- NHWC (a+b) -> NCHW ----------------
__global__ void k_final(const float* __restrict__ a, const float* __restrict__ b2,
                        float* __restrict__ out){
    __shared__ float tile[32][33];
    int b = blockIdx.z;
    int p0 = blockIdx.x*32;
    int c0 = blockIdx.y*32;
    int tx = threadIdx.x, ty = threadIdx.y;
    #pragma unroll
    for (int i=0;i<4;i++){
        long idx = ((long)b*HWD + p0 + ty + i*8)*CDIM + c0 + tx;
        tile[ty+i*8][tx] = a[idx] + b2[idx];
    }
    __syncthreads();
    #pragma unroll
    for (int i=0;i<4;i++){
        int c = c0 + ty + i*8;
        out[((long)b*CDIM + c)*HWD + p0 + tx] = tile[tx][ty+i*8];
    }
}

// ------ LayerNorm over C (warp per pixel), optional residual+roll, bf16 hi/lo out
__global__ void k_ln(const float* __restrict__ in, const float* __restrict__ res,
                     const float* __restrict__ gamma, const float* __restrict__ beta,
                     bf16* __restrict__ oh, bf16* __restrict__ ol, int shift){
    int warp = threadIdx.x >> 5, lane = threadIdx.x & 31;
    int pix = blockIdx.x*8 + warp;
    if (pix >= NPIX) return;
    int b = pix >> 14, rem = pix & (HWD-1);
    int h = rem >> 7, w = rem & 127;
    int sh = (h + shift) & (HDIM-1);
    int sw = (w + shift) & (WDIM-1);
    long src = ((long)b*HWD + sh*WDIM + sw)*CDIM + lane*4;
    float4 v = *(const float4*)(in + src);
    if (res){
        float4 r = *(const float4*)(res + src);
        v.x += r.x; v.y += r.y; v.z += r.z; v.w += r.w;
    }
    float s  = v.x+v.y+v.z+v.w;
    float ss = v.x*v.x+v.y*v.y+v.z*v.z+v.w*v.w;
    #pragma unroll
    for (int o=16;o;o>>=1){
        s  += __shfl_xor_sync(0xffffffffu, s,  o);
        ss += __shfl_xor_sync(0xffffffffu, ss, o);
    }
    float mean = s * (1.f/CDIM);
    float var  = ss * (1.f/CDIM) - mean*mean;
    float rstd = rsqrtf(var + EPSV);
    float4 g  = *(const float4*)(gamma + lane*4);
    float4 be = *(const float4*)(beta  + lane*4);
    float o0 = (v.x-mean)*rstd*g.x + be.x;
    float o1 = (v.y-mean)*rstd*g.y + be.y;
    float o2 = (v.z-mean)*rstd*g.z + be.z;
    float o3 = (v.w-mean)*rstd*g.w + be.w;
    bf16 hh[4], ll[4];
    split2(o0, hh[0], ll[0]); split2(o1, hh[1], ll[1]);
    split2(o2, hh[2], ll[2]); split2(o3, hh[3], ll[3]);
    long dst = (long)pix*CDIM + lane*4;
    *(uint2*)(oh + dst) = *(uint2*)hh;
    *(uint2*)(ol + dst) = *(uint2*)ll;
}

// ---------------- depthwise 3x3, fp32 out (qkv path), 4 consecutive w/thread --
__global__ void k_dwconv(const float* __restrict__ in, const float* __restrict__ wt,
                         float* __restrict__ out, int CHN){
    int cq = threadIdx.x;
    int py = threadIdx.y;          // 0..1, selects 4-pixel half
    int pix0 = blockIdx.x*8;
    int b = pix0 >> 14;
    int h = (pix0 >> 7) & 127;
    int wbase = (pix0 & 127) + py*4;   // 4 consecutive w
    int c4 = cq*4;
    float4 wv[9];
    #pragma unroll
    for (int t=0;t<9;t++) wv[t] = *(const float4*)(wt + t*CHN + c4);
    const float* base = in + (long)b*HWD*CHN + c4;
    float* obase = out + (long)b*HWD*CHN + c4;
    float4 acc[4];
    #pragma unroll
    for (int i=0;i<4;i++) acc[i] = make_float4(0.f,0.f,0.f,0.f);
    #pragma unroll
    for (int dy=-1;dy<=1;dy++){
        int hh = h + dy;
        if ((unsigned)hh >= HDIM) continue;
        const float* rowp = base + (long)hh*WDIM*CHN;
        float4 col[6];
        #pragma unroll
        for (int j=0;j<6;j++){
            int ww = wbase - 1 + j;
            col[j] = ((unsigned)ww < WDIM) ? *(const float4*)(rowp + (long)ww*CHN)
                                           : make_float4(0.f,0.f,0.f,0.f);
        }
        #pragma unroll
        for (int i=0;i<4;i++){
            #pragma unroll
            for (int dx=0;dx<3;dx++){
                float4 wk = wv[(dy+1)*3 + dx];
                float4 v = col[i+dx];
                acc[i].x += wk.x*v.x; acc[i].y += wk.y*v.y;
                acc[i].z += wk.z*v.z; acc[i].w += wk.w*v.w;
            }
        }
    }
    #pragma unroll
    for (int i=0;i<4;i++)
        *(float4*)(obase + ((long)h*WDIM + wbase + i)*CHN) = acc[i];
}

// -------- depthwise 3x3 + gelu -> bf16 hi/lo out, K-padded to HIDP --------
__global__ void k_dwconv_gelu(const float* __restrict__ in, const float* __restrict__ wt,
                              bf16* __restrict__ oh, bf16* __restrict__ ol){
    int cq = threadIdx.x;          // 0..87 (HIDP/4)
    int py = threadIdx.y;          // 0..1
    int pix0 = blockIdx.x*8;
    int b = pix0 >> 14;
    int h = (pix0 >> 7) & 127;
    int wbase = (pix0 & 127) + py*4;
    int c4 = cq*4;
    bool pad = (c4 >= HIDD);
    long obase = (long)b*HWD*HIDP + c4;
    if (pad){
        bf16 z[4] = {};
        #pragma unroll
        for (int i=0;i<4;i++){
            long o = obase + ((long)h*WDIM + wbase + i)*HIDP;
            *(uint2*)(oh + o) = *(uint2*)z;
            *(uint2*)(ol + o) = *(uint2*)z;
        }
        return;
    }
    float4 wv[9];
    #pragma unroll
    for (int t=0;t<9;t++) wv[t] = *(const float4*)(wt + t*HIDD + c4);
    const float* base = in + (long)b*HWD*HIDD + c4;
    float4 acc[4];
    #pragma unroll
    for (int i=0;i<4;i++) acc[i] = make_float4(0.f,0.f,0.f,0.f);
    #pragma unroll
    for (int dy=-1;dy<=1;dy++){
        int hy = h + dy;
        if ((unsigned)hy >= HDIM) continue;
        const float* rowp = base + (long)hy*WDIM*HIDD;
        float4 col[6];
        #pragma unroll
        for (int j=0;j<6;j++){
            int ww = wbase - 1 + j;
            col[j] = ((unsigned)ww < WDIM) ? *(const float4*)(rowp + (long)ww*HIDD)
                                           : make_float4(0.f,0.f,0.f,0.f);
        }
        #pragma unroll
        for (int i=0;i<4;i++){
            #pragma unroll
            for (int dx=0;dx<3;dx++){
                float4 wk = wv[(dy+1)*3 + dx];
                float4 v = col[i+dx];
                acc[i].x += wk.x*v.x; acc[i].y += wk.y*v.y;
                acc[i].z += wk.z*v.z; acc[i].w += wk.w*v.w;
            }
        }
    }
    #pragma unroll
    for (int i=0;i<4;i++){
        float4 a = acc[i];
        a.x = 0.5f*a.x*(1.f + erff(a.x*0.70710678118654752f));
        a.y = 0.5f*a.y*(1.f + erff(a.y*0.70710678118654752f));
        a.z = 0.5f*a.z*(1.f + erff(a.z*0.70710678118654752f));
        a.w = 0.5f*a.w*(1.f + erff(a.w*0.70710678118654752f));
        bf16 hh[4], ll[4];
        split2(a.x, hh[0], ll[0]); split2(a.y, hh[1], ll[1]);
        split2(a.z, hh[2], ll[2]); split2(a.w, hh[3], ll[3]);
        long o = obase + ((long)h*WDIM + wbase + i)*HIDP;
        *(uint2*)(oh + o) = *(uint2*)hh;
        *(uint2*)(ol + o) = *(uint2*)ll;
    }
}

// ---------------- RSA window attention (one CTA per 4x4 window) --------------
__global__ void k_rsa_win(const float* __restrict__ qkv, const float* __restrict__ tempp,
                          bf16* __restrict__ oh, bf16* __restrict__ ol){
    extern __shared__ float sm[];
    float* qs = sm;
    float* ks = sm + 2048;
    float* vs = sm + 4096;
    float* at = sm + 6144;
    __shared__ float rn[32];
    int tid = threadIdx.x;
    int warp = tid >> 5, lane = tid & 31;
    int win = blockIdx.x;
    int b = win >> 10; int wrem = win & 1023;
    int wy = wrem >> 5, wx = wrem & 31;
    for (int i = tid; i < 6144; i += 256){
        int sec = i >> 11; int r = i & 2047; int p = r >> 7; int c = r & 127;
        int gh = wy*4 + (p>>2), gw = wx*4 + (p&3);
        sm[i] = qkv[((long)b*HWD + gh*WDIM + gw)*C3 + sec*128 + c];
    }
    __syncthreads();
    #pragma unroll
    for (int r = warp; r < 32; r += 8){
        const float* basep = sm + (r>>4)*2048 + (r&15)*128;
        float4 v = *(const float4*)(basep + lane*4);
        float s = v.x*v.x + v.y*v.y + v.z*v.z + v.w*v.w;
        #pragma unroll
        for (int o=16;o;o>>=1) s += __shfl_xor_sync(0xffffffffu, s, o);
        if (lane == 0) rn[r] = 1.f / fmaxf(sqrtf(s), 1e-12f);
    }
    __syncthreads();
    for (int i = tid; i < 4096; i += 256){
        int sec = i >> 11; int p = (i & 2047) >> 7;
        sm[i] *= rn[sec*16 + p];
    }
    __syncthreads();
    float temp = tempp[0];
    {
        int c0 = (tid >> 4)*8, d0 = (tid & 15)*8;
        float a2[8][8] = {};
        #pragma unroll
        for (int p=0;p<16;p++){
            float4 q0 = *(const float4*)&qs[p*128+c0];
            float4 q1 = *(const float4*)&qs[p*128+c0+4];
            float4 k0 = *(const float4*)&ks[p*128+d0];
            float4 k1 = *(const float4*)&ks[p*128+d0+4];
            float qa[8] = {q0.x,q0.y,q0.z,q0.w,q1.x,q1.y,q1.z,q1.w};
            float ka[8] = {k0.x,k0.y,k0.z,k0.w,k1.x,k1.y,k1.z,k1.w};
            #pragma unroll
            for (int i=0;i<8;i++)
                #pragma unroll
                for (int j=0;j<8;j++)
                    a2[i][j] += qa[i]*ka[j];
        }
        #pragma unroll
        for (int i=0;i<8;i++){
            float4 r0, r1;
            r0.x = fmaxf(a2[i][0]*temp, 0.f); r0.y = fmaxf(a2[i][1]*temp, 0.f);
            r0.z = fmaxf(a2[i][2]*temp, 0.f); r0.w = fmaxf(a2[i][3]*temp, 0.f);
            r1.x = fmaxf(a2[i][4]*temp, 0.f); r1.y = fmaxf(a2[i][5]*temp, 0.f);
            r1.z = fmaxf(a2[i][6]*temp, 0.f); r1.w = fmaxf(a2[i][7]*temp, 0.f);
            *(float4*)&at[(c0+i)*128 + d0]     = r0;
            *(float4*)&at[(c0+i)*128 + d0 + 4] = r1;
        }
    }
    __syncthreads();
    {
        int p = tid >> 4, d0 = (tid & 15)*8;
        float s0[4] = {}, s1[4] = {};
        #pragma unroll 4
        for (int c=0;c<128;c++){
            float v = vs[p*128+c];
            float4 t0 = *(const float4*)&at[c*128+d0];
            float4 t1 = *(const float4*)&at[c*128+d0+4];
            s0[0] += v*t0.x; s0[1] += v*t0.y; s0[2] += v*t0.z; s0[3] += v*t0.w;
            s1[0] += v*t1.x; s1[1] += v*t1.y; s1[2] += v*t1.z; s1[3] += v*t1.w;
        }
        int gh = wy*4 + (p>>2), gw = wx*4 + (p&3);
        int oh2 = (gh+2)&127, ow = (gw+2)&127;
        long off = ((long)b*HWD + oh2*WDIM + ow)*CDIM + d0;
        bf16 hh[8], ll[8];
        split2(s0[0], hh[0], ll[0]); split2(s0[1], hh[1], ll[1]);
        split2(s0[2], hh[2], ll[2]); split2(s0[3], hh[3], ll[3]);
        split2(s1[0], hh[4], ll[4]); split2(s1[1], hh[5], ll[5]);
        split2(s1[2], hh[6], ll[6]); split2(s1[3], hh[7], ll[7]);
        *(uint4*)(oh + off) = *(uint4*)hh;
        *(uint4*)(ol + off) = *(uint4*)ll;
    }
}

// ---------------- GSA gram + per-channel sumsq reduction (64 chunks) ---------
__global__ void k_gsa_gram(const float* __restrict__ qkv, float* __restrict__ S,
                           float* __restrict__ nq, float* __restrict__ nk){
    __shared__ float sq[32*32];
    __shared__ float sk[32*32];
    int tid = threadIdx.x;
    int blk = blockIdx.x;
    int chunk = blk & 63;
    int head = (blk >> 6) & 3;
    int b = blk >> 8;
    int p0 = chunk*256;
    int c0 = tid >> 3;
    int d0 = (tid & 7) * 4;
    float acc[4] = {0,0,0,0};
    float sumq = 0.f, sumk = 0.f;
    for (int t = 0; t < 8; t++){
        __syncthreads();
        for (int i = tid; i < 2048; i += 256){
            int pi = i >> 6;
            int vv = i & 63;
            long pix = (long)b*HWD + p0 + t*32 + pi;
            int chn = (vv < 32) ? (head*32 + vv) : (128 + head*32 + (vv-32));
            float val = qkv[pix*C3 + chn];
            if (vv < 32) sq[pi*32+vv] = val; else sk[pi*32+(vv-32)] = val;
        }
        __syncthreads();
        #pragma unroll 4
        for (int pi=0; pi<32; pi++){
            float qv = sq[pi*32 + c0];
            #pragma unroll
            for (int j=0;j<4;j++) acc[j] += qv * sk[pi*32 + d0 + j];
        }
        if (tid < 32){
            for (int pi=0;pi<32;pi++){ float v = sq[pi*32+tid]; sumq += v*v; }
        } else if (tid < 64){
            int c = tid-32;
            for (int pi=0;pi<32;pi++){ float v = sk[pi*32+c]; sumk += v*v; }
        }
    }
    int sbase = ((b*NHEADS + head)*32 + c0)*32 + d0;
    #pragma unroll
    for (int j=0;j<4;j++) atomicAdd(&S[sbase+j], acc[j]);
    if (tid < 32) atomicAdd(&nq[b*CDIM + head*32 + tid], sumq);
    else if (tid < 64) atomicAdd(&nk[b*CDIM + head*32 + (tid-32)], sumk);
}

// ---- GSA output: normalize S in-flight, out[c,n] = sum_d attn[c,d] v[d,n] ----
__global__ void k_gsa_out(const float* __restrict__ qkv, const float* __restrict__ A,
                          const float* __restrict__ nq, const float* __restrict__ nk,
                          const float* __restrict__ tempp,
                          bf16* __restrict__ oh, bf16* __restrict__ ol){
    __shared__ float at[NHEADS*32*33];
    __shared__ float vsm[8][128];
    int tid = threadIdx.x;
    int warp = tid >> 5, lane = tid & 31;
    int b = (blockIdx.x*8) / HWD;
    float temp = tempp[0];
    for (int i = tid; i < NHEADS*32*32; i += 256){
        int head = i >> 10; int c = (i >> 5) & 31; int d = i & 31;
        float qn = fmaxf(sqrtf(nq[b*CDIM + head*32 + c]), 1e-12f);
        float kn = fmaxf(sqrtf(nk[b*CDIM + head*32 + d]), 1e-12f);
        float val = fmaxf(A[b*NHEADS*32*32 + i]*temp/(qn*kn), 0.f);
        at[(i>>5)*33 + d] = val;
    }
    __syncthreads();
    long pix = (long)blockIdx.x*8 + warp;
    float4 v4 = *(const float4*)(qkv + pix*C3 + 256 + lane*4);
    vsm[warp][lane*4+0]=v4.x; vsm[warp][lane*4+1]=v4.y;
    vsm[warp][lane*4+2]=v4.z; vsm[warp][lane*4+3]=v4.w;
    __syncwarp();
    #pragma unroll
    for (int hd=0; hd<4; hd++){
        const float* arow = at + (hd*32 + lane)*33;
        const float* vrow = vsm[warp] + hd*32;
        float s = 0.f;
        #pragma unroll
        for (int d=0; d<32; d++) s += arow[d]*vrow[d];
        bf16 h, l; split2(s, h, l);
        long off = pix*CDIM + hd*32 + lane;
        oh[off] = h; ol[off] = l;
    }
}

// =============================== host ===============================
static float* sym(const void* s){
    void* p = nullptr;
    cudaGetSymbolAddress(&p, s);
    return (float*)p;
}
static bf16* symb(const void* s){
    void* p = nullptr;
    cudaGetSymbolAddress(&p, s);
    return (bf16*)p;
}

extern "C" void kernel_launch(void* const* d_in, const int* in_sizes, int n_in,
                              void* d_out, int out_size){
    const float* x        = (const float*)d_in[0];
    const float* w_s0     = (const float*)d_in[1];
    const float* b_s0     = (const float*)d_in[2];
    const float* w_s2     = (const float*)d_in[3];
    const float* b_s2     = (const float*)d_in[4];
    const float* rsa_qkv  = (const float*)d_in[5];
    const float* rsa_dw   = (const float*)d_in[6];
    const float* rsa_proj = (const float*)d_in[7];
    const float* rsa_temp = (const float*)d_in[8];
    const float* ffs_in   = (const float*)d_in[9];
    const float* ffs_dw   = (const float*)d_in[10];
    const float* ffs_out  = (const float*)d_in[11];
    const float* w_c0     = (const float*)d_in[12];
    const float* b_c0     = (const float*)d_in[13];
    const float* w_c2     = (const float*)d_in[14];
    const float* b_c2     = (const float*)d_in[15];
    const float* gsa_qkv  = (const float*)d_in[16];
    const float* gsa_dw   = (const float*)d_in[17];
    const float* gsa_proj = (const float*)d_in[18];
    const float* gsa_temp = (const float*)d_in[19];
    const float* ffc_in   = (const float*)d_in[20];
    const float* ffc_dw   = (const float*)d_in[21];
    const float* ffc_out  = (const float*)d_in[22];
    float* out = (float*)d_out;

    float* xt  = sym(g_xt);
    float* q1  = sym(g_qkv1);
    float* q2  = sym(g_qkv2);
    float* x1  = sym(g_x1);
    float* y   = sym(g_y);
    float* h1  = sym(g_h1);
    float* S   = sym(g_S);
    float* nq  = S + SOFF_NQ;
    float* nk  = S + SOFF_NK;
    float* wt  = sym(g_wt);
    bf16* lnh  = symb(g_lnh);
    bf16* lnl  = symb(g_lnl);
    bf16* atth = symb(g_atth);
    bf16* attl = symb(g_attl);
    bf16* h2h  = symb(g_h2h);
    bf16* h2l  = symb(g_h2l);
    bf16* wbh  = symb(g_wbh);
    bf16* wbl  = symb(g_wbl);
    float* wt_rsa = wt;
    float* wt_ffs = wt + C3*9;
    float* wt_gsa = wt + 2*C3*9;
    float* wt_ffc = wt + 3*C3*9;

    cudaFuncSetAttribute(k_rsa_win, cudaFuncAttributeMaxDynamicSharedMemorySize, 90112);
    cudaFuncSetAttribute(k_gemm_bf, cudaFuncAttributeMaxDynamicSharedMemorySize, GT_SMEM);

    dim3 tb(32,8);
    dim3 tg(HWD/32, CDIM/32, BATCH);
    dim3 dwb3(C3/4, 2);
    dim3 dwbh2(HIDP/4, 2);
    int dwg = NPIX/8;

    // one-shot prep: all weight transposes + bf16 splits
    k_prep<<<(WB_TOTAL + WT_ELEMS + 255)/256, 256>>>(
        rsa_dw, ffs_dw, gsa_dw, ffc_dw,
        rsa_qkv, rsa_proj, ffs_in, ffs_out, gsa_qkv, gsa_proj, ffc_in, ffc_out);

    // ---- spatial (RSA) block ----
    k_nchw2nhwc<<<tg, tb>>>(x, xt);
    k_ln<<<NPIX/8, 256>>>(xt, nullptr, w_s0, b_s0, lnh, lnl, 2);             // LN + roll(-2,-2)
    k_gemm_bf<<<dim3(3,256), 256, GT_SMEM>>>(lnh, lnl, wbh+OFF_RQKV, wbl+OFF_RQKV, q1, nullptr, C3, 128, 128, 4);
    k_dwconv<<<dwg, dwb3>>>(q1, wt_rsa, q2, C3);
    k_rsa_win<<<BATCH*1024, 256, 90112>>>(q2, rsa_temp, atth, attl);         // + roll back
    k_gemm_bf<<<dim3(1,256), 256, GT_SMEM>>>(atth, attl, wbh+OFF_RPROJ, wbl+OFF_RPROJ, x1, nullptr, CDIM, 128, 128, 4);
    k_ln<<<NPIX/8, 256>>>(x1, xt, w_s2, b_s2, lnh, lnl, 0);                  // LN(x_ + x)
    k_gemm_bf<<<dim3(3,256), 256, GT_SMEM>>>(lnh, lnl, wbh+OFF_FSIN, wbl+OFF_FSIN, h1, nullptr, HIDD, 128, 128, 4);
    k_dwconv_gelu<<<dwg, dwbh2>>>(h1, wt_ffs, h2h, h2l);
    k_gemm_bf<<<dim3(1,256), 256, GT_SMEM>>>(h2h, h2l, wbh+OFF_FSOUT, wbl+OFF_FSOUT, y, x1, CDIM, 352, 352, 11);

    // ---- channel (GSA) block ----
    k_ln<<<NPIX/8, 256>>>(y, nullptr, w_c0, b_c0, lnh, lnl, 0);
    k_gemm_bf<<<dim3(3,256), 256, GT_SMEM>>>(lnh, lnl, wbh+OFF_GQKV, wbl+OFF_GQKV, q1, nullptr, C3, 128, 128, 4);
    k_dwconv<<<dwg, dwb3>>>(q1, wt_gsa, q2, C3);
    cudaMemsetAsync(S, 0, (BATCH*NHEADS*32*32 + 2*BATCH*CDIM)*sizeof(float));
    k_gsa_gram<<<BATCH*NHEADS*64, 256>>>(q2, S, nq, nk);
    k_gsa_out<<<NPIX/8, 256>>>(q2, S, nq, nk, gsa_temp, atth, attl);
    k_gemm_bf<<<dim3(1,256), 256, GT_SMEM>>>(atth, attl, wbh+OFF_GPROJ, wbl+OFF_GPROJ, x1, nullptr, CDIM, 128, 128, 4);
    k_ln<<<NPIX/8, 256>>>(x1, y, w_c2, b_c2, lnh, lnl, 0);                   // LN(x_ + x2)
    k_gemm_bf<<<dim3(3,256), 256, GT_SMEM>>>(lnh, lnl, wbh+OFF_FCIN, wbl+OFF_FCIN, h1, nullptr, HIDD, 128, 128, 4);
    k_dwconv_gelu<<<dwg, dwbh2>>>(h1, wt_ffc, h2h, h2l);
    k_gemm_bf<<<dim3(1,256), 256, GT_SMEM>>>(h2h, h2l, wbh+OFF_FCOUT, wbl+OFF_FCOUT, q1, nullptr, CDIM, 352, 352, 11);
    k_final<<<tg, tb>>>(q1, x1, out);                                        // + x_, NHWC->NCHW
}